// round 3
// baseline (speedup 1.0000x reference)
#include <cuda_runtime.h>
#include <cstdint>
#include <cstddef>

#define Hc    256
#define CC    50
#define GG    512
#define NACT  200000
#define NRES  20000
#define NTIME 100000
#define EE    400000

// ---------------- scratch layout (floats) ----------------
static constexpr size_t OFF_A    = 0;                         // 200000*256
static constexpr size_t OFF_R    = 51200000;                  // 20000*256
static constexpr size_t OFF_T    = 56320000;                  // 100000*256
static constexpr size_t OFF_XA   = 81920000;                  // 200000*1024
static constexpr size_t OFF_XR   = 286720000;                 // 20000*512
static constexpr size_t OFF_XT   = 296960000;                 // 100000*512
static constexpr size_t OFF_INV  = 348160000;                 // 720000 (f,ra,ta,ar,at)
static constexpr size_t OFF_WF   = 348880000;                 // 2*8*65536 folded weights
static constexpr size_t OFF_BF   = 349928576;                 // 2*3*256 folded biases
static constexpr size_t OFF_LAST = 349930112;                 // 512 ints
static constexpr size_t TOTALF   = 349931008;

__device__ float g_buf[TOTALF];

// ---------------- small helpers ----------------
__device__ __forceinline__ void red_add_v4(float* a, float4 v) {
    asm volatile("red.global.add.v4.f32 [%0], {%1,%2,%3,%4};"
                 :: "l"(a), "f"(v.x), "f"(v.y), "f"(v.z), "f"(v.w) : "memory");
}

// out[i,j] = sum_k (A1+A2+A3)[i,k] * B[k,j]      (all 256x256, row-major)
__global__ void fold_w(const float* __restrict__ A1, const float* __restrict__ A2,
                       const float* __restrict__ A3, const float* __restrict__ B,
                       float* __restrict__ out) {
    int i = blockIdx.x, j = threadIdx.x;
    float acc = 0.f;
    for (int k = 0; k < Hc; k++) {
        float a = A1[i * Hc + k];
        if (A2) a += A2[i * Hc + k];
        if (A3) a += A3[i * Hc + k];
        acc = fmaf(a, B[k * Hc + j], acc);
    }
    out[i * Hc + j] = acc;
}

// out[j] = sum_k (b1+b2+b3)[k]*B[k,j] + blin[j]
__global__ void fold_b(const float* __restrict__ b1, const float* __restrict__ b2,
                       const float* __restrict__ b3, const float* __restrict__ B,
                       const float* __restrict__ blin, float* __restrict__ out) {
    int j = threadIdx.x;
    float acc = blin[j];
    for (int k = 0; k < Hc; k++) {
        float bb = b1[k];
        if (b2) bb += b2[k];
        if (b3) bb += b3[k];
        acc = fmaf(bb, B[k * Hc + j], acc);
    }
    out[j] = acc;
}

__global__ void count_k(const int* __restrict__ dst, float* __restrict__ cnt, int E) {
    int i = blockIdx.x * blockDim.x + threadIdx.x;
    if (i < E) atomicAdd(&cnt[dst[i]], 1.f);
}

__global__ void inv_k(float* __restrict__ p, int n) {
    int i = blockIdx.x * blockDim.x + threadIdx.x;
    if (i < n) { float c = p[i]; p[i] = 1.f / (c < 1.f ? 1.f : c); }
}

// one edge handled by 64 threads; 4 floats each via vector atomic
__global__ void scatter_k(const int* __restrict__ src, const int* __restrict__ dst,
                          const float* __restrict__ x, float* __restrict__ X,
                          int ldX, int sec, int E) {
    int t = blockIdx.x * blockDim.x + threadIdx.x;
    int e = t >> 6, lane = t & 63;
    if (e >= E) return;
    int s = __ldg(&src[e]), d = __ldg(&dst[e]);
    float4 v = *reinterpret_cast<const float4*>(x + (size_t)s * Hc + lane * 4);
    red_add_v4(X + (size_t)d * ldX + sec + lane * 4, v);
}

// Xa: scale 3 mean sections by inv degree, copy a into section 3
__global__ void finalize_act_k(float* __restrict__ Xa, const float* __restrict__ a,
                               const float* __restrict__ invf, const float* __restrict__ invra,
                               const float* __restrict__ invta) {
    size_t t = (size_t)blockIdx.x * blockDim.x + threadIdx.x;
    int node = (int)(t >> 8), q = (int)(t & 255);
    if (node >= NACT) return;
    float4* row = reinterpret_cast<float4*>(Xa + (size_t)node * 1024);
    if (q < 192) {
        float s = (q < 64) ? invf[node] : (q < 128 ? invra[node] : invta[node]);
        float4 v = row[q];
        v.x *= s; v.y *= s; v.z *= s; v.w *= s;
        row[q] = v;
    } else {
        row[q] = reinterpret_cast<const float4*>(a + (size_t)node * Hc)[q - 192];
    }
}

__global__ void finalize2_k(float* __restrict__ X, const float* __restrict__ xd,
                            const float* __restrict__ inv, int N) {
    size_t t = (size_t)blockIdx.x * blockDim.x + threadIdx.x;
    int node = (int)(t >> 7), q = (int)(t & 127);
    if (node >= N) return;
    float4* row = reinterpret_cast<float4*>(X + (size_t)node * 512);
    if (q < 64) {
        float s = inv[node];
        float4 v = row[q];
        v.x *= s; v.y *= s; v.z *= s; v.w *= s;
        row[q] = v;
    } else {
        row[q] = reinterpret_cast<const float4*>(xd + (size_t)node * Hc)[q - 64];
    }
}

__global__ void last_k(const int* __restrict__ batch, int* __restrict__ last, int N) {
    int i = blockIdx.x * blockDim.x + threadIdx.x;
    if (i < N) {
        if (i == N - 1 || batch[i + 1] != batch[i]) last[batch[i]] = i;
    }
}

// C[N,256] = relu?(A[N,K] @ W[K,256] + bias).  K multiple of 16.
// 64x256 block tile, 8x8 per-thread register tile, 256 threads.
__global__ void __launch_bounds__(256) gemm256(
        const float* __restrict__ A, const float* __restrict__ W,
        const float* __restrict__ bias, float* __restrict__ C,
        int N, int K, int relu) {
    __shared__ float As[16][68];
    __shared__ float Bs[16][256];
    const int tid = threadIdx.x;
    const int row0 = blockIdx.x * 64;
    const int ty = tid >> 5;            // 0..7  (rows ty*8 .. +7)
    const int tx = tid & 31;            // 0..31 (cols tx*8 .. +7)
    const int ar = tid >> 2;            // 0..63
    const int ac = (tid & 3) << 2;      // 0,4,8,12
    const int br = tid >> 4;            // 0..15
    const int bc = (tid & 15) << 4;     // 0..240

    float acc[8][8];
#pragma unroll
    for (int i = 0; i < 8; i++)
#pragma unroll
        for (int j = 0; j < 8; j++) acc[i][j] = 0.f;

    for (int k0 = 0; k0 < K; k0 += 16) {
        int gr = row0 + ar;
        float4 av = make_float4(0.f, 0.f, 0.f, 0.f);
        if (gr < N) av = *reinterpret_cast<const float4*>(A + (size_t)gr * K + k0 + ac);
        As[ac + 0][ar] = av.x; As[ac + 1][ar] = av.y;
        As[ac + 2][ar] = av.z; As[ac + 3][ar] = av.w;
#pragma unroll
        for (int q = 0; q < 4; q++) {
            *reinterpret_cast<float4*>(&Bs[br][bc + q * 4]) =
                *reinterpret_cast<const float4*>(W + (size_t)(k0 + br) * 256 + bc + q * 4);
        }
        __syncthreads();
#pragma unroll
        for (int k = 0; k < 16; k++) {
            float rA[8], rB[8];
#pragma unroll
            for (int i = 0; i < 8; i++) rA[i] = As[k][ty * 8 + i];
#pragma unroll
            for (int j = 0; j < 8; j++) rB[j] = Bs[k][tx * 8 + j];
#pragma unroll
            for (int i = 0; i < 8; i++)
#pragma unroll
                for (int j = 0; j < 8; j++)
                    acc[i][j] = fmaf(rA[i], rB[j], acc[i][j]);
        }
        __syncthreads();
    }
#pragma unroll
    for (int i = 0; i < 8; i++) {
        int gr = row0 + ty * 8 + i;
        if (gr >= N) continue;
#pragma unroll
        for (int jq = 0; jq < 2; jq++) {
            int col = tx * 8 + jq * 4;
            float4 v = make_float4(acc[i][jq * 4 + 0], acc[i][jq * 4 + 1],
                                   acc[i][jq * 4 + 2], acc[i][jq * 4 + 3]);
            if (bias) {
                v.x += bias[col]; v.y += bias[col + 1];
                v.z += bias[col + 2]; v.w += bias[col + 3];
            }
            if (relu) {
                v.x = fmaxf(v.x, 0.f); v.y = fmaxf(v.y, 0.f);
                v.z = fmaxf(v.z, 0.f); v.w = fmaxf(v.w, 0.f);
            }
            *reinterpret_cast<float4*>(C + (size_t)gr * 256 + col) = v;
        }
    }
}

// output heads: one block per graph
__global__ void heads_k(const float* __restrict__ a, const int* __restrict__ last,
                        const float* __restrict__ Wo, const float* __restrict__ bo,
                        const float* __restrict__ Wt, const float* __restrict__ bt,
                        const float* __restrict__ Wrm, const float* __restrict__ brm,
                        float* __restrict__ out) {
    int g = blockIdx.x;
    __shared__ float p[Hc];
    const float* row = a + (size_t)last[g] * Hc;
    for (int k = threadIdx.x; k < Hc; k += blockDim.x) p[k] = row[k];
    __syncthreads();
    int j = threadIdx.x;
    if (j < CC) {
        float acc = bo[j];
        for (int k = 0; k < Hc; k++) acc = fmaf(p[k], Wo[k * CC + j], acc);
        out[g * CC + j] = acc;
    } else if (j == CC) {
        float acc = bt[0];
        for (int k = 0; k < Hc; k++) acc = fmaf(p[k], Wt[k], acc);
        out[GG * CC + g] = acc;
    } else if (j == CC + 1) {
        float acc = brm[0];
        for (int k = 0; k < Hc; k++) acc = fmaf(p[k], Wrm[k], acc);
        out[GG * CC + GG + g] = acc;
    }
}

// ---------------- host orchestration ----------------
extern "C" void kernel_launch(void* const* d_in, const int* in_sizes, int n_in,
                              void* d_out, int out_size) {
    float* buf = nullptr;
    cudaGetSymbolAddress((void**)&buf, g_buf);

    float* A   = buf + OFF_A;
    float* R   = buf + OFF_R;
    float* T   = buf + OFF_T;
    float* XA  = buf + OFF_XA;
    float* XR  = buf + OFF_XR;
    float* XT  = buf + OFF_XT;
    float* INV = buf + OFF_INV;   // f@0, ra@200000, ta@400000, ar@600000, at@620000
    float* WF  = buf + OFF_WF;
    float* BF  = buf + OFF_BF;
    int*   LAST = reinterpret_cast<int*>(buf + OFF_LAST);

    const float* x_act  = (const float*)d_in[0];
    const float* x_res  = (const float*)d_in[1];
    const float* x_time = (const float*)d_in[2];
    const int* src_f  = (const int*)d_in[3];
    const int* dst_f  = (const int*)d_in[4];
    const int* src_ar = (const int*)d_in[5];
    const int* dst_ar = (const int*)d_in[6];
    const int* src_ra = (const int*)d_in[7];
    const int* dst_ra = (const int*)d_in[8];
    const int* src_at = (const int*)d_in[9];
    const int* dst_at = (const int*)d_in[10];
    const int* src_ta = (const int*)d_in[11];
    const int* dst_ta = (const int*)d_in[12];
    const int* batch  = (const int*)d_in[13];

    // num_graphs may or may not be materialized as an input
    int w = (in_sizes[14] <= 4) ? 15 : 14;
    const float* Wp_act = (const float*)d_in[w + 0];
    const float* Wp_res = (const float*)d_in[w + 1];
    const float* Wp_tim = (const float*)d_in[w + 2];
    const float* Wl     = (const float*)d_in[w + 3];
    const float* bl     = (const float*)d_in[w + 4];
    const float* Wr     = (const float*)d_in[w + 5];
    const float* Wlin   = (const float*)d_in[w + 6];
    const float* blin   = (const float*)d_in[w + 7];
    const float* Wo     = (const float*)d_in[w + 8];
    const float* bo     = (const float*)d_in[w + 9];
    const float* Wt     = (const float*)d_in[w + 10];
    const float* bt     = (const float*)d_in[w + 11];
    const float* Wrm    = (const float*)d_in[w + 12];
    const float* brm    = (const float*)d_in[w + 13];

    const size_t HH = 65536;  // 256*256

    // --- fold weights: W' = Wx @ Wlin ; bias' = (Σbl)@Wlin + blin ---
    for (int l = 0; l < 2; l++) {
        const float* wlin0 = Wlin + (size_t)(l * 3 + 0) * HH;
        const float* wlin1 = Wlin + (size_t)(l * 3 + 1) * HH;
        const float* wlin2 = Wlin + (size_t)(l * 3 + 2) * HH;
        float* WFl = WF + (size_t)l * 8 * HH;
        fold_w<<<256, 256>>>(Wl + (size_t)(l * 5 + 0) * HH, nullptr, nullptr, wlin0, WFl + 0 * HH);
        fold_w<<<256, 256>>>(Wl + (size_t)(l * 5 + 2) * HH, nullptr, nullptr, wlin0, WFl + 1 * HH);
        fold_w<<<256, 256>>>(Wl + (size_t)(l * 5 + 4) * HH, nullptr, nullptr, wlin0, WFl + 2 * HH);
        fold_w<<<256, 256>>>(Wr + (size_t)(l * 5 + 0) * HH,
                             Wr + (size_t)(l * 5 + 2) * HH,
                             Wr + (size_t)(l * 5 + 4) * HH, wlin0, WFl + 3 * HH);
        fold_w<<<256, 256>>>(Wl + (size_t)(l * 5 + 1) * HH, nullptr, nullptr, wlin1, WFl + 4 * HH);
        fold_w<<<256, 256>>>(Wr + (size_t)(l * 5 + 1) * HH, nullptr, nullptr, wlin1, WFl + 5 * HH);
        fold_w<<<256, 256>>>(Wl + (size_t)(l * 5 + 3) * HH, nullptr, nullptr, wlin2, WFl + 6 * HH);
        fold_w<<<256, 256>>>(Wr + (size_t)(l * 5 + 3) * HH, nullptr, nullptr, wlin2, WFl + 7 * HH);
        fold_b<<<1, 256>>>(bl + (l * 5 + 0) * 256, bl + (l * 5 + 2) * 256,
                           bl + (l * 5 + 4) * 256, wlin0, blin + (l * 3 + 0) * 256,
                           BF + l * 768 + 0);
        fold_b<<<1, 256>>>(bl + (l * 5 + 1) * 256, nullptr, nullptr, wlin1,
                           blin + (l * 3 + 1) * 256, BF + l * 768 + 256);
        fold_b<<<1, 256>>>(bl + (l * 5 + 3) * 256, nullptr, nullptr, wlin2,
                           blin + (l * 3 + 2) * 256, BF + l * 768 + 512);
    }

    // --- degree counts (indices are layer-invariant: compute once) ---
    cudaMemsetAsync(INV, 0, 720000 * sizeof(float), 0);
    int cblk = (EE + 255) / 256;
    count_k<<<cblk, 256>>>(dst_f,  INV + 0,      EE);
    count_k<<<cblk, 256>>>(dst_ra, INV + 200000, EE);
    count_k<<<cblk, 256>>>(dst_ta, INV + 400000, EE);
    count_k<<<cblk, 256>>>(dst_ar, INV + 600000, EE);
    count_k<<<cblk, 256>>>(dst_at, INV + 620000, EE);
    inv_k<<<(720000 + 255) / 256, 256>>>(INV, 720000);

    // --- input projections ---
    gemm256<<<(NACT  + 63) / 64, 256>>>(x_act,  Wp_act, nullptr, A, NACT,  64, 0);
    gemm256<<<(NRES  + 63) / 64, 256>>>(x_res,  Wp_res, nullptr, R, NRES,  32, 0);
    gemm256<<<(NTIME + 63) / 64, 256>>>(x_time, Wp_tim, nullptr, T, NTIME, 16, 0);

    // --- layers ---
    int sblk = (EE * 64) / 256;  // exact
    for (int l = 0; l < 2; l++) {
        cudaMemsetAsync(XA, 0, (size_t)NACT  * 1024 * sizeof(float), 0);
        cudaMemsetAsync(XR, 0, (size_t)NRES  * 512  * sizeof(float), 0);
        cudaMemsetAsync(XT, 0, (size_t)NTIME * 512  * sizeof(float), 0);

        scatter_k<<<sblk, 256>>>(src_f,  dst_f,  A, XA, 1024, 0,   EE);
        scatter_k<<<sblk, 256>>>(src_ra, dst_ra, R, XA, 1024, 256, EE);
        scatter_k<<<sblk, 256>>>(src_ta, dst_ta, T, XA, 1024, 512, EE);
        scatter_k<<<sblk, 256>>>(src_ar, dst_ar, A, XR, 512,  0,   EE);
        scatter_k<<<sblk, 256>>>(src_at, dst_at, A, XT, 512,  0,   EE);

        finalize_act_k<<<NACT, 256>>>(XA, A, INV, INV + 200000, INV + 400000);
        finalize2_k<<<NRES / 2, 256>>>(XR, R, INV + 600000, NRES);
        finalize2_k<<<NTIME / 2, 256>>>(XT, T, INV + 620000, NTIME);

        float* WFl = WF + (size_t)l * 8 * HH;
        gemm256<<<(NACT  + 63) / 64, 256>>>(XA, WFl + 0 * HH, BF + l * 768 + 0,   A, NACT,  1024, 1);
        gemm256<<<(NRES  + 63) / 64, 256>>>(XR, WFl + 4 * HH, BF + l * 768 + 256, R, NRES,  512,  1);
        gemm256<<<(NTIME + 63) / 64, 256>>>(XT, WFl + 6 * HH, BF + l * 768 + 512, T, NTIME, 512,  1);
    }

    // --- last-node pooling + heads ---
    cudaMemsetAsync(LAST, 0, GG * sizeof(int), 0);
    last_k<<<(NACT + 255) / 256, 256>>>(batch, LAST, NACT);
    heads_k<<<GG, 64>>>(A, LAST, Wo, bo, Wt, bt, Wrm, brm, (float*)d_out);
}

// round 7
// speedup vs baseline: 1.2953x; 1.2953x over previous
#include <cuda_runtime.h>
#include <cstdint>
#include <cstddef>

#define Hc    256
#define CC    50
#define GG    512
#define NACT  200000
#define NRES  20000
#define NTIME 100000
#define EE    400000

// ---------------- scratch layout (floats) ----------------
static constexpr size_t OFF_A    = 0;                         // 200000*256
static constexpr size_t OFF_R    = 51200000;                  // 20000*256
static constexpr size_t OFF_T    = 56320000;                  // 100000*256
static constexpr size_t OFF_XA   = 81920000;                  // 200000*1024
static constexpr size_t OFF_XR   = 286720000;                 // 20000*512
static constexpr size_t OFF_XT   = 296960000;                 // 100000*512
static constexpr size_t OFF_INV  = 348160000;                 // 720000 (f,ra,ta,ar,at)
static constexpr size_t OFF_WF   = 348880000;                 // 2*524288 folded weights (B-operand layout)
static constexpr size_t OFF_BF   = 349928576;                 // 2*3*256 folded biases
static constexpr size_t OFF_LAST = 349930112;                 // 512 ints
static constexpr size_t OFF_WLT  = 349931008;                 // 6*65536 Wlin^T
static constexpr size_t OFF_WPT  = 350324224;                 // 256*(64+32+16) Wp^T
static constexpr size_t TOTALF   = 350352896;

__device__ float g_buf[TOTALF];

// =====================================================================
// helpers
// =====================================================================
__device__ __forceinline__ uint32_t f2tf(float x) {
    uint32_t r;
    asm("cvt.rna.tf32.f32 %0, %1;" : "=r"(r) : "f"(x));
    return r;
}
__device__ __forceinline__ void mma_tf32_16n8k8(float* d, const uint32_t* a,
                                                uint32_t b0, uint32_t b1) {
    asm volatile(
        "mma.sync.aligned.m16n8k8.row.col.f32.tf32.tf32.f32 "
        "{%0,%1,%2,%3}, {%4,%5,%6,%7}, {%8,%9}, {%0,%1,%2,%3};"
        : "+f"(d[0]), "+f"(d[1]), "+f"(d[2]), "+f"(d[3])
        : "r"(a[0]), "r"(a[1]), "r"(a[2]), "r"(a[3]), "r"(b0), "r"(b1));
}
__device__ __forceinline__ void red_add_v4(float* a, float4 v) {
    asm volatile("red.global.add.v4.f32 [%0], {%1,%2,%3,%4};"
                 :: "l"(a), "f"(v.x), "f"(v.y), "f"(v.z), "f"(v.w) : "memory");
}

// =====================================================================
// tf32 mma.sync GEMM: C[Nrow, 256] = relu?(A[Nrow,K] @ Bsrc^T + bias)
// Bsrc is [256, K] row-major (output-col-major "B^T" operand).
// Optional B1s/B2s summed into B while staging (Wr fold).
// CTA: 256 thr, tile 128(M) x 128(N), grid.y=2 covers 256 cols.
// Warp grid 4(m) x 2(n); warp tile 32 x 64; K staged in 32-wide chunks.
// =====================================================================
#define PADK 36

__global__ void __launch_bounds__(256) gemm_tc(
        const float* __restrict__ A,
        const float* __restrict__ B0s, const float* __restrict__ B1s,
        const float* __restrict__ B2s,
        const float* __restrict__ bias, float* __restrict__ C,
        int Nrow, int K, int ldC, int relu) {
    __shared__ float As[128 * PADK];
    __shared__ float Bs[128 * PADK];
    const int tid  = threadIdx.x;
    const int lane = tid & 31;
    const int wid  = tid >> 5;
    const int wm   = wid & 3;            // 0..3  -> rows wm*32
    const int wn   = wid >> 2;           // 0..1  -> cols wn*64
    const int row0 = blockIdx.x * 128;
    const int col0 = blockIdx.y * 128;
    const int g4   = lane >> 2;          // 0..7
    const int t4   = lane & 3;           // 0..3
    const bool has3 = (B1s != nullptr);

    float acc[2][8][4];
#pragma unroll
    for (int mt = 0; mt < 2; mt++)
#pragma unroll
        for (int nt = 0; nt < 8; nt++)
#pragma unroll
            for (int q = 0; q < 4; q++) acc[mt][nt][q] = 0.f;

    const int nc = (K + 31) >> 5;
    for (int c = 0; c < nc; c++) {
        const int k0 = c << 5;
        if (c) __syncthreads();
        // ---- stage A & B tiles (128 x 32 each), tf32-rounded ----
#pragma unroll
        for (int it = 0; it < 4; it++) {
            const int idx = tid + it * 256;          // 0..1023
            const int rr  = idx >> 3;                // row 0..127
            const int cg  = (idx & 7) << 2;          // col 0,4,..,28
            const bool kok = (k0 + cg) < K;
            // A
            float4 v = make_float4(0.f, 0.f, 0.f, 0.f);
            const int gr = row0 + rr;
            if (gr < Nrow && kok)
                v = *reinterpret_cast<const float4*>(A + (size_t)gr * K + k0 + cg);
            uint4 qa = make_uint4(f2tf(v.x), f2tf(v.y), f2tf(v.z), f2tf(v.w));
            *reinterpret_cast<uint4*>(&As[rr * PADK + cg]) = qa;
            // B (row = output col col0+rr; Bsrc always has 256 rows)
            float4 w = make_float4(0.f, 0.f, 0.f, 0.f);
            if (kok) {
                const size_t bo = (size_t)(col0 + rr) * K + k0 + cg;
                w = *reinterpret_cast<const float4*>(B0s + bo);
                if (has3) {
                    float4 w1 = *reinterpret_cast<const float4*>(B1s + bo);
                    float4 w2 = *reinterpret_cast<const float4*>(B2s + bo);
                    w.x += w1.x + w2.x; w.y += w1.y + w2.y;
                    w.z += w1.z + w2.z; w.w += w1.w + w2.w;
                }
            }
            uint4 qb = make_uint4(f2tf(w.x), f2tf(w.y), f2tf(w.z), f2tf(w.w));
            *reinterpret_cast<uint4*>(&Bs[rr * PADK + cg]) = qb;
        }
        __syncthreads();
        // ---- compute: 4 k-steps of 8 ----
#pragma unroll
        for (int ks = 0; ks < 4; ks++) {
            const int kb = ks * 8;
            uint32_t af[2][4];
#pragma unroll
            for (int mt = 0; mt < 2; mt++) {
                const int r = wm * 32 + mt * 16 + g4;
                const int cA = kb + t4;
                af[mt][0] = __float_as_uint(As[r * PADK + cA]);
                af[mt][1] = __float_as_uint(As[(r + 8) * PADK + cA]);
                af[mt][2] = __float_as_uint(As[r * PADK + cA + 4]);
                af[mt][3] = __float_as_uint(As[(r + 8) * PADK + cA + 4]);
            }
#pragma unroll
            for (int nt = 0; nt < 8; nt++) {
                const int n = wn * 64 + nt * 8 + g4;
                const int kB = kb + t4;
                const uint32_t b0 = __float_as_uint(Bs[n * PADK + kB]);
                const uint32_t b1 = __float_as_uint(Bs[n * PADK + kB + 4]);
                mma_tf32_16n8k8(acc[0][nt], af[0], b0, b1);
                mma_tf32_16n8k8(acc[1][nt], af[1], b0, b1);
            }
        }
    }
    // ---- epilogue ----
#pragma unroll
    for (int mt = 0; mt < 2; mt++) {
#pragma unroll
        for (int h = 0; h < 2; h++) {
            const int gr = row0 + wm * 32 + mt * 16 + g4 + h * 8;
            if (gr >= Nrow) continue;
#pragma unroll
            for (int nt = 0; nt < 8; nt++) {
                const int col = col0 + wn * 64 + nt * 8 + t4 * 2;
                float2 v = make_float2(acc[mt][nt][h * 2 + 0], acc[mt][nt][h * 2 + 1]);
                if (bias) { v.x += __ldg(&bias[col]); v.y += __ldg(&bias[col + 1]); }
                if (relu) { v.x = fmaxf(v.x, 0.f); v.y = fmaxf(v.y, 0.f); }
                *reinterpret_cast<float2*>(C + (size_t)gr * ldC + col) = v;
            }
        }
    }
}

// =====================================================================
// aux kernels
// =====================================================================
// out[256,Kin] = in[Kin,256]^T
__global__ void transpose_k(const float* __restrict__ in, float* __restrict__ out, int Kin) {
    int k = blockIdx.x, n = threadIdx.x;
    out[(size_t)n * Kin + k] = in[(size_t)k * 256 + n];
}

// out[j] = sum_k (b1+b2+b3)[k]*B[k,j] + blin[j]
__global__ void fold_b(const float* __restrict__ b1, const float* __restrict__ b2,
                       const float* __restrict__ b3, const float* __restrict__ B,
                       const float* __restrict__ blin, float* __restrict__ out) {
    int j = threadIdx.x;
    float acc = blin[j];
    for (int k = 0; k < Hc; k++) {
        float bb = b1[k];
        if (b2) bb += b2[k];
        if (b3) bb += b3[k];
        acc = fmaf(bb, B[k * Hc + j], acc);
    }
    out[j] = acc;
}

__global__ void count_k(const int* __restrict__ dst, float* __restrict__ cnt, int E) {
    int i = blockIdx.x * blockDim.x + threadIdx.x;
    if (i < E) atomicAdd(&cnt[dst[i]], 1.f);
}

__global__ void inv_k(float* __restrict__ p, int n) {
    int i = blockIdx.x * blockDim.x + threadIdx.x;
    if (i < n) { float c = p[i]; p[i] = 1.f / (c < 1.f ? 1.f : c); }
}

// one edge handled by 64 threads; 4 floats each via vector atomic
__global__ void scatter_k(const int* __restrict__ src, const int* __restrict__ dst,
                          const float* __restrict__ x, float* __restrict__ X,
                          int ldX, int sec, int E) {
    int t = blockIdx.x * blockDim.x + threadIdx.x;
    int e = t >> 6, lane = t & 63;
    if (e >= E) return;
    int s = __ldg(&src[e]), d = __ldg(&dst[e]);
    float4 v = *reinterpret_cast<const float4*>(x + (size_t)s * Hc + lane * 4);
    red_add_v4(X + (size_t)d * ldX + sec + lane * 4, v);
}

__global__ void finalize_act_k(float* __restrict__ Xa, const float* __restrict__ a,
                               const float* __restrict__ invf, const float* __restrict__ invra,
                               const float* __restrict__ invta) {
    size_t t = (size_t)blockIdx.x * blockDim.x + threadIdx.x;
    int node = (int)(t >> 8), q = (int)(t & 255);
    if (node >= NACT) return;
    float4* row = reinterpret_cast<float4*>(Xa + (size_t)node * 1024);
    if (q < 192) {
        float s = (q < 64) ? invf[node] : (q < 128 ? invra[node] : invta[node]);
        float4 v = row[q];
        v.x *= s; v.y *= s; v.z *= s; v.w *= s;
        row[q] = v;
    } else {
        row[q] = reinterpret_cast<const float4*>(a + (size_t)node * Hc)[q - 192];
    }
}

__global__ void finalize2_k(float* __restrict__ X, const float* __restrict__ xd,
                            const float* __restrict__ inv, int N) {
    size_t t = (size_t)blockIdx.x * blockDim.x + threadIdx.x;
    int node = (int)(t >> 7), q = (int)(t & 127);
    if (node >= N) return;
    float4* row = reinterpret_cast<float4*>(X + (size_t)node * 512);
    if (q < 64) {
        float s = inv[node];
        float4 v = row[q];
        v.x *= s; v.y *= s; v.z *= s; v.w *= s;
        row[q] = v;
    } else {
        row[q] = reinterpret_cast<const float4*>(xd + (size_t)node * Hc)[q - 64];
    }
}

__global__ void last_k(const int* __restrict__ batch, int* __restrict__ last, int N) {
    int i = blockIdx.x * blockDim.x + threadIdx.x;
    if (i < N) {
        if (i == N - 1 || batch[i + 1] != batch[i]) last[batch[i]] = i;
    }
}

__global__ void heads_k(const float* __restrict__ a, const int* __restrict__ last,
                        const float* __restrict__ Wo, const float* __restrict__ bo,
                        const float* __restrict__ Wt, const float* __restrict__ bt,
                        const float* __restrict__ Wrm, const float* __restrict__ brm,
                        float* __restrict__ out) {
    int g = blockIdx.x;
    __shared__ float p[Hc];
    const float* row = a + (size_t)last[g] * Hc;
    for (int k = threadIdx.x; k < Hc; k += blockDim.x) p[k] = row[k];
    __syncthreads();
    int j = threadIdx.x;
    if (j < CC) {
        float acc = bo[j];
        for (int k = 0; k < Hc; k++) acc = fmaf(p[k], Wo[k * CC + j], acc);
        out[g * CC + j] = acc;
    } else if (j == CC) {
        float acc = bt[0];
        for (int k = 0; k < Hc; k++) acc = fmaf(p[k], Wt[k], acc);
        out[GG * CC + g] = acc;
    } else if (j == CC + 1) {
        float acc = brm[0];
        for (int k = 0; k < Hc; k++) acc = fmaf(p[k], Wrm[k], acc);
        out[GG * CC + GG + g] = acc;
    }
}

// =====================================================================
// host orchestration
// =====================================================================
extern "C" void kernel_launch(void* const* d_in, const int* in_sizes, int n_in,
                              void* d_out, int out_size) {
    float* buf = nullptr;
    cudaGetSymbolAddress((void**)&buf, g_buf);

    float* A    = buf + OFF_A;
    float* R    = buf + OFF_R;
    float* T    = buf + OFF_T;
    float* XA   = buf + OFF_XA;
    float* XR   = buf + OFF_XR;
    float* XT   = buf + OFF_XT;
    float* INV  = buf + OFF_INV;
    float* WF   = buf + OFF_WF;
    float* BF   = buf + OFF_BF;
    float* WLT  = buf + OFF_WLT;
    float* WPT  = buf + OFF_WPT;
    int*   LAST = reinterpret_cast<int*>(buf + OFF_LAST);

    const float* x_act  = (const float*)d_in[0];
    const float* x_res  = (const float*)d_in[1];
    const float* x_time = (const float*)d_in[2];
    const int* src_f  = (const int*)d_in[3];
    const int* dst_f  = (const int*)d_in[4];
    const int* src_ar = (const int*)d_in[5];
    const int* dst_ar = (const int*)d_in[6];
    const int* src_ra = (const int*)d_in[7];
    const int* dst_ra = (const int*)d_in[8];
    const int* src_at = (const int*)d_in[9];
    const int* dst_at = (const int*)d_in[10];
    const int* src_ta = (const int*)d_in[11];
    const int* dst_ta = (const int*)d_in[12];
    const int* batch  = (const int*)d_in[13];

    int w = (in_sizes[14] <= 4) ? 15 : 14;
    const float* Wp_act = (const float*)d_in[w + 0];
    const float* Wp_res = (const float*)d_in[w + 1];
    const float* Wp_tim = (const float*)d_in[w + 2];
    const float* Wl     = (const float*)d_in[w + 3];
    const float* bl     = (const float*)d_in[w + 4];
    const float* Wr     = (const float*)d_in[w + 5];
    const float* Wlin   = (const float*)d_in[w + 6];
    const float* blin   = (const float*)d_in[w + 7];
    const float* Wo     = (const float*)d_in[w + 8];
    const float* bo     = (const float*)d_in[w + 9];
    const float* Wt     = (const float*)d_in[w + 10];
    const float* bt     = (const float*)d_in[w + 11];
    const float* Wrm    = (const float*)d_in[w + 12];
    const float* brm    = (const float*)d_in[w + 13];

    const size_t HH = 65536;  // 256*256
    const dim3 g2(2, 2);      // 256-row GEMMs

    // --- transpose projection weights and Wlin (B-operand orientation) ---
    transpose_k<<<64, 256>>>(Wp_act, WPT + 0,     64);
    transpose_k<<<32, 256>>>(Wp_res, WPT + 16384, 32);
    transpose_k<<<16, 256>>>(Wp_tim, WPT + 24576, 16);
    for (int i = 0; i < 6; i++)
        transpose_k<<<256, 256>>>(Wlin + (size_t)i * HH, WLT + (size_t)i * HH, 256);

    // --- fold weights via tensor cores:
    //     B-ready WF[n,k] = (Wx @ Wlin)^T = Wlin^T @ Wx^T  ==  gemm(A=Wlin^T, Bsrc=Wx)
    for (int l = 0; l < 2; l++) {
        const float* lt0 = WLT + (size_t)(l * 3 + 0) * HH;
        const float* lt1 = WLT + (size_t)(l * 3 + 1) * HH;
        const float* lt2 = WLT + (size_t)(l * 3 + 2) * HH;
        float* WFa = WF + (size_t)l * 524288;           // [256,1024]
        float* WFr = WFa + 262144;                      // [256,512]
        float* WFt = WFa + 393216;                      // [256,512]
        gemm_tc<<<g2, 256>>>(lt0, Wl + (size_t)(l * 5 + 0) * HH, nullptr, nullptr,
                             nullptr, WFa + 0,   256, 256, 1024, 0);
        gemm_tc<<<g2, 256>>>(lt0, Wl + (size_t)(l * 5 + 2) * HH, nullptr, nullptr,
                             nullptr, WFa + 256, 256, 256, 1024, 0);
        gemm_tc<<<g2, 256>>>(lt0, Wl + (size_t)(l * 5 + 4) * HH, nullptr, nullptr,
                             nullptr, WFa + 512, 256, 256, 1024, 0);
        gemm_tc<<<g2, 256>>>(lt0, Wr + (size_t)(l * 5 + 0) * HH,
                             Wr + (size_t)(l * 5 + 2) * HH,
                             Wr + (size_t)(l * 5 + 4) * HH,
                             nullptr, WFa + 768, 256, 256, 1024, 0);
        gemm_tc<<<g2, 256>>>(lt1, Wl + (size_t)(l * 5 + 1) * HH, nullptr, nullptr,
                             nullptr, WFr + 0,   256, 256, 512, 0);
        gemm_tc<<<g2, 256>>>(lt1, Wr + (size_t)(l * 5 + 1) * HH, nullptr, nullptr,
                             nullptr, WFr + 256, 256, 256, 512, 0);
        gemm_tc<<<g2, 256>>>(lt2, Wl + (size_t)(l * 5 + 3) * HH, nullptr, nullptr,
                             nullptr, WFt + 0,   256, 256, 512, 0);
        gemm_tc<<<g2, 256>>>(lt2, Wr + (size_t)(l * 5 + 3) * HH, nullptr, nullptr,
                             nullptr, WFt + 256, 256, 256, 512, 0);
        fold_b<<<1, 256>>>(bl + (l * 5 + 0) * 256, bl + (l * 5 + 2) * 256,
                           bl + (l * 5 + 4) * 256, Wlin + (size_t)(l * 3 + 0) * HH,
                           blin + (l * 3 + 0) * 256, BF + l * 768 + 0);
        fold_b<<<1, 256>>>(bl + (l * 5 + 1) * 256, nullptr, nullptr,
                           Wlin + (size_t)(l * 3 + 1) * HH,
                           blin + (l * 3 + 1) * 256, BF + l * 768 + 256);
        fold_b<<<1, 256>>>(bl + (l * 5 + 3) * 256, nullptr, nullptr,
                           Wlin + (size_t)(l * 3 + 2) * HH,
                           blin + (l * 3 + 2) * 256, BF + l * 768 + 512);
    }

    // --- degree counts (layer-invariant) ---
    cudaMemsetAsync(INV, 0, 720000 * sizeof(float), 0);
    int cblk = (EE + 255) / 256;
    count_k<<<cblk, 256>>>(dst_f,  INV + 0,      EE);
    count_k<<<cblk, 256>>>(dst_ra, INV + 200000, EE);
    count_k<<<cblk, 256>>>(dst_ta, INV + 400000, EE);
    count_k<<<cblk, 256>>>(dst_ar, INV + 600000, EE);
    count_k<<<cblk, 256>>>(dst_at, INV + 620000, EE);
    inv_k<<<(720000 + 255) / 256, 256>>>(INV, 720000);

    // --- input projections (tensor cores) ---
    gemm_tc<<<dim3((NACT  + 127) / 128, 2), 256>>>(x_act,  WPT + 0,     nullptr, nullptr,
                                                   nullptr, A, NACT,  64, 256, 0);
    gemm_tc<<<dim3((NRES  + 127) / 128, 2), 256>>>(x_res,  WPT + 16384, nullptr, nullptr,
                                                   nullptr, R, NRES,  32, 256, 0);
    gemm_tc<<<dim3((NTIME + 127) / 128, 2), 256>>>(x_time, WPT + 24576, nullptr, nullptr,
                                                   nullptr, T, NTIME, 16, 256, 0);

    // --- layers ---
    int sblk = (EE * 64) / 256;
    for (int l = 0; l < 2; l++) {
        cudaMemsetAsync(XA, 0, (size_t)NACT  * 1024 * sizeof(float), 0);
        cudaMemsetAsync(XR, 0, (size_t)NRES  * 512  * sizeof(float), 0);
        cudaMemsetAsync(XT, 0, (size_t)NTIME * 512  * sizeof(float), 0);

        scatter_k<<<sblk, 256>>>(src_f,  dst_f,  A, XA, 1024, 0,   EE);
        scatter_k<<<sblk, 256>>>(src_ra, dst_ra, R, XA, 1024, 256, EE);
        scatter_k<<<sblk, 256>>>(src_ta, dst_ta, T, XA, 1024, 512, EE);
        scatter_k<<<sblk, 256>>>(src_ar, dst_ar, A, XR, 512,  0,   EE);
        scatter_k<<<sblk, 256>>>(src_at, dst_at, A, XT, 512,  0,   EE);

        finalize_act_k<<<NACT, 256>>>(XA, A, INV, INV + 200000, INV + 400000);
        finalize2_k<<<NRES / 2, 256>>>(XR, R, INV + 600000, NRES);
        finalize2_k<<<NTIME / 2, 256>>>(XT, T, INV + 620000, NTIME);

        float* WFa = WF + (size_t)l * 524288;
        gemm_tc<<<dim3((NACT  + 127) / 128, 2), 256>>>(XA, WFa, nullptr, nullptr,
            BF + l * 768 + 0,   A, NACT,  1024, 256, 1);
        gemm_tc<<<dim3((NRES  + 127) / 128, 2), 256>>>(XR, WFa + 262144, nullptr, nullptr,
            BF + l * 768 + 256, R, NRES,  512,  256, 1);
        gemm_tc<<<dim3((NTIME + 127) / 128, 2), 256>>>(XT, WFa + 393216, nullptr, nullptr,
            BF + l * 768 + 512, T, NTIME, 512,  256, 1);
    }

    // --- last-node pooling + heads ---
    cudaMemsetAsync(LAST, 0, GG * sizeof(int), 0);
    last_k<<<(NACT + 255) / 256, 256>>>(batch, LAST, NACT);
    heads_k<<<GG, 64>>>(A, LAST, Wo, bo, Wt, bt, Wrm, brm, (float*)d_out);
}

// round 8
// speedup vs baseline: 1.9945x; 1.5398x over previous
#include <cuda_runtime.h>
#include <cstdint>
#include <cstddef>

#define Hc    256
#define CC    50
#define GG    512
#define NACT  200000
#define NRES  20000
#define NTIME 100000
#define EE    400000

// ---------------- scratch layout (floats) ----------------
static constexpr size_t OFF_A    = 0;            // 200000*256
static constexpr size_t OFF_R    = 51200000;     // 20000*256
static constexpr size_t OFF_T    = 56320000;     // 100000*256
static constexpr size_t OFF_PA   = 81920000;     // 200000*1024  [f|ar|at|self]
static constexpr size_t OFF_PR   = 286720000;    // 20000*512    [ra|self]
static constexpr size_t OFF_PT   = 296960000;    // 100000*512   [ta|self]
static constexpr size_t OFF_WC   = 348160000;    // 2*524288 folded weight cats
static constexpr size_t OFF_BF   = 349208576;    // 2*3*256 folded biases
static constexpr size_t OFF_WLT  = 349210112;    // 6*65536 Wlin^T
static constexpr size_t OFF_WPT  = 349603328;    // 256*(64+32+16) Wp^T
static constexpr size_t OFF_LAST = 349632000;    // 512 ints
static constexpr size_t OFF_INT  = 349632512;    // int scratch region
static constexpr size_t TOTALF   = 353073552;

// int sub-offsets (in ints, relative to OFF_INT)
static constexpr size_t IO_OFF_F  = 0;        // 200001
static constexpr size_t IO_OFF_RA = 200001;   // 200001
static constexpr size_t IO_OFF_TA = 400002;   // 200001
static constexpr size_t IO_OFF_AR = 600003;   // 20001
static constexpr size_t IO_OFF_AT = 620004;   // 100001
static constexpr size_t IO_CUR    = 720005;   // 720005 (counts, then cursors)
static constexpr size_t IO_IDX    = 1440010;  // 5*400000
static constexpr size_t IO_BSUM   = 3440010;  // 1024

__device__ float g_buf[TOTALF];

// =====================================================================
// helpers
// =====================================================================
__device__ __forceinline__ uint32_t f2tf(float x) {
    uint32_t r;
    asm("cvt.rna.tf32.f32 %0, %1;" : "=r"(r) : "f"(x));
    return r;
}
__device__ __forceinline__ void mma_tf32_16n8k8(float* d, const uint32_t* a,
                                                uint32_t b0, uint32_t b1) {
    asm volatile(
        "mma.sync.aligned.m16n8k8.row.col.f32.tf32.tf32.f32 "
        "{%0,%1,%2,%3}, {%4,%5,%6,%7}, {%8,%9}, {%0,%1,%2,%3};"
        : "+f"(d[0]), "+f"(d[1]), "+f"(d[2]), "+f"(d[3])
        : "r"(a[0]), "r"(a[1]), "r"(a[2]), "r"(a[3]), "r"(b0), "r"(b1));
}

// =====================================================================
// tf32 mma.sync GEMM: C[Nrow, ldC] = A[Nrow,K] @ Bsrc^T (+ bias on cols>=bstart)
// Bsrc [gridDim.x*128, K] row-major. Optional B1s/B2s summed in while staging.
// grid: (colTiles, rowTiles) — col fastest for L2 reuse of A.
// =====================================================================
#define PADK 36

__global__ void __launch_bounds__(256) gemm_tc(
        const float* __restrict__ A,
        const float* __restrict__ B0s, const float* __restrict__ B1s,
        const float* __restrict__ B2s,
        const float* __restrict__ bias, int bstart, float* __restrict__ C,
        int Nrow, int K, int ldC) {
    __shared__ float As[128 * PADK];
    __shared__ float Bs[128 * PADK];
    const int tid  = threadIdx.x;
    const int lane = tid & 31;
    const int wid  = tid >> 5;
    const int wm   = wid & 3;            // rows wm*32
    const int wn   = wid >> 2;           // cols wn*64
    const int row0 = blockIdx.y * 128;
    const int col0 = blockIdx.x * 128;
    const int g4   = lane >> 2;
    const int t4   = lane & 3;
    const bool has3 = (B1s != nullptr);

    float acc[2][8][4];
#pragma unroll
    for (int mt = 0; mt < 2; mt++)
#pragma unroll
        for (int nt = 0; nt < 8; nt++)
#pragma unroll
            for (int q = 0; q < 4; q++) acc[mt][nt][q] = 0.f;

    const int nc = (K + 31) >> 5;
    for (int c = 0; c < nc; c++) {
        const int k0 = c << 5;
        if (c) __syncthreads();
#pragma unroll
        for (int it = 0; it < 4; it++) {
            const int idx = tid + it * 256;
            const int rr  = idx >> 3;
            const int cg  = (idx & 7) << 2;
            const bool kok = (k0 + cg) < K;
            float4 v = make_float4(0.f, 0.f, 0.f, 0.f);
            const int gr = row0 + rr;
            if (gr < Nrow && kok)
                v = *reinterpret_cast<const float4*>(A + (size_t)gr * K + k0 + cg);
            uint4 qa = make_uint4(f2tf(v.x), f2tf(v.y), f2tf(v.z), f2tf(v.w));
            *reinterpret_cast<uint4*>(&As[rr * PADK + cg]) = qa;
            float4 w = make_float4(0.f, 0.f, 0.f, 0.f);
            if (kok) {
                const size_t bo = (size_t)(col0 + rr) * K + k0 + cg;
                w = *reinterpret_cast<const float4*>(B0s + bo);
                if (has3) {
                    float4 w1 = *reinterpret_cast<const float4*>(B1s + bo);
                    float4 w2 = *reinterpret_cast<const float4*>(B2s + bo);
                    w.x += w1.x + w2.x; w.y += w1.y + w2.y;
                    w.z += w1.z + w2.z; w.w += w1.w + w2.w;
                }
            }
            uint4 qb = make_uint4(f2tf(w.x), f2tf(w.y), f2tf(w.z), f2tf(w.w));
            *reinterpret_cast<uint4*>(&Bs[rr * PADK + cg]) = qb;
        }
        __syncthreads();
#pragma unroll
        for (int ks = 0; ks < 4; ks++) {
            const int kb = ks * 8;
            uint32_t af[2][4];
#pragma unroll
            for (int mt = 0; mt < 2; mt++) {
                const int r = wm * 32 + mt * 16 + g4;
                const int cA = kb + t4;
                af[mt][0] = __float_as_uint(As[r * PADK + cA]);
                af[mt][1] = __float_as_uint(As[(r + 8) * PADK + cA]);
                af[mt][2] = __float_as_uint(As[r * PADK + cA + 4]);
                af[mt][3] = __float_as_uint(As[(r + 8) * PADK + cA + 4]);
            }
#pragma unroll
            for (int nt = 0; nt < 8; nt++) {
                const int n = wn * 64 + nt * 8 + g4;
                const int kB = kb + t4;
                const uint32_t b0 = __float_as_uint(Bs[n * PADK + kB]);
                const uint32_t b1 = __float_as_uint(Bs[n * PADK + kB + 4]);
                mma_tf32_16n8k8(acc[0][nt], af[0], b0, b1);
                mma_tf32_16n8k8(acc[1][nt], af[1], b0, b1);
            }
        }
    }
#pragma unroll
    for (int mt = 0; mt < 2; mt++) {
#pragma unroll
        for (int h = 0; h < 2; h++) {
            const int gr = row0 + wm * 32 + mt * 16 + g4 + h * 8;
            if (gr >= Nrow) continue;
#pragma unroll
            for (int nt = 0; nt < 8; nt++) {
                const int col = col0 + wn * 64 + nt * 8 + t4 * 2;
                float2 v = make_float2(acc[mt][nt][h * 2 + 0], acc[mt][nt][h * 2 + 1]);
                if (bias && col >= bstart) {
                    v.x += __ldg(&bias[col - bstart]);
                    v.y += __ldg(&bias[col - bstart + 1]);
                }
                *reinterpret_cast<float2*>(C + (size_t)gr * ldC + col) = v;
            }
        }
    }
}

// =====================================================================
// CSR build: count -> scan -> fill
// =====================================================================
__global__ void cnt_k(const int* __restrict__ dst, int* __restrict__ cnt, int E) {
    int i = blockIdx.x * blockDim.x + threadIdx.x;
    if (i < E) atomicAdd(&cnt[dst[i]], 1);
}
__global__ void scan1(const int* __restrict__ cnt, int* __restrict__ off,
                      int* __restrict__ bsum, int N) {
    __shared__ int sh[1024];
    int i = blockIdx.x * 1024 + threadIdx.x;
    int x = (i < N) ? cnt[i] : 0;
    sh[threadIdx.x] = x;
    __syncthreads();
    for (int d = 1; d < 1024; d <<= 1) {
        int t = (threadIdx.x >= d) ? sh[threadIdx.x - d] : 0;
        __syncthreads();
        sh[threadIdx.x] += t;
        __syncthreads();
    }
    int incl = sh[threadIdx.x];
    if (i < N) off[i] = incl - x;
    if (threadIdx.x == 1023) bsum[blockIdx.x] = incl;
}
__global__ void scan2(int* __restrict__ bsum, int B) {
    if (threadIdx.x == 0 && blockIdx.x == 0) {
        int run = 0;
        for (int i = 0; i < B; i++) { int t = bsum[i]; bsum[i] = run; run += t; }
    }
}
__global__ void scan3(int* __restrict__ off, const int* __restrict__ bsum, int N, int E) {
    int i = blockIdx.x * blockDim.x + threadIdx.x;
    if (i < N) off[i] += bsum[i >> 10];
    if (i == 0) off[N] = E;
}
__global__ void fill_k(const int* __restrict__ src, const int* __restrict__ dst,
                       int* __restrict__ cur, int* __restrict__ idx, int E) {
    int e = blockIdx.x * blockDim.x + threadIdx.x;
    if (e < E) {
        int p = atomicAdd(&cur[dst[e]], 1);
        idx[p] = src[e];
    }
}

// =====================================================================
// dst-centric gather (mean aggregate + self + relu), one warp per dst
// =====================================================================
__device__ __forceinline__ void accum_rel(const float* __restrict__ base, int stride,
                                          const int* __restrict__ off,
                                          const int* __restrict__ idx,
                                          int w, int lane, float4& a0, float4& a1) {
    int se = (lane < 2) ? __ldg(&off[w + lane]) : 0;
    int s = __shfl_sync(0xffffffffu, se, 0);
    int e = __shfl_sync(0xffffffffu, se, 1);
    if (e <= s) return;
    float sc = 1.f / (float)(e - s);
    float4 m0 = make_float4(0.f, 0.f, 0.f, 0.f);
    float4 m1 = make_float4(0.f, 0.f, 0.f, 0.f);
    for (int p = s; p < e; p++) {
        int sn = __ldg(&idx[p]);
        const float* row = base + (size_t)sn * stride;
        float4 v0 = *reinterpret_cast<const float4*>(row + lane * 4);
        float4 v1 = *reinterpret_cast<const float4*>(row + 128 + lane * 4);
        m0.x += v0.x; m0.y += v0.y; m0.z += v0.z; m0.w += v0.w;
        m1.x += v1.x; m1.y += v1.y; m1.z += v1.z; m1.w += v1.w;
    }
    a0.x += m0.x * sc; a0.y += m0.y * sc; a0.z += m0.z * sc; a0.w += m0.w * sc;
    a1.x += m1.x * sc; a1.y += m1.y * sc; a1.z += m1.z * sc; a1.w += m1.w * sc;
}
__device__ __forceinline__ float4 relu4(float4 v) {
    return make_float4(fmaxf(v.x, 0.f), fmaxf(v.y, 0.f), fmaxf(v.z, 0.f), fmaxf(v.w, 0.f));
}

__global__ void __launch_bounds__(256) gather_act(
        const float* __restrict__ Pa, const float* __restrict__ Pr,
        const float* __restrict__ Pt,
        const int* __restrict__ offF,  const int* __restrict__ idxF,
        const int* __restrict__ offRA, const int* __restrict__ idxRA,
        const int* __restrict__ offTA, const int* __restrict__ idxTA,
        float* __restrict__ Aout) {
    int w = (blockIdx.x * 256 + threadIdx.x) >> 5;
    int lane = threadIdx.x & 31;
    if (w >= NACT) return;
    const float* self = Pa + (size_t)w * 1024 + 768;
    float4 a0 = *reinterpret_cast<const float4*>(self + lane * 4);
    float4 a1 = *reinterpret_cast<const float4*>(self + 128 + lane * 4);
    accum_rel(Pa,       1024, offF,  idxF,  w, lane, a0, a1);
    accum_rel(Pr,       512,  offRA, idxRA, w, lane, a0, a1);
    accum_rel(Pt,       512,  offTA, idxTA, w, lane, a0, a1);
    a0 = relu4(a0); a1 = relu4(a1);
    float* o = Aout + (size_t)w * 256;
    *reinterpret_cast<float4*>(o + lane * 4) = a0;
    *reinterpret_cast<float4*>(o + 128 + lane * 4) = a1;
}

__global__ void __launch_bounds__(256) gather_one(
        const float* __restrict__ msgB, int msgStride,
        const float* __restrict__ selfB, int selfStride,
        const int* __restrict__ off, const int* __restrict__ idx,
        float* __restrict__ Out, int N) {
    int w = (blockIdx.x * 256 + threadIdx.x) >> 5;
    int lane = threadIdx.x & 31;
    if (w >= N) return;
    const float* self = selfB + (size_t)w * selfStride;
    float4 a0 = *reinterpret_cast<const float4*>(self + lane * 4);
    float4 a1 = *reinterpret_cast<const float4*>(self + 128 + lane * 4);
    accum_rel(msgB, msgStride, off, idx, w, lane, a0, a1);
    a0 = relu4(a0); a1 = relu4(a1);
    float* o = Out + (size_t)w * 256;
    *reinterpret_cast<float4*>(o + lane * 4) = a0;
    *reinterpret_cast<float4*>(o + 128 + lane * 4) = a1;
}

// =====================================================================
// misc kernels
// =====================================================================
// out[256,Kin] = in[Kin,256]^T
__global__ void transpose_k(const float* __restrict__ in, float* __restrict__ out, int Kin) {
    int k = blockIdx.x, n = threadIdx.x;
    out[(size_t)n * Kin + k] = in[(size_t)k * 256 + n];
}

__global__ void fold_b(const float* __restrict__ b1, const float* __restrict__ b2,
                       const float* __restrict__ b3, const float* __restrict__ B,
                       const float* __restrict__ blin, float* __restrict__ out) {
    int j = threadIdx.x;
    float acc = blin[j];
    for (int k = 0; k < Hc; k++) {
        float bb = b1[k];
        if (b2) bb += b2[k];
        if (b3) bb += b3[k];
        acc = fmaf(bb, B[k * Hc + j], acc);
    }
    out[j] = acc;
}

__global__ void last_k(const int* __restrict__ batch, int* __restrict__ last, int N) {
    int i = blockIdx.x * blockDim.x + threadIdx.x;
    if (i < N) {
        if (i == N - 1 || batch[i + 1] != batch[i]) last[batch[i]] = i;
    }
}

__global__ void heads_k(const float* __restrict__ a, const int* __restrict__ last,
                        const float* __restrict__ Wo, const float* __restrict__ bo,
                        const float* __restrict__ Wt, const float* __restrict__ bt,
                        const float* __restrict__ Wrm, const float* __restrict__ brm,
                        float* __restrict__ out) {
    int g = blockIdx.x;
    __shared__ float p[Hc];
    const float* row = a + (size_t)last[g] * Hc;
    for (int k = threadIdx.x; k < Hc; k += blockDim.x) p[k] = row[k];
    __syncthreads();
    int j = threadIdx.x;
    if (j < CC) {
        float acc = bo[j];
        for (int k = 0; k < Hc; k++) acc = fmaf(p[k], Wo[k * CC + j], acc);
        out[g * CC + j] = acc;
    } else if (j == CC) {
        float acc = bt[0];
        for (int k = 0; k < Hc; k++) acc = fmaf(p[k], Wt[k], acc);
        out[GG * CC + g] = acc;
    } else if (j == CC + 1) {
        float acc = brm[0];
        for (int k = 0; k < Hc; k++) acc = fmaf(p[k], Wrm[k], acc);
        out[GG * CC + GG + g] = acc;
    }
}

// =====================================================================
// host orchestration
// =====================================================================
static inline void run_scan(int* cnt, int* off, int* bsum, int N, int E) {
    int nb = (N + 1023) / 1024;
    scan1<<<nb, 1024>>>(cnt, off, bsum, N);
    scan2<<<1, 32>>>(bsum, nb);
    scan3<<<(N + 256) / 256, 256>>>(off, bsum, N, E);
}

extern "C" void kernel_launch(void* const* d_in, const int* in_sizes, int n_in,
                              void* d_out, int out_size) {
    float* buf = nullptr;
    cudaGetSymbolAddress((void**)&buf, g_buf);

    float* A    = buf + OFF_A;
    float* R    = buf + OFF_R;
    float* T    = buf + OFF_T;
    float* Pa   = buf + OFF_PA;
    float* Pr   = buf + OFF_PR;
    float* Pt   = buf + OFF_PT;
    float* WC   = buf + OFF_WC;
    float* BF   = buf + OFF_BF;
    float* WLT  = buf + OFF_WLT;
    float* WPT  = buf + OFF_WPT;
    int*   LAST = reinterpret_cast<int*>(buf + OFF_LAST);
    int*   IB   = reinterpret_cast<int*>(buf + OFF_INT);
    int* offF  = IB + IO_OFF_F;
    int* offRA = IB + IO_OFF_RA;
    int* offTA = IB + IO_OFF_TA;
    int* offAR = IB + IO_OFF_AR;
    int* offAT = IB + IO_OFF_AT;
    int* cur   = IB + IO_CUR;
    int* idx   = IB + IO_IDX;
    int* bsum  = IB + IO_BSUM;

    const float* x_act  = (const float*)d_in[0];
    const float* x_res  = (const float*)d_in[1];
    const float* x_time = (const float*)d_in[2];
    const int* src_f  = (const int*)d_in[3];
    const int* dst_f  = (const int*)d_in[4];
    const int* src_ar = (const int*)d_in[5];
    const int* dst_ar = (const int*)d_in[6];
    const int* src_ra = (const int*)d_in[7];
    const int* dst_ra = (const int*)d_in[8];
    const int* src_at = (const int*)d_in[9];
    const int* dst_at = (const int*)d_in[10];
    const int* src_ta = (const int*)d_in[11];
    const int* dst_ta = (const int*)d_in[12];
    const int* batch  = (const int*)d_in[13];

    int w = (in_sizes[14] <= 4) ? 15 : 14;
    const float* Wp_act = (const float*)d_in[w + 0];
    const float* Wp_res = (const float*)d_in[w + 1];
    const float* Wp_tim = (const float*)d_in[w + 2];
    const float* Wl     = (const float*)d_in[w + 3];
    const float* bl     = (const float*)d_in[w + 4];
    const float* Wr     = (const float*)d_in[w + 5];
    const float* Wlin   = (const float*)d_in[w + 6];
    const float* blin   = (const float*)d_in[w + 7];
    const float* Wo     = (const float*)d_in[w + 8];
    const float* bo     = (const float*)d_in[w + 9];
    const float* Wt     = (const float*)d_in[w + 10];
    const float* bt     = (const float*)d_in[w + 11];
    const float* Wrm    = (const float*)d_in[w + 12];
    const float* brm    = (const float*)d_in[w + 13];

    const size_t HH = 65536;  // 256*256
    const dim3 g2(2, 2);

    // --- transpose weights into B-operand orientation ---
    transpose_k<<<64, 256>>>(Wp_act, WPT + 0,     64);
    transpose_k<<<32, 256>>>(Wp_res, WPT + 16384, 32);
    transpose_k<<<16, 256>>>(Wp_tim, WPT + 24576, 16);
    for (int i = 0; i < 6; i++)
        transpose_k<<<256, 256>>>(Wlin + (size_t)i * HH, WLT + (size_t)i * HH, 256);

    // --- fold weights into Wcat sections (B-operand layout [n,k]) ---
    for (int l = 0; l < 2; l++) {
        const float* lt0 = WLT + (size_t)(l * 3 + 0) * HH;
        const float* lt1 = WLT + (size_t)(l * 3 + 1) * HH;
        const float* lt2 = WLT + (size_t)(l * 3 + 2) * HH;
        float* WCa = WC + (size_t)l * 524288;   // [1024,256]
        float* WCr = WCa + 262144;              // [512,256]
        float* WCt = WCr + 131072;              // [512,256]
        // act sections: f-msg | ar-msg | at-msg | self(sum Wr)
        gemm_tc<<<g2, 256>>>(lt0, Wl + (size_t)(l * 5 + 0) * HH, nullptr, nullptr,
                             nullptr, 0, WCa + 0,      256, 256, 256);
        gemm_tc<<<g2, 256>>>(lt1, Wl + (size_t)(l * 5 + 1) * HH, nullptr, nullptr,
                             nullptr, 0, WCa + 65536,  256, 256, 256);
        gemm_tc<<<g2, 256>>>(lt2, Wl + (size_t)(l * 5 + 3) * HH, nullptr, nullptr,
                             nullptr, 0, WCa + 131072, 256, 256, 256);
        gemm_tc<<<g2, 256>>>(lt0, Wr + (size_t)(l * 5 + 0) * HH,
                             Wr + (size_t)(l * 5 + 2) * HH,
                             Wr + (size_t)(l * 5 + 4) * HH,
                             nullptr, 0, WCa + 196608, 256, 256, 256);
        // res sections: ra-msg | self
        gemm_tc<<<g2, 256>>>(lt0, Wl + (size_t)(l * 5 + 2) * HH, nullptr, nullptr,
                             nullptr, 0, WCr + 0,      256, 256, 256);
        gemm_tc<<<g2, 256>>>(lt1, Wr + (size_t)(l * 5 + 1) * HH, nullptr, nullptr,
                             nullptr, 0, WCr + 65536,  256, 256, 256);
        // time sections: ta-msg | self
        gemm_tc<<<g2, 256>>>(lt0, Wl + (size_t)(l * 5 + 4) * HH, nullptr, nullptr,
                             nullptr, 0, WCt + 0,      256, 256, 256);
        gemm_tc<<<g2, 256>>>(lt2, Wr + (size_t)(l * 5 + 3) * HH, nullptr, nullptr,
                             nullptr, 0, WCt + 65536,  256, 256, 256);
        fold_b<<<1, 256>>>(bl + (l * 5 + 0) * 256, bl + (l * 5 + 2) * 256,
                           bl + (l * 5 + 4) * 256, Wlin + (size_t)(l * 3 + 0) * HH,
                           blin + (l * 3 + 0) * 256, BF + l * 768 + 0);
        fold_b<<<1, 256>>>(bl + (l * 5 + 1) * 256, nullptr, nullptr,
                           Wlin + (size_t)(l * 3 + 1) * HH,
                           blin + (l * 3 + 1) * 256, BF + l * 768 + 256);
        fold_b<<<1, 256>>>(bl + (l * 5 + 3) * 256, nullptr, nullptr,
                           Wlin + (size_t)(l * 3 + 2) * HH,
                           blin + (l * 3 + 2) * 256, BF + l * 768 + 512);
    }

    // --- CSR build (indices are layer-invariant) ---
    cudaMemsetAsync(cur, 0, 720005 * sizeof(int), 0);
    int cblk = (EE + 255) / 256;
    cnt_k<<<cblk, 256>>>(dst_f,  cur + IO_OFF_F,  EE);
    cnt_k<<<cblk, 256>>>(dst_ra, cur + IO_OFF_RA, EE);
    cnt_k<<<cblk, 256>>>(dst_ta, cur + IO_OFF_TA, EE);
    cnt_k<<<cblk, 256>>>(dst_ar, cur + IO_OFF_AR, EE);
    cnt_k<<<cblk, 256>>>(dst_at, cur + IO_OFF_AT, EE);
    run_scan(cur + IO_OFF_F,  offF,  bsum, NACT,  EE);
    run_scan(cur + IO_OFF_RA, offRA, bsum, NACT,  EE);
    run_scan(cur + IO_OFF_TA, offTA, bsum, NACT,  EE);
    run_scan(cur + IO_OFF_AR, offAR, bsum, NRES,  EE);
    run_scan(cur + IO_OFF_AT, offAT, bsum, NTIME, EE);
    cudaMemcpyAsync(cur, IB, 720005 * sizeof(int), cudaMemcpyDeviceToDevice, 0);
    fill_k<<<cblk, 256>>>(src_f,  dst_f,  cur + IO_OFF_F,  idx + 0,       EE);
    fill_k<<<cblk, 256>>>(src_ra, dst_ra, cur + IO_OFF_RA, idx + 400000,  EE);
    fill_k<<<cblk, 256>>>(src_ta, dst_ta, cur + IO_OFF_TA, idx + 800000,  EE);
    fill_k<<<cblk, 256>>>(src_ar, dst_ar, cur + IO_OFF_AR, idx + 1200000, EE);
    fill_k<<<cblk, 256>>>(src_at, dst_at, cur + IO_OFF_AT, idx + 1600000, EE);

    // --- input projections ---
    gemm_tc<<<dim3(2, (NACT  + 127) / 128), 256>>>(x_act,  WPT + 0,     nullptr, nullptr,
                                                   nullptr, 0, A, NACT,  64, 256);
    gemm_tc<<<dim3(2, (NRES  + 127) / 128), 256>>>(x_res,  WPT + 16384, nullptr, nullptr,
                                                   nullptr, 0, R, NRES,  32, 256);
    gemm_tc<<<dim3(2, (NTIME + 127) / 128), 256>>>(x_time, WPT + 24576, nullptr, nullptr,
                                                   nullptr, 0, T, NTIME, 16, 256);

    // --- layers: wide GEMM then dst-centric mean-gather + self + relu ---
    for (int l = 0; l < 2; l++) {
        float* WCa = WC + (size_t)l * 524288;
        float* WCr = WCa + 262144;
        float* WCt = WCr + 131072;
        gemm_tc<<<dim3(8, (NACT + 127) / 128), 256>>>(A, WCa, nullptr, nullptr,
            BF + l * 768 + 0,   768, Pa, NACT,  256, 1024);
        gemm_tc<<<dim3(4, (NRES + 127) / 128), 256>>>(R, WCr, nullptr, nullptr,
            BF + l * 768 + 256, 256, Pr, NRES,  256, 512);
        gemm_tc<<<dim3(4, (NTIME + 127) / 128), 256>>>(T, WCt, nullptr, nullptr,
            BF + l * 768 + 512, 256, Pt, NTIME, 256, 512);

        gather_act<<<NACT / 8, 256>>>(Pa, Pr, Pt,
                                      offF,  idx + 0,
                                      offRA, idx + 400000,
                                      offTA, idx + 800000, A);
        gather_one<<<NRES / 8, 256>>>(Pa + 256, 1024, Pr + 256, 512,
                                      offAR, idx + 1200000, R, NRES);
        gather_one<<<NTIME / 8, 256>>>(Pa + 512, 1024, Pt + 256, 512,
                                       offAT, idx + 1600000, T, NTIME);
    }

    // --- last-node pooling + heads ---
    cudaMemsetAsync(LAST, 0, GG * sizeof(int), 0);
    last_k<<<(NACT + 255) / 256, 256>>>(batch, LAST, NACT);
    heads_k<<<GG, 64>>>(A, LAST, Wo, bo, Wt, bt, Wrm, brm, (float*)d_out);
}

// round 10
// speedup vs baseline: 3.8628x; 1.9367x over previous
#include <cuda_runtime.h>
#include <cuda_fp16.h>
#include <cstdint>
#include <cstddef>

#define Hc    256
#define CC    50
#define GG    512
#define NACT  200000
#define NRES  20000
#define NTIME 100000
#define EE    400000

// ---------------- scratch layout (float units) ----------------
// features stored as __half (2 halves per float slot)
static constexpr size_t OFF_A    = 0;            // 200000*256 h = 25.6M f
static constexpr size_t OFF_R    = 25600000;     // 20000*256 h
static constexpr size_t OFF_T    = 28160000;     // 100000*256 h
static constexpr size_t OFF_PA   = 40960000;     // 200000*1024 h [f|ar|at|self]
static constexpr size_t OFF_PR   = 143360000;    // 20000*512 h   [ra|self]
static constexpr size_t OFF_PT   = 148480000;    // 100000*512 h  [ta|self]
static constexpr size_t OFF_WC   = 174080000;    // 2*524288 f32 folded weights
static constexpr size_t OFF_BF   = 175128576;    // 2*3*256 f32
static constexpr size_t OFF_WLT  = 175130112;    // 6*65536 f32 Wlin^T
static constexpr size_t OFF_WPT  = 175523328;    // 256*(64+32+16) f32 Wp^T
static constexpr size_t OFF_LAST = 175552000;    // 512 ints
static constexpr size_t OFF_INT  = 175552512;    // int scratch
static constexpr size_t TOTALF   = 178993600;

// int sub-offsets (ints, relative to OFF_INT)
static constexpr size_t IO_OFF_F  = 0;
static constexpr size_t IO_OFF_RA = 200001;
static constexpr size_t IO_OFF_TA = 400002;
static constexpr size_t IO_OFF_AR = 600003;
static constexpr size_t IO_OFF_AT = 620004;
static constexpr size_t IO_CUR    = 720005;
static constexpr size_t IO_IDX    = 1440010;   // 5*400000
static constexpr size_t IO_BSUM   = 3440010;   // 1024

__device__ float g_buf[TOTALF];

// =====================================================================
// helpers
// =====================================================================
__device__ __forceinline__ void mma_f16(float* d, const uint32_t* a,
                                        uint32_t b0, uint32_t b1) {
    asm volatile(
        "mma.sync.aligned.m16n8k16.row.col.f32.f16.f16.f32 "
        "{%0,%1,%2,%3}, {%4,%5,%6,%7}, {%8,%9}, {%0,%1,%2,%3};"
        : "+f"(d[0]), "+f"(d[1]), "+f"(d[2]), "+f"(d[3])
        : "r"(a[0]), "r"(a[1]), "r"(a[2]), "r"(a[3]), "r"(b0), "r"(b1));
}
__device__ __forceinline__ uint32_t packh2(float x, float y) {
    __half2 h = __float22half2_rn(make_float2(x, y));
    return *reinterpret_cast<uint32_t*>(&h);
}
__device__ __forceinline__ uint4 pack8(float4 a, float4 b) {
    return make_uint4(packh2(a.x, a.y), packh2(a.z, a.w),
                      packh2(b.x, b.y), packh2(b.z, b.w));
}
__device__ __forceinline__ void h8_to_f8(uint4 q, float* f) {
    const __half2* h = reinterpret_cast<const __half2*>(&q);
#pragma unroll
    for (int i = 0; i < 4; i++) {
        float2 t = __half22float2(h[i]);
        f[2 * i] = t.x; f[2 * i + 1] = t.y;
    }
}
__device__ __forceinline__ uint4 f8_to_h8(const float* f) {
    return make_uint4(packh2(f[0], f[1]), packh2(f[2], f[3]),
                      packh2(f[4], f[5]), packh2(f[6], f[7]));
}

// =====================================================================
// fp16 mma.sync GEMM: C[Nrow, ldC] = A[Nrow,K] @ Bsrc^T (+ bias cols>=bstart)
// Bsrc f32 [ncols, K] row-major, converted to fp16 while staging.
// AT = float|__half (A operand storage), CT = float|__half (output storage).
// CTA 256 thr, tile 128x128, warp tile 32x64, K-chunk 32.
// STRH = 40 halves (80B): 16B-aligned uint4 rows; frag-load word index
// 20*r + t4 enumerates all 32 banks over a warp -> conflict-free LDS.
// =====================================================================
#define STRH 40   // SMEM row stride in halves

template <typename AT, typename CT>
__global__ void __launch_bounds__(256) gemm_h(
        const AT* __restrict__ A,
        const float* __restrict__ B0s, const float* __restrict__ B1s,
        const float* __restrict__ B2s,
        const float* __restrict__ bias, int bstart, CT* __restrict__ C,
        int Nrow, int K, int ldC) {
    __shared__ __align__(16) __half As[128 * STRH];
    __shared__ __align__(16) __half Bs[128 * STRH];
    const int tid  = threadIdx.x;
    const int lane = tid & 31;
    const int wid  = tid >> 5;
    const int wm   = wid & 3;
    const int wn   = wid >> 2;
    const int row0 = blockIdx.y * 128;
    const int col0 = blockIdx.x * 128;
    const int g4   = lane >> 2;
    const int t4   = lane & 3;
    const bool has3 = (B1s != nullptr);

    float acc[2][8][4];
#pragma unroll
    for (int mt = 0; mt < 2; mt++)
#pragma unroll
        for (int nt = 0; nt < 8; nt++)
#pragma unroll
            for (int q = 0; q < 4; q++) acc[mt][nt][q] = 0.f;

    const int nc = (K + 31) >> 5;
    for (int c = 0; c < nc; c++) {
        const int k0 = c << 5;
        if (c) __syncthreads();
#pragma unroll
        for (int it = 0; it < 2; it++) {
            const int idx = tid + it * 256;        // 0..511
            const int rr  = idx >> 2;              // 0..127
            const int cg  = (idx & 3) << 3;        // 0,8,16,24 (halves)
            const bool kok = (k0 + cg) < K;
            // A tile
            uint4 qa = make_uint4(0, 0, 0, 0);
            const int gr = row0 + rr;
            if (gr < Nrow && kok) {
                if constexpr (sizeof(AT) == 2) {
                    qa = *reinterpret_cast<const uint4*>(
                        reinterpret_cast<const __half*>(A) + (size_t)gr * K + k0 + cg);
                } else {
                    const float* ap = reinterpret_cast<const float*>(A) +
                                      (size_t)gr * K + k0 + cg;
                    float4 v0 = *reinterpret_cast<const float4*>(ap);
                    float4 v1 = *reinterpret_cast<const float4*>(ap + 4);
                    qa = pack8(v0, v1);
                }
            }
            *reinterpret_cast<uint4*>(&As[rr * STRH + cg]) = qa;
            // B tile
            uint4 qb = make_uint4(0, 0, 0, 0);
            if (kok) {
                const size_t bo = (size_t)(col0 + rr) * K + k0 + cg;
                float4 w0 = *reinterpret_cast<const float4*>(B0s + bo);
                float4 w1 = *reinterpret_cast<const float4*>(B0s + bo + 4);
                if (has3) {
                    float4 a1 = *reinterpret_cast<const float4*>(B1s + bo);
                    float4 a2 = *reinterpret_cast<const float4*>(B1s + bo + 4);
                    float4 c1 = *reinterpret_cast<const float4*>(B2s + bo);
                    float4 c2 = *reinterpret_cast<const float4*>(B2s + bo + 4);
                    w0.x += a1.x + c1.x; w0.y += a1.y + c1.y;
                    w0.z += a1.z + c1.z; w0.w += a1.w + c1.w;
                    w1.x += a2.x + c2.x; w1.y += a2.y + c2.y;
                    w1.z += a2.z + c2.z; w1.w += a2.w + c2.w;
                }
                qb = pack8(w0, w1);
            }
            *reinterpret_cast<uint4*>(&Bs[rr * STRH + cg]) = qb;
        }
        __syncthreads();
#pragma unroll
        for (int ks = 0; ks < 2; ks++) {
            const int kb = ks << 4;
            uint32_t af[2][4];
#pragma unroll
            for (int mt = 0; mt < 2; mt++) {
                const int r = wm * 32 + mt * 16 + g4;
                const int base = r * STRH + kb + 2 * t4;
                af[mt][0] = *reinterpret_cast<const uint32_t*>(&As[base]);
                af[mt][1] = *reinterpret_cast<const uint32_t*>(&As[base + 8 * STRH]);
                af[mt][2] = *reinterpret_cast<const uint32_t*>(&As[base + 8]);
                af[mt][3] = *reinterpret_cast<const uint32_t*>(&As[base + 8 * STRH + 8]);
            }
#pragma unroll
            for (int nt = 0; nt < 8; nt++) {
                const int n = wn * 64 + nt * 8 + g4;
                const int bb = n * STRH + kb + 2 * t4;
                const uint32_t b0 = *reinterpret_cast<const uint32_t*>(&Bs[bb]);
                const uint32_t b1 = *reinterpret_cast<const uint32_t*>(&Bs[bb + 8]);
                mma_f16(acc[0][nt], af[0], b0, b1);
                mma_f16(acc[1][nt], af[1], b0, b1);
            }
        }
    }
#pragma unroll
    for (int mt = 0; mt < 2; mt++) {
#pragma unroll
        for (int h = 0; h < 2; h++) {
            const int gr = row0 + wm * 32 + mt * 16 + g4 + h * 8;
            if (gr >= Nrow) continue;
#pragma unroll
            for (int nt = 0; nt < 8; nt++) {
                const int col = col0 + wn * 64 + nt * 8 + t4 * 2;
                float2 v = make_float2(acc[mt][nt][h * 2 + 0], acc[mt][nt][h * 2 + 1]);
                if (bias && col >= bstart) {
                    v.x += __ldg(&bias[col - bstart]);
                    v.y += __ldg(&bias[col - bstart + 1]);
                }
                if constexpr (sizeof(CT) == 2) {
                    __half2 hv = __float22half2_rn(v);
                    *reinterpret_cast<__half2*>(
                        reinterpret_cast<__half*>(C) + (size_t)gr * ldC + col) = hv;
                } else {
                    *reinterpret_cast<float2*>(
                        reinterpret_cast<float*>(C) + (size_t)gr * ldC + col) = v;
                }
            }
        }
    }
}

// =====================================================================
// CSR build: count -> scan -> fill
// =====================================================================
__global__ void cnt_k(const int* __restrict__ dst, int* __restrict__ cnt, int E) {
    int i = blockIdx.x * blockDim.x + threadIdx.x;
    if (i < E) atomicAdd(&cnt[dst[i]], 1);
}
__global__ void scan1(const int* __restrict__ cnt, int* __restrict__ off,
                      int* __restrict__ bsum, int N) {
    __shared__ int sh[1024];
    int i = blockIdx.x * 1024 + threadIdx.x;
    int x = (i < N) ? cnt[i] : 0;
    sh[threadIdx.x] = x;
    __syncthreads();
    for (int d = 1; d < 1024; d <<= 1) {
        int t = (threadIdx.x >= d) ? sh[threadIdx.x - d] : 0;
        __syncthreads();
        sh[threadIdx.x] += t;
        __syncthreads();
    }
    int incl = sh[threadIdx.x];
    if (i < N) off[i] = incl - x;
    if (threadIdx.x == 1023) bsum[blockIdx.x] = incl;
}
__global__ void scan2(int* __restrict__ bsum, int B) {
    if (threadIdx.x == 0 && blockIdx.x == 0) {
        int run = 0;
        for (int i = 0; i < B; i++) { int t = bsum[i]; bsum[i] = run; run += t; }
    }
}
__global__ void scan3(int* __restrict__ off, const int* __restrict__ bsum, int N, int E) {
    int i = blockIdx.x * blockDim.x + threadIdx.x;
    if (i < N) off[i] += bsum[i >> 10];
    if (i == 0) off[N] = E;
}
__global__ void fill_k(const int* __restrict__ src, const int* __restrict__ dst,
                       int* __restrict__ cur, int* __restrict__ idx, int E) {
    int e = blockIdx.x * blockDim.x + threadIdx.x;
    if (e < E) {
        int p = atomicAdd(&cur[dst[e]], 1);
        idx[p] = src[e];
    }
}

// =====================================================================
// dst-centric gather (mean + self + relu), one warp per dst, fp16 rows
// =====================================================================
__device__ __forceinline__ void accum_rel(const __half* __restrict__ base, int stride,
                                          const int* __restrict__ off,
                                          const int* __restrict__ idx,
                                          int w, int lane, float* a) {
    int se = (lane < 2) ? __ldg(&off[w + lane]) : 0;
    int s = __shfl_sync(0xffffffffu, se, 0);
    int e = __shfl_sync(0xffffffffu, se, 1);
    if (e <= s) return;
    float sc = 1.f / (float)(e - s);
    float m[8] = {0.f, 0.f, 0.f, 0.f, 0.f, 0.f, 0.f, 0.f};
    for (int p = s; p < e; p++) {
        int sn = __ldg(&idx[p]);
        uint4 q = *reinterpret_cast<const uint4*>(base + (size_t)sn * stride + lane * 8);
        float f[8];
        h8_to_f8(q, f);
#pragma unroll
        for (int j = 0; j < 8; j++) m[j] += f[j];
    }
#pragma unroll
    for (int j = 0; j < 8; j++) a[j] += m[j] * sc;
}

__global__ void __launch_bounds__(256) gather_act(
        const __half* __restrict__ Pa, const __half* __restrict__ Pr,
        const __half* __restrict__ Pt,
        const int* __restrict__ offF,  const int* __restrict__ idxF,
        const int* __restrict__ offRA, const int* __restrict__ idxRA,
        const int* __restrict__ offTA, const int* __restrict__ idxTA,
        __half* __restrict__ Aout) {
    int w = (blockIdx.x * 256 + threadIdx.x) >> 5;
    int lane = threadIdx.x & 31;
    if (w >= NACT) return;
    float a[8];
    h8_to_f8(*reinterpret_cast<const uint4*>(Pa + (size_t)w * 1024 + 768 + lane * 8), a);
    accum_rel(Pa, 1024, offF,  idxF,  w, lane, a);
    accum_rel(Pr, 512,  offRA, idxRA, w, lane, a);
    accum_rel(Pt, 512,  offTA, idxTA, w, lane, a);
#pragma unroll
    for (int j = 0; j < 8; j++) a[j] = fmaxf(a[j], 0.f);
    *reinterpret_cast<uint4*>(Aout + (size_t)w * 256 + lane * 8) = f8_to_h8(a);
}

__global__ void __launch_bounds__(256) gather_one(
        const __half* __restrict__ msgB, int msgStride,
        const __half* __restrict__ selfB, int selfStride,
        const int* __restrict__ off, const int* __restrict__ idx,
        __half* __restrict__ Out, int N) {
    int w = (blockIdx.x * 256 + threadIdx.x) >> 5;
    int lane = threadIdx.x & 31;
    if (w >= N) return;
    float a[8];
    h8_to_f8(*reinterpret_cast<const uint4*>(selfB + (size_t)w * selfStride + lane * 8), a);
    accum_rel(msgB, msgStride, off, idx, w, lane, a);
#pragma unroll
    for (int j = 0; j < 8; j++) a[j] = fmaxf(a[j], 0.f);
    *reinterpret_cast<uint4*>(Out + (size_t)w * 256 + lane * 8) = f8_to_h8(a);
}

// =====================================================================
// misc kernels
// =====================================================================
__global__ void transpose_k(const float* __restrict__ in, float* __restrict__ out, int Kin) {
    int k = blockIdx.x, n = threadIdx.x;
    out[(size_t)n * Kin + k] = in[(size_t)k * 256 + n];
}

__global__ void fold_b(const float* __restrict__ b1, const float* __restrict__ b2,
                       const float* __restrict__ b3, const float* __restrict__ B,
                       const float* __restrict__ blin, float* __restrict__ out) {
    int j = threadIdx.x;
    float acc = blin[j];
    for (int k = 0; k < Hc; k++) {
        float bb = b1[k];
        if (b2) bb += b2[k];
        if (b3) bb += b3[k];
        acc = fmaf(bb, B[k * Hc + j], acc);
    }
    out[j] = acc;
}

__global__ void last_k(const int* __restrict__ batch, int* __restrict__ last, int N) {
    int i = blockIdx.x * blockDim.x + threadIdx.x;
    if (i < N) {
        if (i == N - 1 || batch[i + 1] != batch[i]) last[batch[i]] = i;
    }
}

__global__ void heads_k(const __half* __restrict__ a, const int* __restrict__ last,
                        const float* __restrict__ Wo, const float* __restrict__ bo,
                        const float* __restrict__ Wt, const float* __restrict__ bt,
                        const float* __restrict__ Wrm, const float* __restrict__ brm,
                        float* __restrict__ out) {
    int g = blockIdx.x;
    __shared__ float p[Hc];
    const __half* row = a + (size_t)last[g] * Hc;
    for (int k = threadIdx.x; k < Hc; k += blockDim.x) p[k] = __half2float(row[k]);
    __syncthreads();
    int j = threadIdx.x;
    if (j < CC) {
        float acc = bo[j];
        for (int k = 0; k < Hc; k++) acc = fmaf(p[k], Wo[k * CC + j], acc);
        out[g * CC + j] = acc;
    } else if (j == CC) {
        float acc = bt[0];
        for (int k = 0; k < Hc; k++) acc = fmaf(p[k], Wt[k], acc);
        out[GG * CC + g] = acc;
    } else if (j == CC + 1) {
        float acc = brm[0];
        for (int k = 0; k < Hc; k++) acc = fmaf(p[k], Wrm[k], acc);
        out[GG * CC + GG + g] = acc;
    }
}

// =====================================================================
// host orchestration
// =====================================================================
static inline void run_scan(int* cnt, int* off, int* bsum, int N, int E) {
    int nb = (N + 1023) / 1024;
    scan1<<<nb, 1024>>>(cnt, off, bsum, N);
    scan2<<<1, 32>>>(bsum, nb);
    scan3<<<(N + 256) / 256, 256>>>(off, bsum, N, E);
}

extern "C" void kernel_launch(void* const* d_in, const int* in_sizes, int n_in,
                              void* d_out, int out_size) {
    float* buf = nullptr;
    cudaGetSymbolAddress((void**)&buf, g_buf);

    __half* A  = reinterpret_cast<__half*>(buf + OFF_A);
    __half* R  = reinterpret_cast<__half*>(buf + OFF_R);
    __half* T  = reinterpret_cast<__half*>(buf + OFF_T);
    __half* Pa = reinterpret_cast<__half*>(buf + OFF_PA);
    __half* Pr = reinterpret_cast<__half*>(buf + OFF_PR);
    __half* Pt = reinterpret_cast<__half*>(buf + OFF_PT);
    float* WC  = buf + OFF_WC;
    float* BF  = buf + OFF_BF;
    float* WLT = buf + OFF_WLT;
    float* WPT = buf + OFF_WPT;
    int*   LAST = reinterpret_cast<int*>(buf + OFF_LAST);
    int*   IB   = reinterpret_cast<int*>(buf + OFF_INT);
    int* offF  = IB + IO_OFF_F;
    int* offRA = IB + IO_OFF_RA;
    int* offTA = IB + IO_OFF_TA;
    int* offAR = IB + IO_OFF_AR;
    int* offAT = IB + IO_OFF_AT;
    int* cur   = IB + IO_CUR;
    int* idx   = IB + IO_IDX;
    int* bsum  = IB + IO_BSUM;

    const float* x_act  = (const float*)d_in[0];
    const float* x_res  = (const float*)d_in[1];
    const float* x_time = (const float*)d_in[2];
    const int* src_f  = (const int*)d_in[3];
    const int* dst_f  = (const int*)d_in[4];
    const int* src_ar = (const int*)d_in[5];
    const int* dst_ar = (const int*)d_in[6];
    const int* src_ra = (const int*)d_in[7];
    const int* dst_ra = (const int*)d_in[8];
    const int* src_at = (const int*)d_in[9];
    const int* dst_at = (const int*)d_in[10];
    const int* src_ta = (const int*)d_in[11];
    const int* dst_ta = (const int*)d_in[12];
    const int* batch  = (const int*)d_in[13];

    int w = (in_sizes[14] <= 4) ? 15 : 14;
    const float* Wp_act = (const float*)d_in[w + 0];
    const float* Wp_res = (const float*)d_in[w + 1];
    const float* Wp_tim = (const float*)d_in[w + 2];
    const float* Wl     = (const float*)d_in[w + 3];
    const float* bl     = (const float*)d_in[w + 4];
    const float* Wr     = (const float*)d_in[w + 5];
    const float* Wlin   = (const float*)d_in[w + 6];
    const float* blin   = (const float*)d_in[w + 7];
    const float* Wo     = (const float*)d_in[w + 8];
    const float* bo     = (const float*)d_in[w + 9];
    const float* Wt     = (const float*)d_in[w + 10];
    const float* bt     = (const float*)d_in[w + 11];
    const float* Wrm    = (const float*)d_in[w + 12];
    const float* brm    = (const float*)d_in[w + 13];

    const size_t HH = 65536;  // 256*256
    const dim3 g2(2, 2);

    // --- transpose weights into B-operand orientation ---
    transpose_k<<<64, 256>>>(Wp_act, WPT + 0,     64);
    transpose_k<<<32, 256>>>(Wp_res, WPT + 16384, 32);
    transpose_k<<<16, 256>>>(Wp_tim, WPT + 24576, 16);
    for (int i = 0; i < 6; i++)
        transpose_k<<<256, 256>>>(Wlin + (size_t)i * HH, WLT + (size_t)i * HH, 256);

    // --- fold weights into Wcat sections (B-operand layout [n,k], f32 out) ---
    for (int l = 0; l < 2; l++) {
        const float* lt0 = WLT + (size_t)(l * 3 + 0) * HH;
        const float* lt1 = WLT + (size_t)(l * 3 + 1) * HH;
        const float* lt2 = WLT + (size_t)(l * 3 + 2) * HH;
        float* WCa = WC + (size_t)l * 524288;   // [1024,256]
        float* WCr = WCa + 262144;              // [512,256]
        float* WCt = WCr + 131072;              // [512,256]
        gemm_h<float, float><<<g2, 256>>>(lt0, Wl + (size_t)(l * 5 + 0) * HH, nullptr,
                                          nullptr, nullptr, 0, WCa + 0,      256, 256, 256);
        gemm_h<float, float><<<g2, 256>>>(lt1, Wl + (size_t)(l * 5 + 1) * HH, nullptr,
                                          nullptr, nullptr, 0, WCa + 65536,  256, 256, 256);
        gemm_h<float, float><<<g2, 256>>>(lt2, Wl + (size_t)(l * 5 + 3) * HH, nullptr,
                                          nullptr, nullptr, 0, WCa + 131072, 256, 256, 256);
        gemm_h<float, float><<<g2, 256>>>(lt0, Wr + (size_t)(l * 5 + 0) * HH,
                                          Wr + (size_t)(l * 5 + 2) * HH,
                                          Wr + (size_t)(l * 5 + 4) * HH,
                                          nullptr, 0, WCa + 196608, 256, 256, 256);
        gemm_h<float, float><<<g2, 256>>>(lt0, Wl + (size_t)(l * 5 + 2) * HH, nullptr,
                                          nullptr, nullptr, 0, WCr + 0,      256, 256, 256);
        gemm_h<float, float><<<g2, 256>>>(lt1, Wr + (size_t)(l * 5 + 1) * HH, nullptr,
                                          nullptr, nullptr, 0, WCr + 65536,  256, 256, 256);
        gemm_h<float, float><<<g2, 256>>>(lt0, Wl + (size_t)(l * 5 + 4) * HH, nullptr,
                                          nullptr, nullptr, 0, WCt + 0,      256, 256, 256);
        gemm_h<float, float><<<g2, 256>>>(lt2, Wr + (size_t)(l * 5 + 3) * HH, nullptr,
                                          nullptr, nullptr, 0, WCt + 65536,  256, 256, 256);
        fold_b<<<1, 256>>>(bl + (l * 5 + 0) * 256, bl + (l * 5 + 2) * 256,
                           bl + (l * 5 + 4) * 256, Wlin + (size_t)(l * 3 + 0) * HH,
                           blin + (l * 3 + 0) * 256, BF + l * 768 + 0);
        fold_b<<<1, 256>>>(bl + (l * 5 + 1) * 256, nullptr, nullptr,
                           Wlin + (size_t)(l * 3 + 1) * HH,
                           blin + (l * 3 + 1) * 256, BF + l * 768 + 256);
        fold_b<<<1, 256>>>(bl + (l * 5 + 3) * 256, nullptr, nullptr,
                           Wlin + (size_t)(l * 3 + 2) * HH,
                           blin + (l * 3 + 2) * 256, BF + l * 768 + 512);
    }

    // --- CSR build (indices layer-invariant) ---
    cudaMemsetAsync(cur, 0, 720005 * sizeof(int), 0);
    int cblk = (EE + 255) / 256;
    cnt_k<<<cblk, 256>>>(dst_f,  cur + IO_OFF_F,  EE);
    cnt_k<<<cblk, 256>>>(dst_ra, cur + IO_OFF_RA, EE);
    cnt_k<<<cblk, 256>>>(dst_ta, cur + IO_OFF_TA, EE);
    cnt_k<<<cblk, 256>>>(dst_ar, cur + IO_OFF_AR, EE);
    cnt_k<<<cblk, 256>>>(dst_at, cur + IO_OFF_AT, EE);
    run_scan(cur + IO_OFF_F,  offF,  bsum, NACT,  EE);
    run_scan(cur + IO_OFF_RA, offRA, bsum, NACT,  EE);
    run_scan(cur + IO_OFF_TA, offTA, bsum, NACT,  EE);
    run_scan(cur + IO_OFF_AR, offAR, bsum, NRES,  EE);
    run_scan(cur + IO_OFF_AT, offAT, bsum, NTIME, EE);
    cudaMemcpyAsync(cur, IB, 720005 * sizeof(int), cudaMemcpyDeviceToDevice, 0);
    fill_k<<<cblk, 256>>>(src_f,  dst_f,  cur + IO_OFF_F,  idx + 0,       EE);
    fill_k<<<cblk, 256>>>(src_ra, dst_ra, cur + IO_OFF_RA, idx + 400000,  EE);
    fill_k<<<cblk, 256>>>(src_ta, dst_ta, cur + IO_OFF_TA, idx + 800000,  EE);
    fill_k<<<cblk, 256>>>(src_ar, dst_ar, cur + IO_OFF_AR, idx + 1200000, EE);
    fill_k<<<cblk, 256>>>(src_at, dst_at, cur + IO_OFF_AT, idx + 1600000, EE);

    // --- input projections (f32 in, fp16 out) ---
    gemm_h<float, __half><<<dim3(2, (NACT  + 127) / 128), 256>>>(
        x_act,  WPT + 0,     nullptr, nullptr, nullptr, 0, A, NACT,  64, 256);
    gemm_h<float, __half><<<dim3(2, (NRES  + 127) / 128), 256>>>(
        x_res,  WPT + 16384, nullptr, nullptr, nullptr, 0, R, NRES,  32, 256);
    gemm_h<float, __half><<<dim3(2, (NTIME + 127) / 128), 256>>>(
        x_time, WPT + 24576, nullptr, nullptr, nullptr, 0, T, NTIME, 16, 256);

    // --- layers: wide GEMM then dst-centric mean-gather + self + relu ---
    for (int l = 0; l < 2; l++) {
        float* WCa = WC + (size_t)l * 524288;
        float* WCr = WCa + 262144;
        float* WCt = WCr + 131072;
        gemm_h<__half, __half><<<dim3(8, (NACT + 127) / 128), 256>>>(
            A, WCa, nullptr, nullptr, BF + l * 768 + 0,   768, Pa, NACT,  256, 1024);
        gemm_h<__half, __half><<<dim3(4, (NRES + 127) / 128), 256>>>(
            R, WCr, nullptr, nullptr, BF + l * 768 + 256, 256, Pr, NRES,  256, 512);
        gemm_h<__half, __half><<<dim3(4, (NTIME + 127) / 128), 256>>>(
            T, WCt, nullptr, nullptr, BF + l * 768 + 512, 256, Pt, NTIME, 256, 512);

        gather_act<<<NACT / 8, 256>>>(Pa, Pr, Pt,
                                      offF,  idx + 0,
                                      offRA, idx + 400000,
                                      offTA, idx + 800000, A);
        gather_one<<<NRES / 8, 256>>>(Pa + 256, 1024, Pr + 256, 512,
                                      offAR, idx + 1200000, R, NRES);
        gather_one<<<NTIME / 8, 256>>>(Pa + 512, 1024, Pt + 256, 512,
                                       offAT, idx + 1600000, T, NTIME);
    }

    // --- last-node pooling + heads ---
    cudaMemsetAsync(LAST, 0, GG * sizeof(int), 0);
    last_k<<<(NACT + 255) / 256, 256>>>(batch, LAST, NACT);
    heads_k<<<GG, 64>>>(A, LAST, Wo, bo, Wt, bt, Wrm, brm, (float*)d_out);
}

// round 11
// speedup vs baseline: 4.5022x; 1.1655x over previous
#include <cuda_runtime.h>
#include <cuda_fp16.h>
#include <cstdint>
#include <cstddef>

#define Hc    256
#define CC    50
#define GG    512
#define NACT  200000
#define NRES  20000
#define NTIME 100000
#define EE    400000

// ---------------- scratch layout (float units) ----------------
static constexpr size_t OFF_A    = 0;            // 200000*256 h
static constexpr size_t OFF_R    = 25600000;     // 20000*256 h
static constexpr size_t OFF_T    = 28160000;     // 100000*256 h
static constexpr size_t OFF_PA   = 40960000;     // 200000*1024 h [f|ar|at|self]
static constexpr size_t OFF_PR   = 143360000;    // 20000*512 h   [ra|self]
static constexpr size_t OFF_PT   = 148480000;    // 100000*512 h  [ta|self]
static constexpr size_t OFF_WC   = 174080000;    // 2*524288 halves folded weights (fp16)
static constexpr size_t OFF_BF   = 175128576;    // 2*3*256 f32
static constexpr size_t OFF_WLT  = 175130112;    // 6*65536 f32 Wlin^T
static constexpr size_t OFF_WPT  = 175523328;    // 256*(64+32+16) f32 Wp^T
static constexpr size_t OFF_LAST = 175552000;    // 512 ints
static constexpr size_t OFF_INT  = 175552512;    // int scratch
static constexpr size_t TOTALF   = 178993600;

static constexpr size_t IO_OFF_F  = 0;
static constexpr size_t IO_OFF_RA = 200001;
static constexpr size_t IO_OFF_TA = 400002;
static constexpr size_t IO_OFF_AR = 600003;
static constexpr size_t IO_OFF_AT = 620004;
static constexpr size_t IO_CUR    = 720005;
static constexpr size_t IO_IDX    = 1440010;   // 5*400000
static constexpr size_t IO_BSUM   = 3440010;   // 1024

__device__ float g_buf[TOTALF];

// =====================================================================
// helpers
// =====================================================================
__device__ __forceinline__ void mma_f16(float* d, const uint32_t* a,
                                        uint32_t b0, uint32_t b1) {
    asm volatile(
        "mma.sync.aligned.m16n8k16.row.col.f32.f16.f16.f32 "
        "{%0,%1,%2,%3}, {%4,%5,%6,%7}, {%8,%9}, {%0,%1,%2,%3};"
        : "+f"(d[0]), "+f"(d[1]), "+f"(d[2]), "+f"(d[3])
        : "r"(a[0]), "r"(a[1]), "r"(a[2]), "r"(a[3]), "r"(b0), "r"(b1));
}
__device__ __forceinline__ void ldsm4(uint32_t* r, uint32_t addr) {
    asm volatile("ldmatrix.sync.aligned.m8n8.x4.shared.b16 {%0,%1,%2,%3}, [%4];"
                 : "=r"(r[0]), "=r"(r[1]), "=r"(r[2]), "=r"(r[3]) : "r"(addr));
}
__device__ __forceinline__ void cp16(uint32_t dst, const void* src, int szbytes) {
    asm volatile("cp.async.cg.shared.global [%0], [%1], 16, %2;"
                 :: "r"(dst), "l"(src), "r"(szbytes));
}
#define CP_COMMIT() asm volatile("cp.async.commit_group;" ::: "memory")
template <int N>
__device__ __forceinline__ void cp_wait() {
    asm volatile("cp.async.wait_group %0;" :: "n"(N) : "memory");
}
__device__ __forceinline__ uint32_t saddr(const void* p) {
    return static_cast<uint32_t>(__cvta_generic_to_shared(p));
}
__device__ __forceinline__ uint32_t packh2(float x, float y) {
    __half2 h = __float22half2_rn(make_float2(x, y));
    return *reinterpret_cast<uint32_t*>(&h);
}
__device__ __forceinline__ uint4 pack8(float4 a, float4 b) {
    return make_uint4(packh2(a.x, a.y), packh2(a.z, a.w),
                      packh2(b.x, b.y), packh2(b.z, b.w));
}
__device__ __forceinline__ void h8_to_f8(uint4 q, float* f) {
    const __half2* h = reinterpret_cast<const __half2*>(&q);
#pragma unroll
    for (int i = 0; i < 4; i++) {
        float2 t = __half22float2(h[i]);
        f[2 * i] = t.x; f[2 * i + 1] = t.y;
    }
}
__device__ __forceinline__ uint4 f8_to_h8(const float* f) {
    return make_uint4(packh2(f[0], f[1]), packh2(f[2], f[3]),
                      packh2(f[4], f[5]), packh2(f[6], f[7]));
}

#define STRH 40   // SMEM row stride in halves (80B: 16B-aligned, ldsm conflict-free)

// =====================================================================
// FAST PATH: fp16 A (gmem) x fp16 B (gmem) -> fp16 C, K % 32 == 0.
// Double-buffered cp.async staging + ldmatrix fragments.
// CTA 256 thr, tile 128x128, warp tile 32x64. grid (colTiles, rowTiles).
// =====================================================================
__global__ void __launch_bounds__(256) gemm_fast(
        const __half* __restrict__ A, const __half* __restrict__ B,
        const float* __restrict__ bias, int bstart, __half* __restrict__ C,
        int Nrow, int K, int ldC) {
    __shared__ __align__(16) __half As[2][128 * STRH];
    __shared__ __align__(16) __half Bs[2][128 * STRH];
    const int tid  = threadIdx.x;
    const int lane = tid & 31;
    const int wid  = tid >> 5;
    const int wm   = wid & 3;
    const int wn   = wid >> 2;
    const int row0 = blockIdx.y * 128;
    const int col0 = blockIdx.x * 128;
    const int t4   = lane & 3;
    const int g4   = lane >> 2;
    // ldmatrix lane->address decomposition
    const int arow = lane & 15;
    const int acol = (lane >> 4) << 3;
    const int brow = (lane & 7) + ((lane >> 4) << 3);
    const int bcol = ((lane >> 3) & 1) << 3;

    float acc[2][8][4];
#pragma unroll
    for (int mt = 0; mt < 2; mt++)
#pragma unroll
        for (int nt = 0; nt < 8; nt++)
#pragma unroll
            for (int q = 0; q < 4; q++) acc[mt][nt][q] = 0.f;

    const int nc = K >> 5;

    auto stage = [&](int c, int b) {
        const int k0 = c << 5;
#pragma unroll
        for (int it = 0; it < 2; it++) {
            const int i  = tid + it * 256;       // 0..511
            const int rr = i >> 2;
            const int sg = (i & 3) << 3;         // 0,8,16,24 halves
            const int gr = row0 + rr;
            const int grc = gr < Nrow ? gr : (Nrow - 1);
            cp16(saddr(&As[b][rr * STRH + sg]),
                 A + (size_t)grc * K + k0 + sg, gr < Nrow ? 16 : 0);
            cp16(saddr(&Bs[b][rr * STRH + sg]),
                 B + (size_t)(col0 + rr) * K + k0 + sg, 16);
        }
    };

    stage(0, 0);
    CP_COMMIT();
    for (int c = 0; c < nc; c++) {
        const int cb = c & 1;
        if (c + 1 < nc) { stage(c + 1, cb ^ 1); CP_COMMIT(); cp_wait<1>(); }
        else            { cp_wait<0>(); }
        __syncthreads();
#pragma unroll
        for (int ks = 0; ks < 2; ks++) {
            const int kb = ks << 4;
            uint32_t af[2][4];
#pragma unroll
            for (int mt = 0; mt < 2; mt++)
                ldsm4(af[mt], saddr(&As[cb][(wm * 32 + mt * 16 + arow) * STRH + kb + acol]));
            uint32_t bf[4][4];
#pragma unroll
            for (int p = 0; p < 4; p++)
                ldsm4(bf[p], saddr(&Bs[cb][(wn * 64 + p * 16 + brow) * STRH + kb + bcol]));
#pragma unroll
            for (int nt = 0; nt < 8; nt++) {
                const uint32_t b0 = bf[nt >> 1][(nt & 1) * 2];
                const uint32_t b1 = bf[nt >> 1][(nt & 1) * 2 + 1];
                mma_f16(acc[0][nt], af[0], b0, b1);
                mma_f16(acc[1][nt], af[1], b0, b1);
            }
        }
        __syncthreads();
    }
#pragma unroll
    for (int mt = 0; mt < 2; mt++) {
#pragma unroll
        for (int h = 0; h < 2; h++) {
            const int gr = row0 + wm * 32 + mt * 16 + g4 + h * 8;
            if (gr >= Nrow) continue;
#pragma unroll
            for (int nt = 0; nt < 8; nt++) {
                const int col = col0 + wn * 64 + nt * 8 + t4 * 2;
                float2 v = make_float2(acc[mt][nt][h * 2 + 0], acc[mt][nt][h * 2 + 1]);
                if (bias && col >= bstart) {
                    v.x += __ldg(&bias[col - bstart]);
                    v.y += __ldg(&bias[col - bstart + 1]);
                }
                __half2 hv = __float22half2_rn(v);
                *reinterpret_cast<__half2*>(C + (size_t)gr * ldC + col) = hv;
            }
        }
    }
}

// =====================================================================
// GENERIC PATH (f32 operands, small GEMMs: folds + projections)
// =====================================================================
template <typename AT, typename CT>
__global__ void __launch_bounds__(256) gemm_h(
        const AT* __restrict__ A,
        const float* __restrict__ B0s, const float* __restrict__ B1s,
        const float* __restrict__ B2s,
        const float* __restrict__ bias, int bstart, CT* __restrict__ C,
        int Nrow, int K, int ldC) {
    __shared__ __align__(16) __half As[128 * STRH];
    __shared__ __align__(16) __half Bs[128 * STRH];
    const int tid  = threadIdx.x;
    const int lane = tid & 31;
    const int wid  = tid >> 5;
    const int wm   = wid & 3;
    const int wn   = wid >> 2;
    const int row0 = blockIdx.y * 128;
    const int col0 = blockIdx.x * 128;
    const int g4   = lane >> 2;
    const int t4   = lane & 3;
    const bool has3 = (B1s != nullptr);

    float acc[2][8][4];
#pragma unroll
    for (int mt = 0; mt < 2; mt++)
#pragma unroll
        for (int nt = 0; nt < 8; nt++)
#pragma unroll
            for (int q = 0; q < 4; q++) acc[mt][nt][q] = 0.f;

    const int nc = (K + 31) >> 5;
    for (int c = 0; c < nc; c++) {
        const int k0 = c << 5;
        if (c) __syncthreads();
#pragma unroll
        for (int it = 0; it < 2; it++) {
            const int idx = tid + it * 256;
            const int rr  = idx >> 2;
            const int cg  = (idx & 3) << 3;
            const bool kok = (k0 + cg) < K;
            uint4 qa = make_uint4(0, 0, 0, 0);
            const int gr = row0 + rr;
            if (gr < Nrow && kok) {
                if constexpr (sizeof(AT) == 2) {
                    qa = *reinterpret_cast<const uint4*>(
                        reinterpret_cast<const __half*>(A) + (size_t)gr * K + k0 + cg);
                } else {
                    const float* ap = reinterpret_cast<const float*>(A) +
                                      (size_t)gr * K + k0 + cg;
                    float4 v0 = *reinterpret_cast<const float4*>(ap);
                    float4 v1 = *reinterpret_cast<const float4*>(ap + 4);
                    qa = pack8(v0, v1);
                }
            }
            *reinterpret_cast<uint4*>(&As[rr * STRH + cg]) = qa;
            uint4 qb = make_uint4(0, 0, 0, 0);
            if (kok) {
                const size_t bo = (size_t)(col0 + rr) * K + k0 + cg;
                float4 w0 = *reinterpret_cast<const float4*>(B0s + bo);
                float4 w1 = *reinterpret_cast<const float4*>(B0s + bo + 4);
                if (has3) {
                    float4 a1 = *reinterpret_cast<const float4*>(B1s + bo);
                    float4 a2 = *reinterpret_cast<const float4*>(B1s + bo + 4);
                    float4 c1 = *reinterpret_cast<const float4*>(B2s + bo);
                    float4 c2 = *reinterpret_cast<const float4*>(B2s + bo + 4);
                    w0.x += a1.x + c1.x; w0.y += a1.y + c1.y;
                    w0.z += a1.z + c1.z; w0.w += a1.w + c1.w;
                    w1.x += a2.x + c2.x; w1.y += a2.y + c2.y;
                    w1.z += a2.z + c2.z; w1.w += a2.w + c2.w;
                }
                qb = pack8(w0, w1);
            }
            *reinterpret_cast<uint4*>(&Bs[rr * STRH + cg]) = qb;
        }
        __syncthreads();
#pragma unroll
        for (int ks = 0; ks < 2; ks++) {
            const int kb = ks << 4;
            uint32_t af[2][4];
#pragma unroll
            for (int mt = 0; mt < 2; mt++) {
                const int r = wm * 32 + mt * 16 + g4;
                const int base = r * STRH + kb + 2 * t4;
                af[mt][0] = *reinterpret_cast<const uint32_t*>(&As[base]);
                af[mt][1] = *reinterpret_cast<const uint32_t*>(&As[base + 8 * STRH]);
                af[mt][2] = *reinterpret_cast<const uint32_t*>(&As[base + 8]);
                af[mt][3] = *reinterpret_cast<const uint32_t*>(&As[base + 8 * STRH + 8]);
            }
#pragma unroll
            for (int nt = 0; nt < 8; nt++) {
                const int n = wn * 64 + nt * 8 + g4;
                const int bb = n * STRH + kb + 2 * t4;
                const uint32_t b0 = *reinterpret_cast<const uint32_t*>(&Bs[bb]);
                const uint32_t b1 = *reinterpret_cast<const uint32_t*>(&Bs[bb + 8]);
                mma_f16(acc[0][nt], af[0], b0, b1);
                mma_f16(acc[1][nt], af[1], b0, b1);
            }
        }
    }
#pragma unroll
    for (int mt = 0; mt < 2; mt++) {
#pragma unroll
        for (int h = 0; h < 2; h++) {
            const int gr = row0 + wm * 32 + mt * 16 + g4 + h * 8;
            if (gr >= Nrow) continue;
#pragma unroll
            for (int nt = 0; nt < 8; nt++) {
                const int col = col0 + wn * 64 + nt * 8 + t4 * 2;
                float2 v = make_float2(acc[mt][nt][h * 2 + 0], acc[mt][nt][h * 2 + 1]);
                if (bias && col >= bstart) {
                    v.x += __ldg(&bias[col - bstart]);
                    v.y += __ldg(&bias[col - bstart + 1]);
                }
                if constexpr (sizeof(CT) == 2) {
                    __half2 hv = __float22half2_rn(v);
                    *reinterpret_cast<__half2*>(
                        reinterpret_cast<__half*>(C) + (size_t)gr * ldC + col) = hv;
                } else {
                    *reinterpret_cast<float2*>(
                        reinterpret_cast<float*>(C) + (size_t)gr * ldC + col) = v;
                }
            }
        }
    }
}

// =====================================================================
// CSR build: count -> scan -> fill
// =====================================================================
__global__ void cnt_k(const int* __restrict__ dst, int* __restrict__ cnt, int E) {
    int i = blockIdx.x * blockDim.x + threadIdx.x;
    if (i < E) atomicAdd(&cnt[dst[i]], 1);
}
__global__ void scan1(const int* __restrict__ cnt, int* __restrict__ off,
                      int* __restrict__ bsum, int N) {
    __shared__ int sh[1024];
    int i = blockIdx.x * 1024 + threadIdx.x;
    int x = (i < N) ? cnt[i] : 0;
    sh[threadIdx.x] = x;
    __syncthreads();
    for (int d = 1; d < 1024; d <<= 1) {
        int t = (threadIdx.x >= d) ? sh[threadIdx.x - d] : 0;
        __syncthreads();
        sh[threadIdx.x] += t;
        __syncthreads();
    }
    int incl = sh[threadIdx.x];
    if (i < N) off[i] = incl - x;
    if (threadIdx.x == 1023) bsum[blockIdx.x] = incl;
}
__global__ void scan2(int* __restrict__ bsum, int B) {
    if (threadIdx.x == 0 && blockIdx.x == 0) {
        int run = 0;
        for (int i = 0; i < B; i++) { int t = bsum[i]; bsum[i] = run; run += t; }
    }
}
__global__ void scan3(int* __restrict__ off, const int* __restrict__ bsum, int N, int E) {
    int i = blockIdx.x * blockDim.x + threadIdx.x;
    if (i < N) off[i] += bsum[i >> 10];
    if (i == 0) off[N] = E;
}
__global__ void fill_k(const int* __restrict__ src, const int* __restrict__ dst,
                       int* __restrict__ cur, int* __restrict__ idx, int E) {
    int e = blockIdx.x * blockDim.x + threadIdx.x;
    if (e < E) {
        int p = atomicAdd(&cur[dst[e]], 1);
        idx[p] = src[e];
    }
}

// =====================================================================
// dst-centric gather (mean + self + relu), one warp per dst, fp16 rows
// =====================================================================
__device__ __forceinline__ void accum_rel(const __half* __restrict__ base, int stride,
                                          const int* __restrict__ off,
                                          const int* __restrict__ idx,
                                          int w, int lane, float* a) {
    int se = (lane < 2) ? __ldg(&off[w + lane]) : 0;
    int s = __shfl_sync(0xffffffffu, se, 0);
    int e = __shfl_sync(0xffffffffu, se, 1);
    if (e <= s) return;
    float sc = 1.f / (float)(e - s);
    float m[8] = {0.f, 0.f, 0.f, 0.f, 0.f, 0.f, 0.f, 0.f};
    for (int p = s; p < e; p++) {
        int sn = __ldg(&idx[p]);
        uint4 q = *reinterpret_cast<const uint4*>(base + (size_t)sn * stride + lane * 8);
        float f[8];
        h8_to_f8(q, f);
#pragma unroll
        for (int j = 0; j < 8; j++) m[j] += f[j];
    }
#pragma unroll
    for (int j = 0; j < 8; j++) a[j] += m[j] * sc;
}

__global__ void __launch_bounds__(256) gather_act(
        const __half* __restrict__ Pa, const __half* __restrict__ Pr,
        const __half* __restrict__ Pt,
        const int* __restrict__ offF,  const int* __restrict__ idxF,
        const int* __restrict__ offRA, const int* __restrict__ idxRA,
        const int* __restrict__ offTA, const int* __restrict__ idxTA,
        __half* __restrict__ Aout) {
    int w = (blockIdx.x * 256 + threadIdx.x) >> 5;
    int lane = threadIdx.x & 31;
    if (w >= NACT) return;
    float a[8];
    h8_to_f8(*reinterpret_cast<const uint4*>(Pa + (size_t)w * 1024 + 768 + lane * 8), a);
    accum_rel(Pa, 1024, offF,  idxF,  w, lane, a);
    accum_rel(Pr, 512,  offRA, idxRA, w, lane, a);
    accum_rel(Pt, 512,  offTA, idxTA, w, lane, a);
#pragma unroll
    for (int j = 0; j < 8; j++) a[j] = fmaxf(a[j], 0.f);
    *reinterpret_cast<uint4*>(Aout + (size_t)w * 256 + lane * 8) = f8_to_h8(a);
}

__global__ void __launch_bounds__(256) gather_one(
        const __half* __restrict__ msgB, int msgStride,
        const __half* __restrict__ selfB, int selfStride,
        const int* __restrict__ off, const int* __restrict__ idx,
        __half* __restrict__ Out, int N) {
    int w = (blockIdx.x * 256 + threadIdx.x) >> 5;
    int lane = threadIdx.x & 31;
    if (w >= N) return;
    float a[8];
    h8_to_f8(*reinterpret_cast<const uint4*>(selfB + (size_t)w * selfStride + lane * 8), a);
    accum_rel(msgB, msgStride, off, idx, w, lane, a);
#pragma unroll
    for (int j = 0; j < 8; j++) a[j] = fmaxf(a[j], 0.f);
    *reinterpret_cast<uint4*>(Out + (size_t)w * 256 + lane * 8) = f8_to_h8(a);
}

// =====================================================================
// misc kernels
// =====================================================================
__global__ void transpose_k(const float* __restrict__ in, float* __restrict__ out, int Kin) {
    int k = blockIdx.x, n = threadIdx.x;
    out[(size_t)n * Kin + k] = in[(size_t)k * 256 + n];
}

__global__ void fold_b(const float* __restrict__ b1, const float* __restrict__ b2,
                       const float* __restrict__ b3, const float* __restrict__ B,
                       const float* __restrict__ blin, float* __restrict__ out) {
    int j = threadIdx.x;
    float acc = blin[j];
    for (int k = 0; k < Hc; k++) {
        float bb = b1[k];
        if (b2) bb += b2[k];
        if (b3) bb += b3[k];
        acc = fmaf(bb, B[k * Hc + j], acc);
    }
    out[j] = acc;
}

__global__ void last_k(const int* __restrict__ batch, int* __restrict__ last, int N) {
    int i = blockIdx.x * blockDim.x + threadIdx.x;
    if (i < N) {
        if (i == N - 1 || batch[i + 1] != batch[i]) last[batch[i]] = i;
    }
}

__global__ void heads_k(const __half* __restrict__ a, const int* __restrict__ last,
                        const float* __restrict__ Wo, const float* __restrict__ bo,
                        const float* __restrict__ Wt, const float* __restrict__ bt,
                        const float* __restrict__ Wrm, const float* __restrict__ brm,
                        float* __restrict__ out) {
    int g = blockIdx.x;
    __shared__ float p[Hc];
    const __half* row = a + (size_t)last[g] * Hc;
    for (int k = threadIdx.x; k < Hc; k += blockDim.x) p[k] = __half2float(row[k]);
    __syncthreads();
    int j = threadIdx.x;
    if (j < CC) {
        float acc = bo[j];
        for (int k = 0; k < Hc; k++) acc = fmaf(p[k], Wo[k * CC + j], acc);
        out[g * CC + j] = acc;
    } else if (j == CC) {
        float acc = bt[0];
        for (int k = 0; k < Hc; k++) acc = fmaf(p[k], Wt[k], acc);
        out[GG * CC + g] = acc;
    } else if (j == CC + 1) {
        float acc = brm[0];
        for (int k = 0; k < Hc; k++) acc = fmaf(p[k], Wrm[k], acc);
        out[GG * CC + GG + g] = acc;
    }
}

// =====================================================================
// host orchestration
// =====================================================================
static inline void run_scan(int* cnt, int* off, int* bsum, int N, int E) {
    int nb = (N + 1023) / 1024;
    scan1<<<nb, 1024>>>(cnt, off, bsum, N);
    scan2<<<1, 32>>>(bsum, nb);
    scan3<<<(N + 256) / 256, 256>>>(off, bsum, N, E);
}

extern "C" void kernel_launch(void* const* d_in, const int* in_sizes, int n_in,
                              void* d_out, int out_size) {
    float* buf = nullptr;
    cudaGetSymbolAddress((void**)&buf, g_buf);

    __half* A  = reinterpret_cast<__half*>(buf + OFF_A);
    __half* R  = reinterpret_cast<__half*>(buf + OFF_R);
    __half* T  = reinterpret_cast<__half*>(buf + OFF_T);
    __half* Pa = reinterpret_cast<__half*>(buf + OFF_PA);
    __half* Pr = reinterpret_cast<__half*>(buf + OFF_PR);
    __half* Pt = reinterpret_cast<__half*>(buf + OFF_PT);
    __half* WCh = reinterpret_cast<__half*>(buf + OFF_WC);
    float* BF  = buf + OFF_BF;
    float* WLT = buf + OFF_WLT;
    float* WPT = buf + OFF_WPT;
    int*   LAST = reinterpret_cast<int*>(buf + OFF_LAST);
    int*   IB   = reinterpret_cast<int*>(buf + OFF_INT);
    int* offF  = IB + IO_OFF_F;
    int* offRA = IB + IO_OFF_RA;
    int* offTA = IB + IO_OFF_TA;
    int* offAR = IB + IO_OFF_AR;
    int* offAT = IB + IO_OFF_AT;
    int* cur   = IB + IO_CUR;
    int* idx   = IB + IO_IDX;
    int* bsum  = IB + IO_BSUM;

    const float* x_act  = (const float*)d_in[0];
    const float* x_res  = (const float*)d_in[1];
    const float* x_time = (const float*)d_in[2];
    const int* src_f  = (const int*)d_in[3];
    const int* dst_f  = (const int*)d_in[4];
    const int* src_ar = (const int*)d_in[5];
    const int* dst_ar = (const int*)d_in[6];
    const int* src_ra = (const int*)d_in[7];
    const int* dst_ra = (const int*)d_in[8];
    const int* src_at = (const int*)d_in[9];
    const int* dst_at = (const int*)d_in[10];
    const int* src_ta = (const int*)d_in[11];
    const int* dst_ta = (const int*)d_in[12];
    const int* batch  = (const int*)d_in[13];

    int w = (in_sizes[14] <= 4) ? 15 : 14;
    const float* Wp_act = (const float*)d_in[w + 0];
    const float* Wp_res = (const float*)d_in[w + 1];
    const float* Wp_tim = (const float*)d_in[w + 2];
    const float* Wl     = (const float*)d_in[w + 3];
    const float* bl     = (const float*)d_in[w + 4];
    const float* Wr     = (const float*)d_in[w + 5];
    const float* Wlin   = (const float*)d_in[w + 6];
    const float* blin   = (const float*)d_in[w + 7];
    const float* Wo     = (const float*)d_in[w + 8];
    const float* bo     = (const float*)d_in[w + 9];
    const float* Wt     = (const float*)d_in[w + 10];
    const float* bt     = (const float*)d_in[w + 11];
    const float* Wrm    = (const float*)d_in[w + 12];
    const float* brm    = (const float*)d_in[w + 13];

    const size_t HH = 65536;  // 256*256
    const dim3 g2(2, 2);

    // --- transpose weights into B-operand orientation ---
    transpose_k<<<64, 256>>>(Wp_act, WPT + 0,     64);
    transpose_k<<<32, 256>>>(Wp_res, WPT + 16384, 32);
    transpose_k<<<16, 256>>>(Wp_tim, WPT + 24576, 16);
    for (int i = 0; i < 6; i++)
        transpose_k<<<256, 256>>>(Wlin + (size_t)i * HH, WLT + (size_t)i * HH, 256);

    // --- fold weights into fp16 Wcat sections (B-operand layout [n,k]) ---
    for (int l = 0; l < 2; l++) {
        const float* lt0 = WLT + (size_t)(l * 3 + 0) * HH;
        const float* lt1 = WLT + (size_t)(l * 3 + 1) * HH;
        const float* lt2 = WLT + (size_t)(l * 3 + 2) * HH;
        __half* WCa = WCh + (size_t)l * 524288;   // [1024,256]
        __half* WCr = WCa + 262144;               // [512,256]
        __half* WCt = WCr + 131072;               // [512,256]
        gemm_h<float, __half><<<g2, 256>>>(lt0, Wl + (size_t)(l * 5 + 0) * HH, nullptr,
                                           nullptr, nullptr, 0, WCa + 0,      256, 256, 256);
        gemm_h<float, __half><<<g2, 256>>>(lt1, Wl + (size_t)(l * 5 + 1) * HH, nullptr,
                                           nullptr, nullptr, 0, WCa + 65536,  256, 256, 256);
        gemm_h<float, __half><<<g2, 256>>>(lt2, Wl + (size_t)(l * 5 + 3) * HH, nullptr,
                                           nullptr, nullptr, 0, WCa + 131072, 256, 256, 256);
        gemm_h<float, __half><<<g2, 256>>>(lt0, Wr + (size_t)(l * 5 + 0) * HH,
                                           Wr + (size_t)(l * 5 + 2) * HH,
                                           Wr + (size_t)(l * 5 + 4) * HH,
                                           nullptr, 0, WCa + 196608, 256, 256, 256);
        gemm_h<float, __half><<<g2, 256>>>(lt0, Wl + (size_t)(l * 5 + 2) * HH, nullptr,
                                           nullptr, nullptr, 0, WCr + 0,      256, 256, 256);
        gemm_h<float, __half><<<g2, 256>>>(lt1, Wr + (size_t)(l * 5 + 1) * HH, nullptr,
                                           nullptr, nullptr, 0, WCr + 65536,  256, 256, 256);
        gemm_h<float, __half><<<g2, 256>>>(lt0, Wl + (size_t)(l * 5 + 4) * HH, nullptr,
                                           nullptr, nullptr, 0, WCt + 0,      256, 256, 256);
        gemm_h<float, __half><<<g2, 256>>>(lt2, Wr + (size_t)(l * 5 + 3) * HH, nullptr,
                                           nullptr, nullptr, 0, WCt + 65536,  256, 256, 256);
        fold_b<<<1, 256>>>(bl + (l * 5 + 0) * 256, bl + (l * 5 + 2) * 256,
                           bl + (l * 5 + 4) * 256, Wlin + (size_t)(l * 3 + 0) * HH,
                           blin + (l * 3 + 0) * 256, BF + l * 768 + 0);
        fold_b<<<1, 256>>>(bl + (l * 5 + 1) * 256, nullptr, nullptr,
                           Wlin + (size_t)(l * 3 + 1) * HH,
                           blin + (l * 3 + 1) * 256, BF + l * 768 + 256);
        fold_b<<<1, 256>>>(bl + (l * 5 + 3) * 256, nullptr, nullptr,
                           Wlin + (size_t)(l * 3 + 2) * HH,
                           blin + (l * 3 + 2) * 256, BF + l * 768 + 512);
    }

    // --- CSR build (indices layer-invariant) ---
    cudaMemsetAsync(cur, 0, 720005 * sizeof(int), 0);
    int cblk = (EE + 255) / 256;
    cnt_k<<<cblk, 256>>>(dst_f,  cur + IO_OFF_F,  EE);
    cnt_k<<<cblk, 256>>>(dst_ra, cur + IO_OFF_RA, EE);
    cnt_k<<<cblk, 256>>>(dst_ta, cur + IO_OFF_TA, EE);
    cnt_k<<<cblk, 256>>>(dst_ar, cur + IO_OFF_AR, EE);
    cnt_k<<<cblk, 256>>>(dst_at, cur + IO_OFF_AT, EE);
    run_scan(cur + IO_OFF_F,  offF,  bsum, NACT,  EE);
    run_scan(cur + IO_OFF_RA, offRA, bsum, NACT,  EE);
    run_scan(cur + IO_OFF_TA, offTA, bsum, NACT,  EE);
    run_scan(cur + IO_OFF_AR, offAR, bsum, NRES,  EE);
    run_scan(cur + IO_OFF_AT, offAT, bsum, NTIME, EE);
    cudaMemcpyAsync(cur, IB, 720005 * sizeof(int), cudaMemcpyDeviceToDevice, 0);
    fill_k<<<cblk, 256>>>(src_f,  dst_f,  cur + IO_OFF_F,  idx + 0,       EE);
    fill_k<<<cblk, 256>>>(src_ra, dst_ra, cur + IO_OFF_RA, idx + 400000,  EE);
    fill_k<<<cblk, 256>>>(src_ta, dst_ta, cur + IO_OFF_TA, idx + 800000,  EE);
    fill_k<<<cblk, 256>>>(src_ar, dst_ar, cur + IO_OFF_AR, idx + 1200000, EE);
    fill_k<<<cblk, 256>>>(src_at, dst_at, cur + IO_OFF_AT, idx + 1600000, EE);

    // --- input projections (f32 in, fp16 out; generic path) ---
    gemm_h<float, __half><<<dim3(2, (NACT  + 127) / 128), 256>>>(
        x_act,  WPT + 0,     nullptr, nullptr, nullptr, 0, A, NACT,  64, 256);
    gemm_h<float, __half><<<dim3(2, (NRES  + 127) / 128), 256>>>(
        x_res,  WPT + 16384, nullptr, nullptr, nullptr, 0, R, NRES,  32, 256);
    gemm_h<float, __half><<<dim3(2, (NTIME + 127) / 128), 256>>>(
        x_time, WPT + 24576, nullptr, nullptr, nullptr, 0, T, NTIME, 16, 256);

    // --- layers: pipelined fp16 GEMM then dst-centric mean-gather ---
    for (int l = 0; l < 2; l++) {
        __half* WCa = WCh + (size_t)l * 524288;
        __half* WCr = WCa + 262144;
        __half* WCt = WCr + 131072;
        gemm_fast<<<dim3(8, (NACT + 127) / 128), 256>>>(
            A, WCa, BF + l * 768 + 0,   768, Pa, NACT,  256, 1024);
        gemm_fast<<<dim3(4, (NRES + 127) / 128), 256>>>(
            R, WCr, BF + l * 768 + 256, 256, Pr, NRES,  256, 512);
        gemm_fast<<<dim3(4, (NTIME + 127) / 128), 256>>>(
            T, WCt, BF + l * 768 + 512, 256, Pt, NTIME, 256, 512);

        gather_act<<<NACT / 8, 256>>>(Pa, Pr, Pt,
                                      offF,  idx + 0,
                                      offRA, idx + 400000,
                                      offTA, idx + 800000, A);
        gather_one<<<NRES / 8, 256>>>(Pa + 256, 1024, Pr + 256, 512,
                                      offAR, idx + 1200000, R, NRES);
        gather_one<<<NTIME / 8, 256>>>(Pa + 512, 1024, Pt + 256, 512,
                                       offAT, idx + 1600000, T, NTIME);
    }

    // --- last-node pooling + heads ---
    cudaMemsetAsync(LAST, 0, GG * sizeof(int), 0);
    last_k<<<(NACT + 255) / 256, 256>>>(batch, LAST, NACT);
    heads_k<<<GG, 64>>>(A, LAST, Wo, bo, Wt, bt, Wrm, brm, (float*)d_out);
}

// round 12
// speedup vs baseline: 5.5177x; 1.2255x over previous
#include <cuda_runtime.h>
#include <cuda_fp16.h>
#include <cstdint>
#include <cstddef>

#define Hc    256
#define CC    50
#define GG    512
#define NACT  200000
#define NRES  20000
#define NTIME 100000
#define EE    400000

// ---------------- scratch layout (float units) ----------------
static constexpr size_t OFF_A    = 0;            // 200000*256 h
static constexpr size_t OFF_R    = 25600000;     // 20000*256 h
static constexpr size_t OFF_T    = 28160000;     // 100000*256 h
static constexpr size_t OFF_PA   = 40960000;     // 200000*1024 h [f|ar|at|self]
static constexpr size_t OFF_PR   = 143360000;    // 20000*512 h   [ra|self]
static constexpr size_t OFF_PT   = 148480000;    // 100000*512 h  [ta|self]
static constexpr size_t OFF_WC   = 174080000;    // 2*524288 halves folded weights (fp16)
static constexpr size_t OFF_BF   = 175128576;    // 2*3*256 f32
static constexpr size_t OFF_WLT  = 175130112;    // 6*65536 f32 Wlin^T
static constexpr size_t OFF_WPT  = 175523328;    // 256*(64+32+16) f32 Wp^T
static constexpr size_t OFF_LAST = 175552000;    // 512 ints
static constexpr size_t OFF_INT  = 175552512;    // int scratch
static constexpr size_t TOTALF   = 178993600;

// unified CSR (ints, relative to OFF_INT)
// off layout: [f:200000][ra:200000][ta:200000][ar:20000][at:100000][sentinel]
static constexpr int CSR_N     = 720000;
static constexpr int B_F  = 0;
static constexpr int B_RA = 200000;
static constexpr int B_TA = 400000;
static constexpr int B_AR = 600000;
static constexpr int B_AT = 620000;
static constexpr size_t IO_OFFS = 0;         // 720001
static constexpr size_t IO_CNT  = 720004;    // 720000 (counts, then cursors)
static constexpr size_t IO_BSUM = 1440004;   // 1024
static constexpr size_t IO_IDX  = 1441028;   // 2,000,000

__device__ float g_buf[TOTALF];

// =====================================================================
// helpers
// =====================================================================
__device__ __forceinline__ void mma_f16(float* d, const uint32_t* a,
                                        uint32_t b0, uint32_t b1) {
    asm volatile(
        "mma.sync.aligned.m16n8k16.row.col.f32.f16.f16.f32 "
        "{%0,%1,%2,%3}, {%4,%5,%6,%7}, {%8,%9}, {%0,%1,%2,%3};"
        : "+f"(d[0]), "+f"(d[1]), "+f"(d[2]), "+f"(d[3])
        : "r"(a[0]), "r"(a[1]), "r"(a[2]), "r"(a[3]), "r"(b0), "r"(b1));
}
__device__ __forceinline__ void ldsm4(uint32_t* r, uint32_t addr) {
    asm volatile("ldmatrix.sync.aligned.m8n8.x4.shared.b16 {%0,%1,%2,%3}, [%4];"
                 : "=r"(r[0]), "=r"(r[1]), "=r"(r[2]), "=r"(r[3]) : "r"(addr));
}
__device__ __forceinline__ void cp16(uint32_t dst, const void* src, int szbytes) {
    asm volatile("cp.async.cg.shared.global [%0], [%1], 16, %2;"
                 :: "r"(dst), "l"(src), "r"(szbytes));
}
#define CP_COMMIT() asm volatile("cp.async.commit_group;" ::: "memory")
template <int N>
__device__ __forceinline__ void cp_wait() {
    asm volatile("cp.async.wait_group %0;" :: "n"(N) : "memory");
}
__device__ __forceinline__ uint32_t saddr(const void* p) {
    return static_cast<uint32_t>(__cvta_generic_to_shared(p));
}
__device__ __forceinline__ uint32_t packh2(float x, float y) {
    __half2 h = __float22half2_rn(make_float2(x, y));
    return *reinterpret_cast<uint32_t*>(&h);
}
__device__ __forceinline__ uint4 pack8(float4 a, float4 b) {
    return make_uint4(packh2(a.x, a.y), packh2(a.z, a.w),
                      packh2(b.x, b.y), packh2(b.z, b.w));
}
__device__ __forceinline__ void h8_to_f8(uint4 q, float* f) {
    const __half2* h = reinterpret_cast<const __half2*>(&q);
#pragma unroll
    for (int i = 0; i < 4; i++) {
        float2 t = __half22float2(h[i]);
        f[2 * i] = t.x; f[2 * i + 1] = t.y;
    }
}
__device__ __forceinline__ uint4 f8_to_h8(const float* f) {
    return make_uint4(packh2(f[0], f[1]), packh2(f[2], f[3]),
                      packh2(f[4], f[5]), packh2(f[6], f[7]));
}

#define STRH 40   // SMEM row stride in halves (80B: 16B-aligned, ldsm conflict-free)

// =====================================================================
// FUSED fast fp16 GEMM: 3 sub-GEMMs (act/res/time) in one launch.
// K = 256 fixed. tile 128x128, warp tile 32x64, cp.async double buffer.
// =====================================================================
struct GemmDesc {
    const __half* A; const __half* B; const float* bias;
    __half* C; int bstart; int Nrow; int ldC; int colT;
};
struct Gemm3 { GemmDesc d[3]; int n0, n01; };

__global__ void __launch_bounds__(256) gemm_fast3(Gemm3 g) {
    __shared__ __align__(16) __half As[2][128 * STRH];
    __shared__ __align__(16) __half Bs[2][128 * STRH];
    const int id = blockIdx.x;
    const int zi = (id < g.n0) ? 0 : ((id < g.n01) ? 1 : 2);
    const int rid = id - ((zi == 0) ? 0 : ((zi == 1) ? g.n0 : g.n01));
    const GemmDesc d = g.d[zi];
    const int row0 = (rid / d.colT) * 128;
    const int col0 = (rid % d.colT) * 128;
    const int Nrow = d.Nrow;
    const __half* __restrict__ A = d.A;
    const __half* __restrict__ B = d.B;
    constexpr int K = 256;

    const int tid  = threadIdx.x;
    const int lane = tid & 31;
    const int wid  = tid >> 5;
    const int wm   = wid & 3;
    const int wn   = wid >> 2;
    const int t4   = lane & 3;
    const int g4   = lane >> 2;
    const int arow = lane & 15;
    const int acol = (lane >> 4) << 3;
    const int brow = (lane & 7) + ((lane >> 4) << 3);
    const int bcol = ((lane >> 3) & 1) << 3;

    float acc[2][8][4];
#pragma unroll
    for (int mt = 0; mt < 2; mt++)
#pragma unroll
        for (int nt = 0; nt < 8; nt++)
#pragma unroll
            for (int q = 0; q < 4; q++) acc[mt][nt][q] = 0.f;

    auto stage = [&](int c, int b) {
        const int k0 = c << 5;
#pragma unroll
        for (int it = 0; it < 2; it++) {
            const int i  = tid + it * 256;
            const int rr = i >> 2;
            const int sg = (i & 3) << 3;
            const int gr = row0 + rr;
            const int grc = gr < Nrow ? gr : (Nrow - 1);
            cp16(saddr(&As[b][rr * STRH + sg]),
                 A + (size_t)grc * K + k0 + sg, gr < Nrow ? 16 : 0);
            cp16(saddr(&Bs[b][rr * STRH + sg]),
                 B + (size_t)(col0 + rr) * K + k0 + sg, 16);
        }
    };

    stage(0, 0);
    CP_COMMIT();
    constexpr int nc = K >> 5;
#pragma unroll 1
    for (int c = 0; c < nc; c++) {
        const int cb = c & 1;
        if (c + 1 < nc) { stage(c + 1, cb ^ 1); CP_COMMIT(); cp_wait<1>(); }
        else            { cp_wait<0>(); }
        __syncthreads();
#pragma unroll
        for (int ks = 0; ks < 2; ks++) {
            const int kb = ks << 4;
            uint32_t af[2][4];
#pragma unroll
            for (int mt = 0; mt < 2; mt++)
                ldsm4(af[mt], saddr(&As[cb][(wm * 32 + mt * 16 + arow) * STRH + kb + acol]));
            uint32_t bf[4][4];
#pragma unroll
            for (int p = 0; p < 4; p++)
                ldsm4(bf[p], saddr(&Bs[cb][(wn * 64 + p * 16 + brow) * STRH + kb + bcol]));
#pragma unroll
            for (int nt = 0; nt < 8; nt++) {
                const uint32_t b0 = bf[nt >> 1][(nt & 1) * 2];
                const uint32_t b1 = bf[nt >> 1][(nt & 1) * 2 + 1];
                mma_f16(acc[0][nt], af[0], b0, b1);
                mma_f16(acc[1][nt], af[1], b0, b1);
            }
        }
        __syncthreads();
    }
#pragma unroll
    for (int mt = 0; mt < 2; mt++) {
#pragma unroll
        for (int h = 0; h < 2; h++) {
            const int gr = row0 + wm * 32 + mt * 16 + g4 + h * 8;
            if (gr >= Nrow) continue;
#pragma unroll
            for (int nt = 0; nt < 8; nt++) {
                const int col = col0 + wn * 64 + nt * 8 + t4 * 2;
                float2 v = make_float2(acc[mt][nt][h * 2 + 0], acc[mt][nt][h * 2 + 1]);
                if (col >= d.bstart) {
                    v.x += __ldg(&d.bias[col - d.bstart]);
                    v.y += __ldg(&d.bias[col - d.bstart + 1]);
                }
                __half2 hv = __float22half2_rn(v);
                *reinterpret_cast<__half2*>(d.C + (size_t)gr * d.ldC + col) = hv;
            }
        }
    }
}

// =====================================================================
// GENERIC GEMM core (f32 A staged to fp16) — used by projections & folds
// =====================================================================
__device__ __forceinline__ void gemm_core_f32(
        const float* __restrict__ A,
        const float* __restrict__ B0s, const float* __restrict__ B1s,
        const float* __restrict__ B2s,
        const float* __restrict__ bias, int bstart, __half* __restrict__ C,
        int Nrow, int K, int ldC, int row0, int col0,
        __half* As, __half* Bs) {
    const int tid  = threadIdx.x;
    const int lane = tid & 31;
    const int wid  = tid >> 5;
    const int wm   = wid & 3;
    const int wn   = wid >> 2;
    const int g4   = lane >> 2;
    const int t4   = lane & 3;
    const bool has3 = (B1s != nullptr);

    float acc[2][8][4];
#pragma unroll
    for (int mt = 0; mt < 2; mt++)
#pragma unroll
        for (int nt = 0; nt < 8; nt++)
#pragma unroll
            for (int q = 0; q < 4; q++) acc[mt][nt][q] = 0.f;

    const int nc = (K + 31) >> 5;
    for (int c = 0; c < nc; c++) {
        const int k0 = c << 5;
        if (c) __syncthreads();
#pragma unroll
        for (int it = 0; it < 2; it++) {
            const int idx = tid + it * 256;
            const int rr  = idx >> 2;
            const int cg  = (idx & 3) << 3;
            const bool kok = (k0 + cg) < K;
            uint4 qa = make_uint4(0, 0, 0, 0);
            const int gr = row0 + rr;
            if (gr < Nrow && kok) {
                const float* ap = A + (size_t)gr * K + k0 + cg;
                float4 v0 = *reinterpret_cast<const float4*>(ap);
                float4 v1 = *reinterpret_cast<const float4*>(ap + 4);
                qa = pack8(v0, v1);
            }
            *reinterpret_cast<uint4*>(&As[rr * STRH + cg]) = qa;
            uint4 qb = make_uint4(0, 0, 0, 0);
            if (kok) {
                const size_t bo = (size_t)(col0 + rr) * K + k0 + cg;
                float4 w0 = *reinterpret_cast<const float4*>(B0s + bo);
                float4 w1 = *reinterpret_cast<const float4*>(B0s + bo + 4);
                if (has3) {
                    float4 a1 = *reinterpret_cast<const float4*>(B1s + bo);
                    float4 a2 = *reinterpret_cast<const float4*>(B1s + bo + 4);
                    float4 c1 = *reinterpret_cast<const float4*>(B2s + bo);
                    float4 c2 = *reinterpret_cast<const float4*>(B2s + bo + 4);
                    w0.x += a1.x + c1.x; w0.y += a1.y + c1.y;
                    w0.z += a1.z + c1.z; w0.w += a1.w + c1.w;
                    w1.x += a2.x + c2.x; w1.y += a2.y + c2.y;
                    w1.z += a2.z + c2.z; w1.w += a2.w + c2.w;
                }
                qb = pack8(w0, w1);
            }
            *reinterpret_cast<uint4*>(&Bs[rr * STRH + cg]) = qb;
        }
        __syncthreads();
#pragma unroll
        for (int ks = 0; ks < 2; ks++) {
            const int kb = ks << 4;
            uint32_t af[2][4];
#pragma unroll
            for (int mt = 0; mt < 2; mt++) {
                const int r = wm * 32 + mt * 16 + g4;
                const int base = r * STRH + kb + 2 * t4;
                af[mt][0] = *reinterpret_cast<const uint32_t*>(&As[base]);
                af[mt][1] = *reinterpret_cast<const uint32_t*>(&As[base + 8 * STRH]);
                af[mt][2] = *reinterpret_cast<const uint32_t*>(&As[base + 8]);
                af[mt][3] = *reinterpret_cast<const uint32_t*>(&As[base + 8 * STRH + 8]);
            }
#pragma unroll
            for (int nt = 0; nt < 8; nt++) {
                const int n = wn * 64 + nt * 8 + g4;
                const int bb = n * STRH + kb + 2 * t4;
                const uint32_t b0 = *reinterpret_cast<const uint32_t*>(&Bs[bb]);
                const uint32_t b1 = *reinterpret_cast<const uint32_t*>(&Bs[bb + 8]);
                mma_f16(acc[0][nt], af[0], b0, b1);
                mma_f16(acc[1][nt], af[1], b0, b1);
            }
        }
    }
#pragma unroll
    for (int mt = 0; mt < 2; mt++) {
#pragma unroll
        for (int h = 0; h < 2; h++) {
            const int gr = row0 + wm * 32 + mt * 16 + g4 + h * 8;
            if (gr >= Nrow) continue;
#pragma unroll
            for (int nt = 0; nt < 8; nt++) {
                const int col = col0 + wn * 64 + nt * 8 + t4 * 2;
                float2 v = make_float2(acc[mt][nt][h * 2 + 0], acc[mt][nt][h * 2 + 1]);
                if (bias && col >= bstart) {
                    v.x += __ldg(&bias[col - bstart]);
                    v.y += __ldg(&bias[col - bstart + 1]);
                }
                __half2 hv = __float22half2_rn(v);
                *reinterpret_cast<__half2*>(C + (size_t)gr * ldC + col) = hv;
            }
        }
    }
}

// projections: f32 A, one B
__global__ void __launch_bounds__(256) gemm_proj(
        const float* __restrict__ A, const float* __restrict__ B,
        __half* __restrict__ C, int Nrow, int K, int ldC) {
    __shared__ __align__(16) __half As[128 * STRH];
    __shared__ __align__(16) __half Bs[128 * STRH];
    gemm_core_f32(A, B, nullptr, nullptr, nullptr, 0, C,
                  Nrow, K, ldC, blockIdx.y * 128, blockIdx.x * 128, As, Bs);
}

// batched 256x256x256 weight folds: ONE launch, grid (2,2,16)
struct FoldDesc { const float* A; const float* B0; const float* B1;
                  const float* B2; __half* C; };
struct Fold16 { FoldDesc d[16]; };
__global__ void __launch_bounds__(256) gemm_fold(Fold16 args) {
    __shared__ __align__(16) __half As[128 * STRH];
    __shared__ __align__(16) __half Bs[128 * STRH];
    const FoldDesc f = args.d[blockIdx.z];
    gemm_core_f32(f.A, f.B0, f.B1, f.B2, nullptr, 0, f.C,
                  256, 256, 256, blockIdx.y * 128, blockIdx.x * 128, As, Bs);
}

// batched transposes: out[256,Kin] = in[Kin,256]^T  (9 in one launch)
struct TPArgs { const float* in[9]; float* out[9]; int kin[9]; };
__global__ void transpose9(TPArgs a) {
    int z = blockIdx.z, k = blockIdx.x, n = threadIdx.x;
    if (k < a.kin[z])
        a.out[z][(size_t)n * a.kin[z] + k] = a.in[z][(size_t)k * 256 + n];
}

// batched bias folds (6 in one launch)
struct FoldB { const float* b1; const float* b2; const float* b3;
               const float* B; const float* blin; float* out; };
struct FoldB6 { FoldB d[6]; };
__global__ void fold_b6(FoldB6 a) {
    const FoldB f = a.d[blockIdx.x];
    int j = threadIdx.x;
    float acc = f.blin[j];
    for (int k = 0; k < Hc; k++) {
        float bb = f.b1[k];
        if (f.b2) bb += f.b2[k];
        if (f.b3) bb += f.b3[k];
        acc = fmaf(bb, f.B[k * Hc + j], acc);
    }
    f.out[j] = acc;
}

// =====================================================================
// unified CSR build: fused count -> one scan -> fused fill
// =====================================================================
__global__ void cnt5(const int* __restrict__ d0, const int* __restrict__ d1,
                     const int* __restrict__ d2, const int* __restrict__ d3,
                     const int* __restrict__ d4, int* __restrict__ cnt) {
    int i = blockIdx.x * blockDim.x + threadIdx.x;
    if (i >= 5 * EE) return;
    int r = i / EE, e = i - r * EE;
    const int* dp; int base;
    switch (r) {
        case 0: dp = d0; base = B_F;  break;
        case 1: dp = d1; base = B_RA; break;
        case 2: dp = d2; base = B_TA; break;
        case 3: dp = d3; base = B_AR; break;
        default: dp = d4; base = B_AT; break;
    }
    atomicAdd(&cnt[base + dp[e]], 1);
}
__global__ void scan1(const int* __restrict__ cnt, int* __restrict__ off,
                      int* __restrict__ bsum, int N) {
    __shared__ int sh[1024];
    int i = blockIdx.x * 1024 + threadIdx.x;
    int x = (i < N) ? cnt[i] : 0;
    sh[threadIdx.x] = x;
    __syncthreads();
    for (int d = 1; d < 1024; d <<= 1) {
        int t = (threadIdx.x >= d) ? sh[threadIdx.x - d] : 0;
        __syncthreads();
        sh[threadIdx.x] += t;
        __syncthreads();
    }
    int incl = sh[threadIdx.x];
    if (i < N) off[i] = incl - x;
    if (threadIdx.x == 1023) bsum[blockIdx.x] = incl;
}
__global__ void scan2(int* __restrict__ bsum, int B) {
    __shared__ int sh[1024];
    int t = threadIdx.x;
    int x = (t < B) ? bsum[t] : 0;
    sh[t] = x;
    __syncthreads();
    for (int d = 1; d < 1024; d <<= 1) {
        int v = (t >= d) ? sh[t - d] : 0;
        __syncthreads();
        sh[t] += v;
        __syncthreads();
    }
    if (t < B) bsum[t] = sh[t] - x;
}
__global__ void scan3(int* __restrict__ off, const int* __restrict__ bsum,
                      int N, int total) {
    int i = blockIdx.x * blockDim.x + threadIdx.x;
    if (i < N) off[i] += bsum[i >> 10];
    if (i == 0) off[N] = total;
}
__global__ void fill5(const int* __restrict__ s0, const int* __restrict__ d0,
                      const int* __restrict__ s1, const int* __restrict__ d1,
                      const int* __restrict__ s2, const int* __restrict__ d2,
                      const int* __restrict__ s3, const int* __restrict__ d3,
                      const int* __restrict__ s4, const int* __restrict__ d4,
                      int* __restrict__ cur, int* __restrict__ idx) {
    int i = blockIdx.x * blockDim.x + threadIdx.x;
    if (i >= 5 * EE) return;
    int r = i / EE, e = i - r * EE;
    const int *sp, *dp; int base;
    switch (r) {
        case 0: sp = s0; dp = d0; base = B_F;  break;
        case 1: sp = s1; dp = d1; base = B_RA; break;
        case 2: sp = s2; dp = d2; base = B_TA; break;
        case 3: sp = s3; dp = d3; base = B_AR; break;
        default: sp = s4; dp = d4; base = B_AT; break;
    }
    int p = atomicAdd(&cur[base + dp[e]], 1);
    idx[p] = sp[e];
}

// =====================================================================
// fused dst-centric gather (mean + self + relu) for all 3 node types
// =====================================================================
__device__ __forceinline__ void accum_rel(const __half* __restrict__ base, int stride,
                                          const int* __restrict__ off,
                                          const int* __restrict__ idx,
                                          int w, int lane, float* a) {
    int se = (lane < 2) ? __ldg(&off[w + lane]) : 0;
    int s = __shfl_sync(0xffffffffu, se, 0);
    int e = __shfl_sync(0xffffffffu, se, 1);
    if (e <= s) return;
    float sc = 1.f / (float)(e - s);
    float m[8] = {0.f, 0.f, 0.f, 0.f, 0.f, 0.f, 0.f, 0.f};
    for (int p = s; p < e; p++) {
        int sn = __ldg(&idx[p]);
        uint4 q = *reinterpret_cast<const uint4*>(base + (size_t)sn * stride + lane * 8);
        float f[8];
        h8_to_f8(q, f);
#pragma unroll
        for (int j = 0; j < 8; j++) m[j] += f[j];
    }
#pragma unroll
    for (int j = 0; j < 8; j++) a[j] += m[j] * sc;
}

__global__ void __launch_bounds__(256) gather_all(
        const __half* __restrict__ Pa, const __half* __restrict__ Pr,
        const __half* __restrict__ Pt,
        const int* __restrict__ off, const int* __restrict__ idx,
        __half* __restrict__ A, __half* __restrict__ R, __half* __restrict__ T) {
    int w = (blockIdx.x * 256 + threadIdx.x) >> 5;
    int lane = threadIdx.x & 31;
    float a[8];
    if (w < NACT) {
        h8_to_f8(*reinterpret_cast<const uint4*>(Pa + (size_t)w * 1024 + 768 + lane * 8), a);
        accum_rel(Pa, 1024, off + B_F,  idx, w, lane, a);
        accum_rel(Pr, 512,  off + B_RA, idx, w, lane, a);
        accum_rel(Pt, 512,  off + B_TA, idx, w, lane, a);
#pragma unroll
        for (int j = 0; j < 8; j++) a[j] = fmaxf(a[j], 0.f);
        *reinterpret_cast<uint4*>(A + (size_t)w * 256 + lane * 8) = f8_to_h8(a);
    } else if (w < NACT + NRES) {
        int v = w - NACT;
        h8_to_f8(*reinterpret_cast<const uint4*>(Pr + (size_t)v * 512 + 256 + lane * 8), a);
        accum_rel(Pa + 256, 1024, off + B_AR, idx, v, lane, a);
#pragma unroll
        for (int j = 0; j < 8; j++) a[j] = fmaxf(a[j], 0.f);
        *reinterpret_cast<uint4*>(R + (size_t)v * 256 + lane * 8) = f8_to_h8(a);
    } else if (w < NACT + NRES + NTIME) {
        int v = w - NACT - NRES;
        h8_to_f8(*reinterpret_cast<const uint4*>(Pt + (size_t)v * 512 + 256 + lane * 8), a);
        accum_rel(Pa + 512, 1024, off + B_AT, idx, v, lane, a);
#pragma unroll
        for (int j = 0; j < 8; j++) a[j] = fmaxf(a[j], 0.f);
        *reinterpret_cast<uint4*>(T + (size_t)v * 256 + lane * 8) = f8_to_h8(a);
    }
}

// =====================================================================
// misc kernels
// =====================================================================
__global__ void last_k(const int* __restrict__ batch, int* __restrict__ last, int N) {
    int i = blockIdx.x * blockDim.x + threadIdx.x;
    if (i < N) {
        if (i == N - 1 || batch[i + 1] != batch[i]) last[batch[i]] = i;
    }
}

__global__ void heads_k(const __half* __restrict__ a, const int* __restrict__ last,
                        const float* __restrict__ Wo, const float* __restrict__ bo,
                        const float* __restrict__ Wt, const float* __restrict__ bt,
                        const float* __restrict__ Wrm, const float* __restrict__ brm,
                        float* __restrict__ out) {
    int g = blockIdx.x;
    __shared__ float p[Hc];
    const __half* row = a + (size_t)last[g] * Hc;
    for (int k = threadIdx.x; k < Hc; k += blockDim.x) p[k] = __half2float(row[k]);
    __syncthreads();
    int j = threadIdx.x;
    if (j < CC) {
        float acc = bo[j];
        for (int k = 0; k < Hc; k++) acc = fmaf(p[k], Wo[k * CC + j], acc);
        out[g * CC + j] = acc;
    } else if (j == CC) {
        float acc = bt[0];
        for (int k = 0; k < Hc; k++) acc = fmaf(p[k], Wt[k], acc);
        out[GG * CC + g] = acc;
    } else if (j == CC + 1) {
        float acc = brm[0];
        for (int k = 0; k < Hc; k++) acc = fmaf(p[k], Wrm[k], acc);
        out[GG * CC + GG + g] = acc;
    }
}

// =====================================================================
// host orchestration
// =====================================================================
extern "C" void kernel_launch(void* const* d_in, const int* in_sizes, int n_in,
                              void* d_out, int out_size) {
    float* buf = nullptr;
    cudaGetSymbolAddress((void**)&buf, g_buf);

    __half* A  = reinterpret_cast<__half*>(buf + OFF_A);
    __half* R  = reinterpret_cast<__half*>(buf + OFF_R);
    __half* T  = reinterpret_cast<__half*>(buf + OFF_T);
    __half* Pa = reinterpret_cast<__half*>(buf + OFF_PA);
    __half* Pr = reinterpret_cast<__half*>(buf + OFF_PR);
    __half* Pt = reinterpret_cast<__half*>(buf + OFF_PT);
    __half* WCh = reinterpret_cast<__half*>(buf + OFF_WC);
    float* BF  = buf + OFF_BF;
    float* WLT = buf + OFF_WLT;
    float* WPT = buf + OFF_WPT;
    int*   LAST = reinterpret_cast<int*>(buf + OFF_LAST);
    int*   IB   = reinterpret_cast<int*>(buf + OFF_INT);
    int* off  = IB + IO_OFFS;
    int* cnt  = IB + IO_CNT;
    int* bsum = IB + IO_BSUM;
    int* idx  = IB + IO_IDX;

    const float* x_act  = (const float*)d_in[0];
    const float* x_res  = (const float*)d_in[1];
    const float* x_time = (const float*)d_in[2];
    const int* src_f  = (const int*)d_in[3];
    const int* dst_f  = (const int*)d_in[4];
    const int* src_ar = (const int*)d_in[5];
    const int* dst_ar = (const int*)d_in[6];
    const int* src_ra = (const int*)d_in[7];
    const int* dst_ra = (const int*)d_in[8];
    const int* src_at = (const int*)d_in[9];
    const int* dst_at = (const int*)d_in[10];
    const int* src_ta = (const int*)d_in[11];
    const int* dst_ta = (const int*)d_in[12];
    const int* batch  = (const int*)d_in[13];

    int w = (in_sizes[14] <= 4) ? 15 : 14;
    const float* Wp_act = (const float*)d_in[w + 0];
    const float* Wp_res = (const float*)d_in[w + 1];
    const float* Wp_tim = (const float*)d_in[w + 2];
    const float* Wl     = (const float*)d_in[w + 3];
    const float* bl     = (const float*)d_in[w + 4];
    const float* Wr     = (const float*)d_in[w + 5];
    const float* Wlin   = (const float*)d_in[w + 6];
    const float* blin   = (const float*)d_in[w + 7];
    const float* Wo     = (const float*)d_in[w + 8];
    const float* bo     = (const float*)d_in[w + 9];
    const float* Wt     = (const float*)d_in[w + 10];
    const float* bt     = (const float*)d_in[w + 11];
    const float* Wrm    = (const float*)d_in[w + 12];
    const float* brm    = (const float*)d_in[w + 13];

    const size_t HH = 65536;  // 256*256

    // --- fused transposes (9 -> 1 launch) ---
    {
        TPArgs tp;
        tp.in[0] = Wp_act; tp.out[0] = WPT + 0;     tp.kin[0] = 64;
        tp.in[1] = Wp_res; tp.out[1] = WPT + 16384; tp.kin[1] = 32;
        tp.in[2] = Wp_tim; tp.out[2] = WPT + 24576; tp.kin[2] = 16;
        for (int i = 0; i < 6; i++) {
            tp.in[3 + i]  = Wlin + (size_t)i * HH;
            tp.out[3 + i] = WLT + (size_t)i * HH;
            tp.kin[3 + i] = 256;
        }
        transpose9<<<dim3(256, 1, 9), 256>>>(tp);
    }

    // --- fused weight folds (16 -> 1 launch) + bias folds (6 -> 1) ---
    {
        Fold16 fa;
        for (int l = 0; l < 2; l++) {
            const float* lt0 = WLT + (size_t)(l * 3 + 0) * HH;
            const float* lt1 = WLT + (size_t)(l * 3 + 1) * HH;
            const float* lt2 = WLT + (size_t)(l * 3 + 2) * HH;
            __half* WCa = WCh + (size_t)l * 524288;
            __half* WCr = WCa + 262144;
            __half* WCt = WCr + 131072;
            FoldDesc* d = fa.d + l * 8;
            d[0] = {lt0, Wl + (size_t)(l * 5 + 0) * HH, nullptr, nullptr, WCa + 0};
            d[1] = {lt1, Wl + (size_t)(l * 5 + 1) * HH, nullptr, nullptr, WCa + 65536};
            d[2] = {lt2, Wl + (size_t)(l * 5 + 3) * HH, nullptr, nullptr, WCa + 131072};
            d[3] = {lt0, Wr + (size_t)(l * 5 + 0) * HH,
                         Wr + (size_t)(l * 5 + 2) * HH,
                         Wr + (size_t)(l * 5 + 4) * HH, WCa + 196608};
            d[4] = {lt0, Wl + (size_t)(l * 5 + 2) * HH, nullptr, nullptr, WCr + 0};
            d[5] = {lt1, Wr + (size_t)(l * 5 + 1) * HH, nullptr, nullptr, WCr + 65536};
            d[6] = {lt0, Wl + (size_t)(l * 5 + 4) * HH, nullptr, nullptr, WCt + 0};
            d[7] = {lt2, Wr + (size_t)(l * 5 + 3) * HH, nullptr, nullptr, WCt + 65536};
        }
        gemm_fold<<<dim3(2, 2, 16), 256>>>(fa);

        FoldB6 fb;
        for (int l = 0; l < 2; l++) {
            fb.d[l * 3 + 0] = {bl + (l * 5 + 0) * 256, bl + (l * 5 + 2) * 256,
                               bl + (l * 5 + 4) * 256, Wlin + (size_t)(l * 3 + 0) * HH,
                               blin + (l * 3 + 0) * 256, BF + l * 768 + 0};
            fb.d[l * 3 + 1] = {bl + (l * 5 + 1) * 256, nullptr, nullptr,
                               Wlin + (size_t)(l * 3 + 1) * HH,
                               blin + (l * 3 + 1) * 256, BF + l * 768 + 256};
            fb.d[l * 3 + 2] = {bl + (l * 5 + 3) * 256, nullptr, nullptr,
                               Wlin + (size_t)(l * 3 + 2) * HH,
                               blin + (l * 3 + 2) * 256, BF + l * 768 + 512};
        }
        fold_b6<<<6, 256>>>(fb);
    }

    // --- unified CSR build ---
    cudaMemsetAsync(cnt, 0, CSR_N * sizeof(int), 0);
    {
        int nb = (5 * EE + 255) / 256;
        cnt5<<<nb, 256>>>(dst_f, dst_ra, dst_ta, dst_ar, dst_at, cnt);
        int sb = (CSR_N + 1023) / 1024;
        scan1<<<sb, 1024>>>(cnt, off, bsum, CSR_N);
        scan2<<<1, 1024>>>(bsum, sb);
        scan3<<<(CSR_N + 255) / 256, 256>>>(off, bsum, CSR_N, 5 * EE);
        cudaMemcpyAsync(cnt, off, CSR_N * sizeof(int), cudaMemcpyDeviceToDevice, 0);
        fill5<<<nb, 256>>>(src_f, dst_f, src_ra, dst_ra, src_ta, dst_ta,
                           src_ar, dst_ar, src_at, dst_at, cnt, idx);
    }

    // --- input projections ---
    gemm_proj<<<dim3(2, (NACT  + 127) / 128), 256>>>(x_act,  WPT + 0,     A, NACT,  64, 256);
    gemm_proj<<<dim3(2, (NRES  + 127) / 128), 256>>>(x_res,  WPT + 16384, R, NRES,  32, 256);
    gemm_proj<<<dim3(2, (NTIME + 127) / 128), 256>>>(x_time, WPT + 24576, T, NTIME, 16, 256);

    // --- layers: one fused GEMM launch + one fused gather launch each ---
    const int rtA = (NACT + 127) / 128, rtR = (NRES + 127) / 128, rtT = (NTIME + 127) / 128;
    const int n0 = 8 * rtA, n1 = 4 * rtR, n2 = 4 * rtT;
    const int gblocks = ((NACT + NRES + NTIME) * 32 + 255) / 256;
    for (int l = 0; l < 2; l++) {
        __half* WCa = WCh + (size_t)l * 524288;
        __half* WCr = WCa + 262144;
        __half* WCt = WCr + 131072;
        Gemm3 g;
        g.d[0] = {A, WCa, BF + l * 768 + 0,   Pa, 768, NACT,  1024, 8};
        g.d[1] = {R, WCr, BF + l * 768 + 256, Pr, 256, NRES,  512,  4};
        g.d[2] = {T, WCt, BF + l * 768 + 512, Pt, 256, NTIME, 512,  4};
        g.n0 = n0; g.n01 = n0 + n1;
        gemm_fast3<<<n0 + n1 + n2, 256>>>(g);

        gather_all<<<gblocks, 256>>>(Pa, Pr, Pt, off, idx, A, R, T);
    }

    // --- last-node pooling + heads ---
    cudaMemsetAsync(LAST, 0, GG * sizeof(int), 0);
    last_k<<<(NACT + 255) / 256, 256>>>(batch, LAST, NACT);
    heads_k<<<GG, 64>>>(A, LAST, Wo, bo, Wt, bt, Wrm, brm, (float*)d_out);
}

// round 13
// speedup vs baseline: 9.5382x; 1.7287x over previous
#include <cuda_runtime.h>
#include <cuda_fp16.h>
#include <cstdint>
#include <cstddef>

#define Hc    256
#define CC    50
#define GG    512
#define NACT  200000
#define NRES  20000
#define NTIME 100000
#define EE    400000

// ---------------- scratch layout (float units) ----------------
static constexpr size_t OFF_A    = 0;            // 200000*256 h
static constexpr size_t OFF_R    = 25600000;     // 20000*256 h
static constexpr size_t OFF_T    = 28160000;     // 100000*256 h
static constexpr size_t OFF_PA   = 40960000;     // 200000*1024 h [f|ar|at|self]
static constexpr size_t OFF_PR   = 143360000;    // 20000*512 h   (reused: X2 at l=1)
static constexpr size_t OFF_PT   = 148480000;    // 100000*512 h  (reused: A2 at l=1)
static constexpr size_t OFF_WC   = 174080000;    // folded weights fp16 (l0: 524288 h; +WB2 256*1024 h)
static constexpr size_t OFF_BF   = 175128576;    // 2*3*256 f32
static constexpr size_t OFF_WLT  = 175130112;    // 6*65536 f32 Wlin^T
static constexpr size_t OFF_WPT  = 175523328;    // 256*(64+32+16) f32 Wp^T
static constexpr size_t OFF_LAST = 175552000;    // 512 ints
static constexpr size_t OFF_INT  = 175552512;    // int scratch
static constexpr size_t TOTALF   = 178993600;

// unified CSR (ints, relative to OFF_INT)
static constexpr int CSR_N = 720000;
static constexpr int B_F  = 0;
static constexpr int B_RA = 200000;
static constexpr int B_TA = 400000;
static constexpr int B_AR = 600000;
static constexpr int B_AT = 620000;
static constexpr size_t IO_OFFS = 0;         // 720001
static constexpr size_t IO_CNT  = 720004;    // 720000
static constexpr size_t IO_BSUM = 1440004;   // 1024
static constexpr size_t IO_IDX  = 1441028;   // 2,000,000

__device__ float g_buf[TOTALF];

// =====================================================================
// helpers
// =====================================================================
__device__ __forceinline__ void mma_f16(float* d, const uint32_t* a,
                                        uint32_t b0, uint32_t b1) {
    asm volatile(
        "mma.sync.aligned.m16n8k16.row.col.f32.f16.f16.f32 "
        "{%0,%1,%2,%3}, {%4,%5,%6,%7}, {%8,%9}, {%0,%1,%2,%3};"
        : "+f"(d[0]), "+f"(d[1]), "+f"(d[2]), "+f"(d[3])
        : "r"(a[0]), "r"(a[1]), "r"(a[2]), "r"(a[3]), "r"(b0), "r"(b1));
}
__device__ __forceinline__ void ldsm4(uint32_t* r, uint32_t addr) {
    asm volatile("ldmatrix.sync.aligned.m8n8.x4.shared.b16 {%0,%1,%2,%3}, [%4];"
                 : "=r"(r[0]), "=r"(r[1]), "=r"(r[2]), "=r"(r[3]) : "r"(addr));
}
__device__ __forceinline__ void cp16(uint32_t dst, const void* src, int szbytes) {
    asm volatile("cp.async.cg.shared.global [%0], [%1], 16, %2;"
                 :: "r"(dst), "l"(src), "r"(szbytes));
}
#define CP_COMMIT() asm volatile("cp.async.commit_group;" ::: "memory")
template <int N>
__device__ __forceinline__ void cp_wait() {
    asm volatile("cp.async.wait_group %0;" :: "n"(N) : "memory");
}
__device__ __forceinline__ uint32_t saddr(const void* p) {
    return static_cast<uint32_t>(__cvta_generic_to_shared(p));
}
__device__ __forceinline__ uint32_t packh2(float x, float y) {
    __half2 h = __float22half2_rn(make_float2(x, y));
    return *reinterpret_cast<uint32_t*>(&h);
}
__device__ __forceinline__ uint4 pack8(float4 a, float4 b) {
    return make_uint4(packh2(a.x, a.y), packh2(a.z, a.w),
                      packh2(b.x, b.y), packh2(b.z, b.w));
}
__device__ __forceinline__ void h8_to_f8(uint4 q, float* f) {
    const __half2* h = reinterpret_cast<const __half2*>(&q);
#pragma unroll
    for (int i = 0; i < 4; i++) {
        float2 t = __half22float2(h[i]);
        f[2 * i] = t.x; f[2 * i + 1] = t.y;
    }
}
__device__ __forceinline__ uint4 f8_to_h8(const float* f) {
    return make_uint4(packh2(f[0], f[1]), packh2(f[2], f[3]),
                      packh2(f[4], f[5]), packh2(f[6], f[7]));
}

#define STRH 40   // SMEM row stride in halves (80B: 16B-aligned, ldsm conflict-free)

// =====================================================================
// FUSED fast fp16 GEMM (up to 3 sub-GEMMs per launch), runtime K, relu.
// tile 128x128, warp tile 32x64, cp.async double buffer.
// =====================================================================
struct GemmDesc {
    const __half* A; const __half* B; const float* bias;
    __half* C; int bstart; int Nrow; int ldC; int colT; int K; int relu;
};
struct Gemm3 { GemmDesc d[3]; int n0, n01; };

__global__ void __launch_bounds__(256) gemm_fast3(Gemm3 g) {
    __shared__ __align__(16) __half As[2][128 * STRH];
    __shared__ __align__(16) __half Bs[2][128 * STRH];
    const int id = blockIdx.x;
    const int zi = (id < g.n0) ? 0 : ((id < g.n01) ? 1 : 2);
    const int rid = id - ((zi == 0) ? 0 : ((zi == 1) ? g.n0 : g.n01));
    const GemmDesc d = g.d[zi];
    const int row0 = (rid / d.colT) * 128;
    const int col0 = (rid % d.colT) * 128;
    const int Nrow = d.Nrow;
    const int K = d.K;
    const __half* __restrict__ A = d.A;
    const __half* __restrict__ B = d.B;

    const int tid  = threadIdx.x;
    const int lane = tid & 31;
    const int wid  = tid >> 5;
    const int wm   = wid & 3;
    const int wn   = wid >> 2;
    const int t4   = lane & 3;
    const int g4   = lane >> 2;
    const int arow = lane & 15;
    const int acol = (lane >> 4) << 3;
    const int brow = (lane & 7) + ((lane >> 4) << 3);
    const int bcol = ((lane >> 3) & 1) << 3;

    float acc[2][8][4];
#pragma unroll
    for (int mt = 0; mt < 2; mt++)
#pragma unroll
        for (int nt = 0; nt < 8; nt++)
#pragma unroll
            for (int q = 0; q < 4; q++) acc[mt][nt][q] = 0.f;

    auto stage = [&](int c, int b) {
        const int k0 = c << 5;
#pragma unroll
        for (int it = 0; it < 2; it++) {
            const int i  = tid + it * 256;
            const int rr = i >> 2;
            const int sg = (i & 3) << 3;
            const int gr = row0 + rr;
            const int grc = gr < Nrow ? gr : (Nrow - 1);
            cp16(saddr(&As[b][rr * STRH + sg]),
                 A + (size_t)grc * K + k0 + sg, gr < Nrow ? 16 : 0);
            cp16(saddr(&Bs[b][rr * STRH + sg]),
                 B + (size_t)(col0 + rr) * K + k0 + sg, 16);
        }
    };

    stage(0, 0);
    CP_COMMIT();
    const int nc = K >> 5;
#pragma unroll 1
    for (int c = 0; c < nc; c++) {
        const int cb = c & 1;
        if (c + 1 < nc) { stage(c + 1, cb ^ 1); CP_COMMIT(); cp_wait<1>(); }
        else            { cp_wait<0>(); }
        __syncthreads();
#pragma unroll
        for (int ks = 0; ks < 2; ks++) {
            const int kb = ks << 4;
            uint32_t af[2][4];
#pragma unroll
            for (int mt = 0; mt < 2; mt++)
                ldsm4(af[mt], saddr(&As[cb][(wm * 32 + mt * 16 + arow) * STRH + kb + acol]));
            uint32_t bf[4][4];
#pragma unroll
            for (int p = 0; p < 4; p++)
                ldsm4(bf[p], saddr(&Bs[cb][(wn * 64 + p * 16 + brow) * STRH + kb + bcol]));
#pragma unroll
            for (int nt = 0; nt < 8; nt++) {
                const uint32_t b0 = bf[nt >> 1][(nt & 1) * 2];
                const uint32_t b1 = bf[nt >> 1][(nt & 1) * 2 + 1];
                mma_f16(acc[0][nt], af[0], b0, b1);
                mma_f16(acc[1][nt], af[1], b0, b1);
            }
        }
        __syncthreads();
    }
#pragma unroll
    for (int mt = 0; mt < 2; mt++) {
#pragma unroll
        for (int h = 0; h < 2; h++) {
            const int gr = row0 + wm * 32 + mt * 16 + g4 + h * 8;
            if (gr >= Nrow) continue;
#pragma unroll
            for (int nt = 0; nt < 8; nt++) {
                const int col = col0 + wn * 64 + nt * 8 + t4 * 2;
                float2 v = make_float2(acc[mt][nt][h * 2 + 0], acc[mt][nt][h * 2 + 1]);
                if (col >= d.bstart) {
                    v.x += __ldg(&d.bias[col - d.bstart]);
                    v.y += __ldg(&d.bias[col - d.bstart + 1]);
                }
                if (d.relu) { v.x = fmaxf(v.x, 0.f); v.y = fmaxf(v.y, 0.f); }
                __half2 hv = __float22half2_rn(v);
                *reinterpret_cast<__half2*>(d.C + (size_t)gr * d.ldC + col) = hv;
            }
        }
    }
}

// =====================================================================
// GENERIC GEMM core (f32 A staged to fp16) — projections & folds
// =====================================================================
__device__ __forceinline__ void gemm_core_f32(
        const float* __restrict__ A,
        const float* __restrict__ B0s, const float* __restrict__ B1s,
        const float* __restrict__ B2s,
        __half* __restrict__ C,
        int Nrow, int K, int ldC, int row0, int col0,
        __half* As, __half* Bs) {
    const int tid  = threadIdx.x;
    const int lane = tid & 31;
    const int wid  = tid >> 5;
    const int wm   = wid & 3;
    const int wn   = wid >> 2;
    const int g4   = lane >> 2;
    const int t4   = lane & 3;
    const bool has3 = (B1s != nullptr);

    float acc[2][8][4];
#pragma unroll
    for (int mt = 0; mt < 2; mt++)
#pragma unroll
        for (int nt = 0; nt < 8; nt++)
#pragma unroll
            for (int q = 0; q < 4; q++) acc[mt][nt][q] = 0.f;

    const int nc = (K + 31) >> 5;
    for (int c = 0; c < nc; c++) {
        const int k0 = c << 5;
        if (c) __syncthreads();
#pragma unroll
        for (int it = 0; it < 2; it++) {
            const int idx = tid + it * 256;
            const int rr  = idx >> 2;
            const int cg  = (idx & 3) << 3;
            const bool kok = (k0 + cg) < K;
            uint4 qa = make_uint4(0, 0, 0, 0);
            const int gr = row0 + rr;
            if (gr < Nrow && kok) {
                const float* ap = A + (size_t)gr * K + k0 + cg;
                float4 v0 = *reinterpret_cast<const float4*>(ap);
                float4 v1 = *reinterpret_cast<const float4*>(ap + 4);
                qa = pack8(v0, v1);
            }
            *reinterpret_cast<uint4*>(&As[rr * STRH + cg]) = qa;
            uint4 qb = make_uint4(0, 0, 0, 0);
            if (kok) {
                const size_t bo = (size_t)(col0 + rr) * K + k0 + cg;
                float4 w0 = *reinterpret_cast<const float4*>(B0s + bo);
                float4 w1 = *reinterpret_cast<const float4*>(B0s + bo + 4);
                if (has3) {
                    float4 a1 = *reinterpret_cast<const float4*>(B1s + bo);
                    float4 a2 = *reinterpret_cast<const float4*>(B1s + bo + 4);
                    float4 c1 = *reinterpret_cast<const float4*>(B2s + bo);
                    float4 c2 = *reinterpret_cast<const float4*>(B2s + bo + 4);
                    w0.x += a1.x + c1.x; w0.y += a1.y + c1.y;
                    w0.z += a1.z + c1.z; w0.w += a1.w + c1.w;
                    w1.x += a2.x + c2.x; w1.y += a2.y + c2.y;
                    w1.z += a2.z + c2.z; w1.w += a2.w + c2.w;
                }
                qb = pack8(w0, w1);
            }
            *reinterpret_cast<uint4*>(&Bs[rr * STRH + cg]) = qb;
        }
        __syncthreads();
#pragma unroll
        for (int ks = 0; ks < 2; ks++) {
            const int kb = ks << 4;
            uint32_t af[2][4];
#pragma unroll
            for (int mt = 0; mt < 2; mt++) {
                const int r = wm * 32 + mt * 16 + g4;
                const int base = r * STRH + kb + 2 * t4;
                af[mt][0] = *reinterpret_cast<const uint32_t*>(&As[base]);
                af[mt][1] = *reinterpret_cast<const uint32_t*>(&As[base + 8 * STRH]);
                af[mt][2] = *reinterpret_cast<const uint32_t*>(&As[base + 8]);
                af[mt][3] = *reinterpret_cast<const uint32_t*>(&As[base + 8 * STRH + 8]);
            }
#pragma unroll
            for (int nt = 0; nt < 8; nt++) {
                const int n = wn * 64 + nt * 8 + g4;
                const int bb = n * STRH + kb + 2 * t4;
                const uint32_t b0 = *reinterpret_cast<const uint32_t*>(&Bs[bb]);
                const uint32_t b1 = *reinterpret_cast<const uint32_t*>(&Bs[bb + 8]);
                mma_f16(acc[0][nt], af[0], b0, b1);
                mma_f16(acc[1][nt], af[1], b0, b1);
            }
        }
    }
#pragma unroll
    for (int mt = 0; mt < 2; mt++) {
#pragma unroll
        for (int h = 0; h < 2; h++) {
            const int gr = row0 + wm * 32 + mt * 16 + g4 + h * 8;
            if (gr >= Nrow) continue;
#pragma unroll
            for (int nt = 0; nt < 8; nt++) {
                const int col = col0 + wn * 64 + nt * 8 + t4 * 2;
                float2 v = make_float2(acc[mt][nt][h * 2 + 0], acc[mt][nt][h * 2 + 1]);
                __half2 hv = __float22half2_rn(v);
                *reinterpret_cast<__half2*>(C + (size_t)gr * ldC + col) = hv;
            }
        }
    }
}

// projections: f32 A, one B
__global__ void __launch_bounds__(256) gemm_proj(
        const float* __restrict__ A, const float* __restrict__ B,
        __half* __restrict__ C, int Nrow, int K, int ldC) {
    __shared__ __align__(16) __half As[128 * STRH];
    __shared__ __align__(16) __half Bs[128 * STRH];
    gemm_core_f32(A, B, nullptr, nullptr, C,
                  Nrow, K, ldC, blockIdx.y * 128, blockIdx.x * 128, As, Bs);
}

// batched 256x256x256 weight folds: ONE launch, grid (2,2,12)
struct FoldDesc { const float* A; const float* B0; const float* B1;
                  const float* B2; __half* C; int ldC; };
struct Fold12 { FoldDesc d[12]; };
__global__ void __launch_bounds__(256) gemm_fold(Fold12 args) {
    __shared__ __align__(16) __half As[128 * STRH];
    __shared__ __align__(16) __half Bs[128 * STRH];
    const FoldDesc f = args.d[blockIdx.z];
    gemm_core_f32(f.A, f.B0, f.B1, f.B2, f.C,
                  256, 256, f.ldC, blockIdx.y * 128, blockIdx.x * 128, As, Bs);
}

// batched transposes (9 in one launch)
struct TPArgs { const float* in[9]; float* out[9]; int kin[9]; };
__global__ void transpose9(TPArgs a) {
    int z = blockIdx.z, k = blockIdx.x, n = threadIdx.x;
    if (k < a.kin[z])
        a.out[z][(size_t)n * a.kin[z] + k] = a.in[z][(size_t)k * 256 + n];
}

// batched bias folds (6 in one launch)
struct FoldB { const float* b1; const float* b2; const float* b3;
               const float* B; const float* blin; float* out; };
struct FoldB6 { FoldB d[6]; };
__global__ void fold_b6(FoldB6 a) {
    const FoldB f = a.d[blockIdx.x];
    int j = threadIdx.x;
    float acc = f.blin[j];
    for (int k = 0; k < Hc; k++) {
        float bb = f.b1[k];
        if (f.b2) bb += f.b2[k];
        if (f.b3) bb += f.b3[k];
        acc = fmaf(bb, f.B[k * Hc + j], acc);
    }
    f.out[j] = acc;
}

// =====================================================================
// unified CSR build
// =====================================================================
__global__ void cnt5(const int* __restrict__ d0, const int* __restrict__ d1,
                     const int* __restrict__ d2, const int* __restrict__ d3,
                     const int* __restrict__ d4, int* __restrict__ cnt) {
    int i = blockIdx.x * blockDim.x + threadIdx.x;
    if (i >= 5 * EE) return;
    int r = i / EE, e = i - r * EE;
    const int* dp; int base;
    switch (r) {
        case 0: dp = d0; base = B_F;  break;
        case 1: dp = d1; base = B_RA; break;
        case 2: dp = d2; base = B_TA; break;
        case 3: dp = d3; base = B_AR; break;
        default: dp = d4; base = B_AT; break;
    }
    atomicAdd(&cnt[base + dp[e]], 1);
}
__global__ void scan1(const int* __restrict__ cnt, int* __restrict__ off,
                      int* __restrict__ bsum, int N) {
    __shared__ int sh[1024];
    int i = blockIdx.x * 1024 + threadIdx.x;
    int x = (i < N) ? cnt[i] : 0;
    sh[threadIdx.x] = x;
    __syncthreads();
    for (int d = 1; d < 1024; d <<= 1) {
        int t = (threadIdx.x >= d) ? sh[threadIdx.x - d] : 0;
        __syncthreads();
        sh[threadIdx.x] += t;
        __syncthreads();
    }
    int incl = sh[threadIdx.x];
    if (i < N) off[i] = incl - x;
    if (threadIdx.x == 1023) bsum[blockIdx.x] = incl;
}
__global__ void scan2(int* __restrict__ bsum, int B) {
    __shared__ int sh[1024];
    int t = threadIdx.x;
    int x = (t < B) ? bsum[t] : 0;
    sh[t] = x;
    __syncthreads();
    for (int d = 1; d < 1024; d <<= 1) {
        int v = (t >= d) ? sh[t - d] : 0;
        __syncthreads();
        sh[t] += v;
        __syncthreads();
    }
    if (t < B) bsum[t] = sh[t] - x;
}
__global__ void scan3(int* __restrict__ off, const int* __restrict__ bsum,
                      int N, int total) {
    int i = blockIdx.x * blockDim.x + threadIdx.x;
    if (i < N) off[i] += bsum[i >> 10];
    if (i == 0) off[N] = total;
}
__global__ void fill5(const int* __restrict__ s0, const int* __restrict__ d0,
                      const int* __restrict__ s1, const int* __restrict__ d1,
                      const int* __restrict__ s2, const int* __restrict__ d2,
                      const int* __restrict__ s3, const int* __restrict__ d3,
                      const int* __restrict__ s4, const int* __restrict__ d4,
                      int* __restrict__ cur, int* __restrict__ idx) {
    int i = blockIdx.x * blockDim.x + threadIdx.x;
    if (i >= 5 * EE) return;
    int r = i / EE, e = i - r * EE;
    const int *sp, *dp; int base;
    switch (r) {
        case 0: sp = s0; dp = d0; base = B_F;  break;
        case 1: sp = s1; dp = d1; base = B_RA; break;
        case 2: sp = s2; dp = d2; base = B_TA; break;
        case 3: sp = s3; dp = d3; base = B_AR; break;
        default: sp = s4; dp = d4; base = B_AT; break;
    }
    int p = atomicAdd(&cur[base + dp[e]], 1);
    idx[p] = sp[e];
}

// =====================================================================
// gathers
// =====================================================================
__device__ __forceinline__ void accum_rel(const __half* __restrict__ base, int stride,
                                          const int* __restrict__ off,
                                          const int* __restrict__ idx,
                                          int w, int lane, float* a) {
    int se = (lane < 2) ? __ldg(&off[w + lane]) : 0;
    int s = __shfl_sync(0xffffffffu, se, 0);
    int e = __shfl_sync(0xffffffffu, se, 1);
    if (e <= s) return;
    float sc = 1.f / (float)(e - s);
    float m[8] = {0.f, 0.f, 0.f, 0.f, 0.f, 0.f, 0.f, 0.f};
    for (int p = s; p < e; p++) {
        int sn = __ldg(&idx[p]);
        uint4 q = *reinterpret_cast<const uint4*>(base + (size_t)sn * stride + lane * 8);
        float f[8];
        h8_to_f8(q, f);
#pragma unroll
        for (int j = 0; j < 8; j++) m[j] += f[j];
    }
#pragma unroll
    for (int j = 0; j < 8; j++) a[j] += m[j] * sc;
}

// layer-0 gather: all node types (mean + self + relu)
__global__ void __launch_bounds__(256) gather_all(
        const __half* __restrict__ Pa, const __half* __restrict__ Pr,
        const __half* __restrict__ Pt,
        const int* __restrict__ off, const int* __restrict__ idx,
        __half* __restrict__ A, __half* __restrict__ R, __half* __restrict__ T) {
    int w = (blockIdx.x * 256 + threadIdx.x) >> 5;
    int lane = threadIdx.x & 31;
    float a[8];
    if (w < NACT) {
        h8_to_f8(*reinterpret_cast<const uint4*>(Pa + (size_t)w * 1024 + 768 + lane * 8), a);
        accum_rel(Pa, 1024, off + B_F,  idx, w, lane, a);
        accum_rel(Pr, 512,  off + B_RA, idx, w, lane, a);
        accum_rel(Pt, 512,  off + B_TA, idx, w, lane, a);
#pragma unroll
        for (int j = 0; j < 8; j++) a[j] = fmaxf(a[j], 0.f);
        *reinterpret_cast<uint4*>(A + (size_t)w * 256 + lane * 8) = f8_to_h8(a);
    } else if (w < NACT + NRES) {
        int v = w - NACT;
        h8_to_f8(*reinterpret_cast<const uint4*>(Pr + (size_t)v * 512 + 256 + lane * 8), a);
        accum_rel(Pa + 256, 1024, off + B_AR, idx, v, lane, a);
#pragma unroll
        for (int j = 0; j < 8; j++) a[j] = fmaxf(a[j], 0.f);
        *reinterpret_cast<uint4*>(R + (size_t)v * 256 + lane * 8) = f8_to_h8(a);
    } else if (w < NACT + NRES + NTIME) {
        int v = w - NACT - NRES;
        h8_to_f8(*reinterpret_cast<const uint4*>(Pt + (size_t)v * 512 + 256 + lane * 8), a);
        accum_rel(Pa + 512, 1024, off + B_AT, idx, v, lane, a);
#pragma unroll
        for (int j = 0; j < 8; j++) a[j] = fmaxf(a[j], 0.f);
        *reinterpret_cast<uint4*>(T + (size_t)v * 256 + lane * 8) = f8_to_h8(a);
    }
}

// layer-1 pooled gather: build X2[512, 1024] = [mf(a1)|mra(r1)|mta(t1)|a1 self]
__global__ void __launch_bounds__(256) gather_pool(
        const __half* __restrict__ A, const __half* __restrict__ R,
        const __half* __restrict__ T,
        const int* __restrict__ off, const int* __restrict__ idx,
        const int* __restrict__ last, __half* __restrict__ X2) {
    int w = (blockIdx.x * 256 + threadIdx.x) >> 5;   // 0..2047
    int lane = threadIdx.x & 31;
    if (w >= 4 * GG) return;
    int g = w >> 2, s = w & 3;
    int nid = __ldg(&last[g]);
    float a[8] = {0.f, 0.f, 0.f, 0.f, 0.f, 0.f, 0.f, 0.f};
    if (s == 0)      accum_rel(A, 256, off + B_F,  idx, nid, lane, a);
    else if (s == 1) accum_rel(R, 256, off + B_RA, idx, nid, lane, a);
    else if (s == 2) accum_rel(T, 256, off + B_TA, idx, nid, lane, a);
    else h8_to_f8(*reinterpret_cast<const uint4*>(A + (size_t)nid * 256 + lane * 8), a);
    *reinterpret_cast<uint4*>(X2 + (size_t)g * 1024 + s * 256 + lane * 8) = f8_to_h8(a);
}

// =====================================================================
// misc kernels
// =====================================================================
__global__ void last_k(const int* __restrict__ batch, int* __restrict__ last, int N) {
    int i = blockIdx.x * blockDim.x + threadIdx.x;
    if (i < N) {
        if (i == N - 1 || batch[i + 1] != batch[i]) last[batch[i]] = i;
    }
}

__global__ void heads_k(const __half* __restrict__ a2,
                        const float* __restrict__ Wo, const float* __restrict__ bo,
                        const float* __restrict__ Wt, const float* __restrict__ bt,
                        const float* __restrict__ Wrm, const float* __restrict__ brm,
                        float* __restrict__ out) {
    int g = blockIdx.x;
    __shared__ float p[Hc];
    const __half* row = a2 + (size_t)g * Hc;
    for (int k = threadIdx.x; k < Hc; k += blockDim.x) p[k] = __half2float(row[k]);
    __syncthreads();
    int j = threadIdx.x;
    if (j < CC) {
        float acc = bo[j];
        for (int k = 0; k < Hc; k++) acc = fmaf(p[k], Wo[k * CC + j], acc);
        out[g * CC + j] = acc;
    } else if (j == CC) {
        float acc = bt[0];
        for (int k = 0; k < Hc; k++) acc = fmaf(p[k], Wt[k], acc);
        out[GG * CC + g] = acc;
    } else if (j == CC + 1) {
        float acc = brm[0];
        for (int k = 0; k < Hc; k++) acc = fmaf(p[k], Wrm[k], acc);
        out[GG * CC + GG + g] = acc;
    }
}

// =====================================================================
// host orchestration
// =====================================================================
extern "C" void kernel_launch(void* const* d_in, const int* in_sizes, int n_in,
                              void* d_out, int out_size) {
    float* buf = nullptr;
    cudaGetSymbolAddress((void**)&buf, g_buf);

    __half* A  = reinterpret_cast<__half*>(buf + OFF_A);
    __half* R  = reinterpret_cast<__half*>(buf + OFF_R);
    __half* T  = reinterpret_cast<__half*>(buf + OFF_T);
    __half* Pa = reinterpret_cast<__half*>(buf + OFF_PA);
    __half* Pr = reinterpret_cast<__half*>(buf + OFF_PR);
    __half* Pt = reinterpret_cast<__half*>(buf + OFF_PT);
    __half* X2 = Pr;                                   // reused at l=1
    __half* A2 = Pt;                                   // reused at l=1
    __half* WCh = reinterpret_cast<__half*>(buf + OFF_WC);   // l=0 folds [524288 h]
    __half* WB2 = WCh + 524288;                               // l=1 folds [256x1024 h]
    float* BF  = buf + OFF_BF;
    float* WLT = buf + OFF_WLT;
    float* WPT = buf + OFF_WPT;
    int*   LAST = reinterpret_cast<int*>(buf + OFF_LAST);
    int*   IB   = reinterpret_cast<int*>(buf + OFF_INT);
    int* off  = IB + IO_OFFS;
    int* cnt  = IB + IO_CNT;
    int* bsum = IB + IO_BSUM;
    int* idx  = IB + IO_IDX;

    const float* x_act  = (const float*)d_in[0];
    const float* x_res  = (const float*)d_in[1];
    const float* x_time = (const float*)d_in[2];
    const int* src_f  = (const int*)d_in[3];
    const int* dst_f  = (const int*)d_in[4];
    const int* src_ar = (const int*)d_in[5];
    const int* dst_ar = (const int*)d_in[6];
    const int* src_ra = (const int*)d_in[7];
    const int* dst_ra = (const int*)d_in[8];
    const int* src_at = (const int*)d_in[9];
    const int* dst_at = (const int*)d_in[10];
    const int* src_ta = (const int*)d_in[11];
    const int* dst_ta = (const int*)d_in[12];
    const int* batch  = (const int*)d_in[13];

    int w = (in_sizes[14] <= 4) ? 15 : 14;
    const float* Wp_act = (const float*)d_in[w + 0];
    const float* Wp_res = (const float*)d_in[w + 1];
    const float* Wp_tim = (const float*)d_in[w + 2];
    const float* Wl     = (const float*)d_in[w + 3];
    const float* bl     = (const float*)d_in[w + 4];
    const float* Wr     = (const float*)d_in[w + 5];
    const float* Wlin   = (const float*)d_in[w + 6];
    const float* blin   = (const float*)d_in[w + 7];
    const float* Wo     = (const float*)d_in[w + 8];
    const float* bo     = (const float*)d_in[w + 9];
    const float* Wt     = (const float*)d_in[w + 10];
    const float* bt     = (const float*)d_in[w + 11];
    const float* Wrm    = (const float*)d_in[w + 12];
    const float* brm    = (const float*)d_in[w + 13];

    const size_t HH = 65536;  // 256*256

    // --- fused transposes ---
    {
        TPArgs tp;
        tp.in[0] = Wp_act; tp.out[0] = WPT + 0;     tp.kin[0] = 64;
        tp.in[1] = Wp_res; tp.out[1] = WPT + 16384; tp.kin[1] = 32;
        tp.in[2] = Wp_tim; tp.out[2] = WPT + 24576; tp.kin[2] = 16;
        for (int i = 0; i < 6; i++) {
            tp.in[3 + i]  = Wlin + (size_t)i * HH;
            tp.out[3 + i] = WLT + (size_t)i * HH;
            tp.kin[3 + i] = 256;
        }
        transpose9<<<dim3(256, 1, 9), 256>>>(tp);
    }

    // --- fused weight folds: 8 (l=0, P layout) + 4 (l=1, B2 layout) ---
    {
        Fold12 fa;
        // l = 0: P layout [col, kin], ldC = 256
        {
            const float* lt0 = WLT + 0 * HH;
            const float* lt1 = WLT + 1 * HH;
            const float* lt2 = WLT + 2 * HH;
            __half* WCa = WCh;
            __half* WCr = WCa + 262144;
            __half* WCt = WCr + 131072;
            fa.d[0] = {lt0, Wl + 0 * HH, nullptr, nullptr, WCa + 0,      256};
            fa.d[1] = {lt1, Wl + 1 * HH, nullptr, nullptr, WCa + 65536,  256};
            fa.d[2] = {lt2, Wl + 3 * HH, nullptr, nullptr, WCa + 131072, 256};
            fa.d[3] = {lt0, Wr + 0 * HH, Wr + 2 * HH, Wr + 4 * HH, WCa + 196608, 256};
            fa.d[4] = {lt0, Wl + 2 * HH, nullptr, nullptr, WCr + 0,      256};
            fa.d[5] = {lt1, Wr + 1 * HH, nullptr, nullptr, WCr + 65536,  256};
            fa.d[6] = {lt0, Wl + 4 * HH, nullptr, nullptr, WCt + 0,      256};
            fa.d[7] = {lt2, Wr + 3 * HH, nullptr, nullptr, WCt + 65536,  256};
        }
        // l = 1: act-only folds in concat-K layout [o, s*256+kin], ldC = 1024
        {
            const float* lt0 = WLT + 3 * HH;   // Wlin^T act, layer 1
            fa.d[8]  = {lt0, Wl + 5 * HH, nullptr, nullptr, WB2 + 0,   1024};  // f
            fa.d[9]  = {lt0, Wl + 7 * HH, nullptr, nullptr, WB2 + 256, 1024};  // ra
            fa.d[10] = {lt0, Wl + 9 * HH, nullptr, nullptr, WB2 + 512, 1024};  // ta
            fa.d[11] = {lt0, Wr + 5 * HH, Wr + 7 * HH, Wr + 9 * HH, WB2 + 768, 1024};  // self
        }
        gemm_fold<<<dim3(2, 2, 12), 256>>>(fa);

        FoldB6 fb;
        for (int l = 0; l < 2; l++) {
            fb.d[l * 3 + 0] = {bl + (l * 5 + 0) * 256, bl + (l * 5 + 2) * 256,
                               bl + (l * 5 + 4) * 256, Wlin + (size_t)(l * 3 + 0) * HH,
                               blin + (l * 3 + 0) * 256, BF + l * 768 + 0};
            fb.d[l * 3 + 1] = {bl + (l * 5 + 1) * 256, nullptr, nullptr,
                               Wlin + (size_t)(l * 3 + 1) * HH,
                               blin + (l * 3 + 1) * 256, BF + l * 768 + 256};
            fb.d[l * 3 + 2] = {bl + (l * 5 + 3) * 256, nullptr, nullptr,
                               Wlin + (size_t)(l * 3 + 2) * HH,
                               blin + (l * 3 + 2) * 256, BF + l * 768 + 512};
        }
        fold_b6<<<6, 256>>>(fb);
    }

    // --- unified CSR build + pooled-row indices ---
    cudaMemsetAsync(cnt, 0, CSR_N * sizeof(int), 0);
    {
        int nb = (5 * EE + 255) / 256;
        cnt5<<<nb, 256>>>(dst_f, dst_ra, dst_ta, dst_ar, dst_at, cnt);
        int sb = (CSR_N + 1023) / 1024;
        scan1<<<sb, 1024>>>(cnt, off, bsum, CSR_N);
        scan2<<<1, 1024>>>(bsum, sb);
        scan3<<<(CSR_N + 255) / 256, 256>>>(off, bsum, CSR_N, 5 * EE);
        cudaMemcpyAsync(cnt, off, CSR_N * sizeof(int), cudaMemcpyDeviceToDevice, 0);
        fill5<<<nb, 256>>>(src_f, dst_f, src_ra, dst_ra, src_ta, dst_ta,
                           src_ar, dst_ar, src_at, dst_at, cnt, idx);
    }
    cudaMemsetAsync(LAST, 0, GG * sizeof(int), 0);
    last_k<<<(NACT + 255) / 256, 256>>>(batch, LAST, NACT);

    // --- input projections ---
    gemm_proj<<<dim3(2, (NACT  + 127) / 128), 256>>>(x_act,  WPT + 0,     A, NACT,  64, 256);
    gemm_proj<<<dim3(2, (NRES  + 127) / 128), 256>>>(x_res,  WPT + 16384, R, NRES,  32, 256);
    gemm_proj<<<dim3(2, (NTIME + 127) / 128), 256>>>(x_time, WPT + 24576, T, NTIME, 16, 256);

    // --- layer 0: full wide GEMM + full gather ---
    {
        __half* WCa = WCh;
        __half* WCr = WCa + 262144;
        __half* WCt = WCr + 131072;
        const int rtA = (NACT + 127) / 128, rtR = (NRES + 127) / 128, rtT = (NTIME + 127) / 128;
        const int n0 = 8 * rtA, n1 = 4 * rtR, n2 = 4 * rtT;
        Gemm3 g;
        g.d[0] = {A, WCa, BF + 0,   Pa, 768, NACT,  1024, 8, 256, 0};
        g.d[1] = {R, WCr, BF + 256, Pr, 256, NRES,  512,  4, 256, 0};
        g.d[2] = {T, WCt, BF + 512, Pt, 256, NTIME, 512,  4, 256, 0};
        g.n0 = n0; g.n01 = n0 + n1;
        gemm_fast3<<<n0 + n1 + n2, 256>>>(g);

        const int gblocks = ((NACT + NRES + NTIME) * 32 + 255) / 256;
        gather_all<<<gblocks, 256>>>(Pa, Pr, Pt, off, idx, A, R, T);
    }

    // --- layer 1: pooled-only aggregate-then-project (512 rows) ---
    {
        gather_pool<<<(4 * GG * 32 + 255) / 256, 256>>>(A, R, T, off, idx, LAST, X2);
        Gemm3 g;
        g.d[0] = {X2, WB2, BF + 768, A2, 0, GG, 256, 2, 1024, 1};
        g.d[1] = g.d[0]; g.d[2] = g.d[0];
        g.n0 = 8; g.n01 = 8;               // 4 row tiles x 2 col tiles
        gemm_fast3<<<8, 256>>>(g);
    }

    // --- heads on pooled features ---
    heads_k<<<GG, 64>>>(A2, Wo, bo, Wt, bt, Wrm, brm, (float*)d_out);
}

// round 14
// speedup vs baseline: 27.9324x; 2.9285x over previous
#include <cuda_runtime.h>
#include <cuda_fp16.h>
#include <cstdint>
#include <cstddef>

#define Hc    256
#define CC    50
#define GG    512
#define NACT  200000
#define NRES  20000
#define NTIME 100000
#define EE    400000

// ---------------- scratch layout (float units) ----------------
static constexpr size_t OFF_A    = 0;            // 200000*256 h
static constexpr size_t OFF_R    = 25600000;     // 20000*256 h
static constexpr size_t OFF_T    = 28160000;     // 100000*256 h
static constexpr size_t OFF_PA   = 40960000;     // 200000*1024 h [f|ar|at|self]
static constexpr size_t OFF_PR   = 143360000;    // 20000*512 h   (reused: X2)
static constexpr size_t OFF_PT   = 148480000;    // 100000*512 h  (reused: A2)
static constexpr size_t OFF_WC   = 174080000;    // folded weights fp16
static constexpr size_t OFF_BF   = 175128576;    // 2*3*256 f32
static constexpr size_t OFF_WLT  = 175130112;    // 6*65536 f32 Wlin^T
static constexpr size_t OFF_WPT  = 175523328;    // 256*(64+32+16) f32 Wp^T
static constexpr size_t OFF_LAST = 175552000;    // 512 ints
static constexpr size_t OFF_INT  = 175552512;    // CSR int scratch
static constexpr size_t OFF_INT2 = 178993600;    // frontier int scratch
static constexpr size_t TOTALF   = 180680000;

// unified CSR (ints, relative to OFF_INT)
static constexpr int CSR_N = 720000;
static constexpr int B_F  = 0;
static constexpr int B_RA = 200000;
static constexpr int B_TA = 400000;
static constexpr int B_AR = 600000;
static constexpr int B_AT = 620000;
static constexpr size_t IO_OFFS = 0;         // 720001
static constexpr size_t IO_CNT  = 720004;    // 720000
static constexpr size_t IO_BSUM = 1440004;   // 1024
static constexpr size_t IO_IDX  = 1441028;   // 2,000,000

// frontier region (ints, relative to OFF_INT2)
static constexpr size_t F_LAST = 0;         // 200000
static constexpr size_t F_A1   = 200000;    // 200000
static constexpr size_t F_R1   = 400000;    // 20000
static constexpr size_t F_T1   = 420000;    // 100000
static constexpr size_t F_PA   = 520000;    // 200000
static constexpr size_t F_PR   = 720000;    // 20000
static constexpr size_t F_PT   = 740000;    // 100000  (flags end @ 840000)
static constexpr size_t L_A1   = 840000;    // 200000
static constexpr size_t L_R1   = 1040000;   // 20000
static constexpr size_t L_T1   = 1060000;   // 100000
static constexpr size_t L_PA   = 1160000;   // 200000
static constexpr size_t L_PR   = 1360000;   // 20000
static constexpr size_t L_PT   = 1380000;   // 100000
static constexpr size_t CTRS   = 1480000;   // 8 (0:A1 1:R1 2:T1 3:PA 4:PR 5:PT)

__device__ float g_buf[TOTALF];

// =====================================================================
// helpers
// =====================================================================
__device__ __forceinline__ void mma_f16(float* d, const uint32_t* a,
                                        uint32_t b0, uint32_t b1) {
    asm volatile(
        "mma.sync.aligned.m16n8k16.row.col.f32.f16.f16.f32 "
        "{%0,%1,%2,%3}, {%4,%5,%6,%7}, {%8,%9}, {%0,%1,%2,%3};"
        : "+f"(d[0]), "+f"(d[1]), "+f"(d[2]), "+f"(d[3])
        : "r"(a[0]), "r"(a[1]), "r"(a[2]), "r"(a[3]), "r"(b0), "r"(b1));
}
__device__ __forceinline__ void ldsm4(uint32_t* r, uint32_t addr) {
    asm volatile("ldmatrix.sync.aligned.m8n8.x4.shared.b16 {%0,%1,%2,%3}, [%4];"
                 : "=r"(r[0]), "=r"(r[1]), "=r"(r[2]), "=r"(r[3]) : "r"(addr));
}
__device__ __forceinline__ void cp16(uint32_t dst, const void* src, int szbytes) {
    asm volatile("cp.async.cg.shared.global [%0], [%1], 16, %2;"
                 :: "r"(dst), "l"(src), "r"(szbytes));
}
#define CP_COMMIT() asm volatile("cp.async.commit_group;" ::: "memory")
template <int N>
__device__ __forceinline__ void cp_wait() {
    asm volatile("cp.async.wait_group %0;" :: "n"(N) : "memory");
}
__device__ __forceinline__ uint32_t saddr(const void* p) {
    return static_cast<uint32_t>(__cvta_generic_to_shared(p));
}
__device__ __forceinline__ uint32_t packh2(float x, float y) {
    __half2 h = __float22half2_rn(make_float2(x, y));
    return *reinterpret_cast<uint32_t*>(&h);
}
__device__ __forceinline__ uint4 pack8(float4 a, float4 b) {
    return make_uint4(packh2(a.x, a.y), packh2(a.z, a.w),
                      packh2(b.x, b.y), packh2(b.z, b.w));
}
__device__ __forceinline__ void h8_to_f8(uint4 q, float* f) {
    const __half2* h = reinterpret_cast<const __half2*>(&q);
#pragma unroll
    for (int i = 0; i < 4; i++) {
        float2 t = __half22float2(h[i]);
        f[2 * i] = t.x; f[2 * i + 1] = t.y;
    }
}
__device__ __forceinline__ uint4 f8_to_h8(const float* f) {
    return make_uint4(packh2(f[0], f[1]), packh2(f[2], f[3]),
                      packh2(f[4], f[5]), packh2(f[6], f[7]));
}

#define STRH 40

// =====================================================================
// fused fp16 GEMM (pooled layer-1): up to 3 sub-GEMMs, runtime K, relu
// =====================================================================
struct GemmDesc {
    const __half* A; const __half* B; const float* bias;
    __half* C; int bstart; int Nrow; int ldC; int colT; int K; int relu;
};
struct Gemm3 { GemmDesc d[3]; int n0, n01; };

__global__ void __launch_bounds__(256) gemm_fast3(Gemm3 g) {
    __shared__ __align__(16) __half As[2][128 * STRH];
    __shared__ __align__(16) __half Bs[2][128 * STRH];
    const int id = blockIdx.x;
    const int zi = (id < g.n0) ? 0 : ((id < g.n01) ? 1 : 2);
    const int rid = id - ((zi == 0) ? 0 : ((zi == 1) ? g.n0 : g.n01));
    const GemmDesc d = g.d[zi];
    const int row0 = (rid / d.colT) * 128;
    const int col0 = (rid % d.colT) * 128;
    const int Nrow = d.Nrow;
    const int K = d.K;
    const __half* __restrict__ A = d.A;
    const __half* __restrict__ B = d.B;

    const int tid  = threadIdx.x;
    const int lane = tid & 31;
    const int wid  = tid >> 5;
    const int wm   = wid & 3;
    const int wn   = wid >> 2;
    const int t4   = lane & 3;
    const int g4   = lane >> 2;
    const int arow = lane & 15;
    const int acol = (lane >> 4) << 3;
    const int brow = (lane & 7) + ((lane >> 4) << 3);
    const int bcol = ((lane >> 3) & 1) << 3;

    float acc[2][8][4];
#pragma unroll
    for (int mt = 0; mt < 2; mt++)
#pragma unroll
        for (int nt = 0; nt < 8; nt++)
#pragma unroll
            for (int q = 0; q < 4; q++) acc[mt][nt][q] = 0.f;

    auto stage = [&](int c, int b) {
        const int k0 = c << 5;
#pragma unroll
        for (int it = 0; it < 2; it++) {
            const int i  = tid + it * 256;
            const int rr = i >> 2;
            const int sg = (i & 3) << 3;
            const int gr = row0 + rr;
            const int grc = gr < Nrow ? gr : (Nrow - 1);
            cp16(saddr(&As[b][rr * STRH + sg]),
                 A + (size_t)grc * K + k0 + sg, gr < Nrow ? 16 : 0);
            cp16(saddr(&Bs[b][rr * STRH + sg]),
                 B + (size_t)(col0 + rr) * K + k0 + sg, 16);
        }
    };

    stage(0, 0);
    CP_COMMIT();
    const int nc = K >> 5;
#pragma unroll 1
    for (int c = 0; c < nc; c++) {
        const int cb = c & 1;
        if (c + 1 < nc) { stage(c + 1, cb ^ 1); CP_COMMIT(); cp_wait<1>(); }
        else            { cp_wait<0>(); }
        __syncthreads();
#pragma unroll
        for (int ks = 0; ks < 2; ks++) {
            const int kb = ks << 4;
            uint32_t af[2][4];
#pragma unroll
            for (int mt = 0; mt < 2; mt++)
                ldsm4(af[mt], saddr(&As[cb][(wm * 32 + mt * 16 + arow) * STRH + kb + acol]));
            uint32_t bf[4][4];
#pragma unroll
            for (int p = 0; p < 4; p++)
                ldsm4(bf[p], saddr(&Bs[cb][(wn * 64 + p * 16 + brow) * STRH + kb + bcol]));
#pragma unroll
            for (int nt = 0; nt < 8; nt++) {
                const uint32_t b0 = bf[nt >> 1][(nt & 1) * 2];
                const uint32_t b1 = bf[nt >> 1][(nt & 1) * 2 + 1];
                mma_f16(acc[0][nt], af[0], b0, b1);
                mma_f16(acc[1][nt], af[1], b0, b1);
            }
        }
        __syncthreads();
    }
#pragma unroll
    for (int mt = 0; mt < 2; mt++) {
#pragma unroll
        for (int h = 0; h < 2; h++) {
            const int gr = row0 + wm * 32 + mt * 16 + g4 + h * 8;
            if (gr >= Nrow) continue;
#pragma unroll
            for (int nt = 0; nt < 8; nt++) {
                const int col = col0 + wn * 64 + nt * 8 + t4 * 2;
                float2 v = make_float2(acc[mt][nt][h * 2 + 0], acc[mt][nt][h * 2 + 1]);
                if (col >= d.bstart) {
                    v.x += __ldg(&d.bias[col - d.bstart]);
                    v.y += __ldg(&d.bias[col - d.bstart + 1]);
                }
                if (d.relu) { v.x = fmaxf(v.x, 0.f); v.y = fmaxf(v.y, 0.f); }
                __half2 hv = __float22half2_rn(v);
                *reinterpret_cast<__half2*>(d.C + (size_t)gr * d.ldC + col) = hv;
            }
        }
    }
}

// =====================================================================
// INDEXED fp16 GEMM (layer-0 frontier): fused 3 sub-GEMMs, K=256,
// rows via list, row count device-side, early-exit CTAs.
// =====================================================================
struct IdxG { const __half* A; const __half* B; const float* bias; int bstart;
              __half* C; int ldC; int colT; const int* rows; const int* cntp; };
struct IdxG3 { IdxG d[3]; };

__global__ void __launch_bounds__(256) gemm_idx3(IdxG3 g) {
    const IdxG d = g.d[blockIdx.z];
    if ((int)blockIdx.x >= d.colT) return;
    const int nrows = *d.cntp;
    const int row0 = blockIdx.y * 128;
    if (row0 >= nrows) return;
    __shared__ __align__(16) __half As[2][128 * STRH];
    __shared__ __align__(16) __half Bs[2][128 * STRH];
    const int col0 = blockIdx.x * 128;
    const __half* __restrict__ A = d.A;
    const __half* __restrict__ B = d.B;
    const int* __restrict__ rows = d.rows;
    constexpr int K = 256;

    const int tid  = threadIdx.x;
    const int lane = tid & 31;
    const int wid  = tid >> 5;
    const int wm   = wid & 3;
    const int wn   = wid >> 2;
    const int t4   = lane & 3;
    const int g4   = lane >> 2;
    const int arow = lane & 15;
    const int acol = (lane >> 4) << 3;
    const int brow = (lane & 7) + ((lane >> 4) << 3);
    const int bcol = ((lane >> 3) & 1) << 3;

    float acc[2][8][4];
#pragma unroll
    for (int mt = 0; mt < 2; mt++)
#pragma unroll
        for (int nt = 0; nt < 8; nt++)
#pragma unroll
            for (int q = 0; q < 4; q++) acc[mt][nt][q] = 0.f;

    auto stage = [&](int c, int b) {
        const int k0 = c << 5;
#pragma unroll
        for (int it = 0; it < 2; it++) {
            const int i  = tid + it * 256;
            const int rr = i >> 2;
            const int sg = (i & 3) << 3;
            const int gr = row0 + rr;
            const int ri = __ldg(&rows[gr < nrows ? gr : (nrows - 1)]);
            cp16(saddr(&As[b][rr * STRH + sg]),
                 A + (size_t)ri * K + k0 + sg, gr < nrows ? 16 : 0);
            cp16(saddr(&Bs[b][rr * STRH + sg]),
                 B + (size_t)(col0 + rr) * K + k0 + sg, 16);
        }
    };

    stage(0, 0);
    CP_COMMIT();
    constexpr int nc = K >> 5;
#pragma unroll 1
    for (int c = 0; c < nc; c++) {
        const int cb = c & 1;
        if (c + 1 < nc) { stage(c + 1, cb ^ 1); CP_COMMIT(); cp_wait<1>(); }
        else            { cp_wait<0>(); }
        __syncthreads();
#pragma unroll
        for (int ks = 0; ks < 2; ks++) {
            const int kb = ks << 4;
            uint32_t af[2][4];
#pragma unroll
            for (int mt = 0; mt < 2; mt++)
                ldsm4(af[mt], saddr(&As[cb][(wm * 32 + mt * 16 + arow) * STRH + kb + acol]));
            uint32_t bf[4][4];
#pragma unroll
            for (int p = 0; p < 4; p++)
                ldsm4(bf[p], saddr(&Bs[cb][(wn * 64 + p * 16 + brow) * STRH + kb + bcol]));
#pragma unroll
            for (int nt = 0; nt < 8; nt++) {
                const uint32_t b0 = bf[nt >> 1][(nt & 1) * 2];
                const uint32_t b1 = bf[nt >> 1][(nt & 1) * 2 + 1];
                mma_f16(acc[0][nt], af[0], b0, b1);
                mma_f16(acc[1][nt], af[1], b0, b1);
            }
        }
        __syncthreads();
    }
#pragma unroll
    for (int mt = 0; mt < 2; mt++) {
#pragma unroll
        for (int h = 0; h < 2; h++) {
            const int gr = row0 + wm * 32 + mt * 16 + g4 + h * 8;
            if (gr >= nrows) continue;
            const int ro = __ldg(&rows[gr]);
#pragma unroll
            for (int nt = 0; nt < 8; nt++) {
                const int col = col0 + wn * 64 + nt * 8 + t4 * 2;
                float2 v = make_float2(acc[mt][nt][h * 2 + 0], acc[mt][nt][h * 2 + 1]);
                if (col >= d.bstart) {
                    v.x += __ldg(&d.bias[col - d.bstart]);
                    v.y += __ldg(&d.bias[col - d.bstart + 1]);
                }
                __half2 hv = __float22half2_rn(v);
                *reinterpret_cast<__half2*>(d.C + (size_t)ro * d.ldC + col) = hv;
            }
        }
    }
}

// =====================================================================
// GENERIC GEMM core (f32 A staged to fp16), optional row indexing
// =====================================================================
__device__ __forceinline__ void gemm_core_f32(
        const float* __restrict__ A,
        const float* __restrict__ B0s, const float* __restrict__ B1s,
        const float* __restrict__ B2s,
        __half* __restrict__ C,
        int nrows, int K, int ldC, int row0, int col0,
        const int* __restrict__ rows,
        __half* As, __half* Bs) {
    const int tid  = threadIdx.x;
    const int lane = tid & 31;
    const int wid  = tid >> 5;
    const int wm   = wid & 3;
    const int wn   = wid >> 2;
    const int g4   = lane >> 2;
    const int t4   = lane & 3;
    const bool has3 = (B1s != nullptr);

    float acc[2][8][4];
#pragma unroll
    for (int mt = 0; mt < 2; mt++)
#pragma unroll
        for (int nt = 0; nt < 8; nt++)
#pragma unroll
            for (int q = 0; q < 4; q++) acc[mt][nt][q] = 0.f;

    const int nc = (K + 31) >> 5;
    for (int c = 0; c < nc; c++) {
        const int k0 = c << 5;
        if (c) __syncthreads();
#pragma unroll
        for (int it = 0; it < 2; it++) {
            const int idx = tid + it * 256;
            const int rr  = idx >> 2;
            const int cg  = (idx & 3) << 3;
            const bool kok = (k0 + cg) < K;
            uint4 qa = make_uint4(0, 0, 0, 0);
            const int gr = row0 + rr;
            if (gr < nrows && kok) {
                const int ri = rows ? __ldg(&rows[gr]) : gr;
                const float* ap = A + (size_t)ri * K + k0 + cg;
                float4 v0 = *reinterpret_cast<const float4*>(ap);
                float4 v1 = *reinterpret_cast<const float4*>(ap + 4);
                qa = pack8(v0, v1);
            }
            *reinterpret_cast<uint4*>(&As[rr * STRH + cg]) = qa;
            uint4 qb = make_uint4(0, 0, 0, 0);
            if (kok) {
                const size_t bo = (size_t)(col0 + rr) * K + k0 + cg;
                float4 w0 = *reinterpret_cast<const float4*>(B0s + bo);
                float4 w1 = *reinterpret_cast<const float4*>(B0s + bo + 4);
                if (has3) {
                    float4 a1 = *reinterpret_cast<const float4*>(B1s + bo);
                    float4 a2 = *reinterpret_cast<const float4*>(B1s + bo + 4);
                    float4 c1 = *reinterpret_cast<const float4*>(B2s + bo);
                    float4 c2 = *reinterpret_cast<const float4*>(B2s + bo + 4);
                    w0.x += a1.x + c1.x; w0.y += a1.y + c1.y;
                    w0.z += a1.z + c1.z; w0.w += a1.w + c1.w;
                    w1.x += a2.x + c2.x; w1.y += a2.y + c2.y;
                    w1.z += a2.z + c2.z; w1.w += a2.w + c2.w;
                }
                qb = pack8(w0, w1);
            }
            *reinterpret_cast<uint4*>(&Bs[rr * STRH + cg]) = qb;
        }
        __syncthreads();
#pragma unroll
        for (int ks = 0; ks < 2; ks++) {
            const int kb = ks << 4;
            uint32_t af[2][4];
#pragma unroll
            for (int mt = 0; mt < 2; mt++) {
                const int r = wm * 32 + mt * 16 + g4;
                const int base = r * STRH + kb + 2 * t4;
                af[mt][0] = *reinterpret_cast<const uint32_t*>(&As[base]);
                af[mt][1] = *reinterpret_cast<const uint32_t*>(&As[base + 8 * STRH]);
                af[mt][2] = *reinterpret_cast<const uint32_t*>(&As[base + 8]);
                af[mt][3] = *reinterpret_cast<const uint32_t*>(&As[base + 8 * STRH + 8]);
            }
#pragma unroll
            for (int nt = 0; nt < 8; nt++) {
                const int n = wn * 64 + nt * 8 + g4;
                const int bb = n * STRH + kb + 2 * t4;
                const uint32_t b0 = *reinterpret_cast<const uint32_t*>(&Bs[bb]);
                const uint32_t b1 = *reinterpret_cast<const uint32_t*>(&Bs[bb + 8]);
                mma_f16(acc[0][nt], af[0], b0, b1);
                mma_f16(acc[1][nt], af[1], b0, b1);
            }
        }
    }
#pragma unroll
    for (int mt = 0; mt < 2; mt++) {
#pragma unroll
        for (int h = 0; h < 2; h++) {
            const int gr = row0 + wm * 32 + mt * 16 + g4 + h * 8;
            if (gr >= nrows) continue;
            const int ro = rows ? __ldg(&rows[gr]) : gr;
#pragma unroll
            for (int nt = 0; nt < 8; nt++) {
                const int col = col0 + wn * 64 + nt * 8 + t4 * 2;
                float2 v = make_float2(acc[mt][nt][h * 2 + 0], acc[mt][nt][h * 2 + 1]);
                __half2 hv = __float22half2_rn(v);
                *reinterpret_cast<__half2*>(C + (size_t)ro * ldC + col) = hv;
            }
        }
    }
}

// indexed projections: fused 3 (act/res/time), grid (2, maxRowT, 3)
struct IdxP { const float* A; const float* B; __half* C; int K;
              const int* rows; const int* cntp; };
struct IdxP3 { IdxP d[3]; };
__global__ void __launch_bounds__(256) gemm_proj3(IdxP3 g) {
    const IdxP d = g.d[blockIdx.z];
    const int nrows = *d.cntp;
    const int row0 = blockIdx.y * 128;
    if (row0 >= nrows) return;
    __shared__ __align__(16) __half As[128 * STRH];
    __shared__ __align__(16) __half Bs[128 * STRH];
    gemm_core_f32(d.A, d.B, nullptr, nullptr, d.C,
                  nrows, d.K, 256, row0, blockIdx.x * 128, d.rows, As, Bs);
}

// batched weight folds: ONE launch, grid (2,2,12)
struct FoldDesc { const float* A; const float* B0; const float* B1;
                  const float* B2; __half* C; int ldC; };
struct Fold12 { FoldDesc d[12]; };
__global__ void __launch_bounds__(256) gemm_fold(Fold12 args) {
    __shared__ __align__(16) __half As[128 * STRH];
    __shared__ __align__(16) __half Bs[128 * STRH];
    const FoldDesc f = args.d[blockIdx.z];
    gemm_core_f32(f.A, f.B0, f.B1, f.B2, f.C,
                  256, 256, f.ldC, blockIdx.y * 128, blockIdx.x * 128, nullptr, As, Bs);
}

// batched transposes (9 in one launch)
struct TPArgs { const float* in[9]; float* out[9]; int kin[9]; };
__global__ void transpose9(TPArgs a) {
    int z = blockIdx.z, k = blockIdx.x, n = threadIdx.x;
    if (k < a.kin[z])
        a.out[z][(size_t)n * a.kin[z] + k] = a.in[z][(size_t)k * 256 + n];
}

// batched bias folds (6 in one launch)
struct FoldB { const float* b1; const float* b2; const float* b3;
               const float* B; const float* blin; float* out; };
struct FoldB6 { FoldB d[6]; };
__global__ void fold_b6(FoldB6 a) {
    const FoldB f = a.d[blockIdx.x];
    int j = threadIdx.x;
    float acc = f.blin[j];
    for (int k = 0; k < Hc; k++) {
        float bb = f.b1[k];
        if (f.b2) bb += f.b2[k];
        if (f.b3) bb += f.b3[k];
        acc = fmaf(bb, f.B[k * Hc + j], acc);
    }
    f.out[j] = acc;
}

// =====================================================================
// unified CSR build
// =====================================================================
__global__ void cnt5(const int* __restrict__ d0, const int* __restrict__ d1,
                     const int* __restrict__ d2, const int* __restrict__ d3,
                     const int* __restrict__ d4, int* __restrict__ cnt) {
    int i = blockIdx.x * blockDim.x + threadIdx.x;
    if (i >= 5 * EE) return;
    int r = i / EE, e = i - r * EE;
    const int* dp; int base;
    switch (r) {
        case 0: dp = d0; base = B_F;  break;
        case 1: dp = d1; base = B_RA; break;
        case 2: dp = d2; base = B_TA; break;
        case 3: dp = d3; base = B_AR; break;
        default: dp = d4; base = B_AT; break;
    }
    atomicAdd(&cnt[base + dp[e]], 1);
}
__global__ void scan1(const int* __restrict__ cnt, int* __restrict__ off,
                      int* __restrict__ bsum, int N) {
    __shared__ int sh[1024];
    int i = blockIdx.x * 1024 + threadIdx.x;
    int x = (i < N) ? cnt[i] : 0;
    sh[threadIdx.x] = x;
    __syncthreads();
    for (int d = 1; d < 1024; d <<= 1) {
        int t = (threadIdx.x >= d) ? sh[threadIdx.x - d] : 0;
        __syncthreads();
        sh[threadIdx.x] += t;
        __syncthreads();
    }
    int incl = sh[threadIdx.x];
    if (i < N) off[i] = incl - x;
    if (threadIdx.x == 1023) bsum[blockIdx.x] = incl;
}
__global__ void scan2(int* __restrict__ bsum, int B) {
    __shared__ int sh[1024];
    int t = threadIdx.x;
    int x = (t < B) ? bsum[t] : 0;
    sh[t] = x;
    __syncthreads();
    for (int d = 1; d < 1024; d <<= 1) {
        int v = (t >= d) ? sh[t - d] : 0;
        __syncthreads();
        sh[t] += v;
        __syncthreads();
    }
    if (t < B) bsum[t] = sh[t] - x;
}
__global__ void scan3(int* __restrict__ off, const int* __restrict__ bsum,
                      int N, int total) {
    int i = blockIdx.x * blockDim.x + threadIdx.x;
    if (i < N) off[i] += bsum[i >> 10];
    if (i == 0) off[N] = total;
}
__global__ void fill5(const int* __restrict__ s0, const int* __restrict__ d0,
                      const int* __restrict__ s1, const int* __restrict__ d1,
                      const int* __restrict__ s2, const int* __restrict__ d2,
                      const int* __restrict__ s3, const int* __restrict__ d3,
                      const int* __restrict__ s4, const int* __restrict__ d4,
                      int* __restrict__ cur, int* __restrict__ idx) {
    int i = blockIdx.x * blockDim.x + threadIdx.x;
    if (i >= 5 * EE) return;
    int r = i / EE, e = i - r * EE;
    const int *sp, *dp; int base;
    switch (r) {
        case 0: sp = s0; dp = d0; base = B_F;  break;
        case 1: sp = s1; dp = d1; base = B_RA; break;
        case 2: sp = s2; dp = d2; base = B_TA; break;
        case 3: sp = s3; dp = d3; base = B_AR; break;
        default: sp = s4; dp = d4; base = B_AT; break;
    }
    int p = atomicAdd(&cur[base + dp[e]], 1);
    idx[p] = sp[e];
}

// =====================================================================
// frontier flags: last -> A1/R1/T1 -> Pa/Pr/Pt -> compact lists
// =====================================================================
__global__ void flag_last(const int* __restrict__ last, int* __restrict__ fLast,
                          int* __restrict__ fA1) {
    int g = blockIdx.x * blockDim.x + threadIdx.x;
    if (g < GG) { int n = __ldg(&last[g]); fLast[n] = 1; fA1[n] = 1; }
}
// pass 1: sources of edges into last-set (reads fLast only)
__global__ void prop1(const int* __restrict__ sf, const int* __restrict__ df,
                      const int* __restrict__ sra, const int* __restrict__ dra,
                      const int* __restrict__ sta, const int* __restrict__ dta,
                      const int* __restrict__ fLast,
                      int* __restrict__ fA1, int* __restrict__ fR1,
                      int* __restrict__ fT1) {
    int i = blockIdx.x * blockDim.x + threadIdx.x;
    if (i >= 3 * EE) return;
    int r = i / EE, e = i - r * EE;
    if (r == 0)      { if (__ldg(&fLast[df[e]]))  fA1[sf[e]]  = 1; }
    else if (r == 1) { if (__ldg(&fLast[dra[e]])) fR1[sra[e]] = 1; }
    else             { if (__ldg(&fLast[dta[e]])) fT1[sta[e]] = 1; }
}
// pass 2: P-row frontier (reads fA1/fR1/fT1 only; writes fPa/fPr/fPt)
__global__ void prop2(const int* __restrict__ sf, const int* __restrict__ df,
                      const int* __restrict__ sra, const int* __restrict__ dra,
                      const int* __restrict__ sta, const int* __restrict__ dta,
                      const int* __restrict__ sar, const int* __restrict__ dar,
                      const int* __restrict__ sat, const int* __restrict__ dat,
                      const int* __restrict__ fA1, const int* __restrict__ fR1,
                      const int* __restrict__ fT1,
                      int* __restrict__ fPa, int* __restrict__ fPr,
                      int* __restrict__ fPt) {
    int i = blockIdx.x * blockDim.x + threadIdx.x;
    if (i >= 5 * EE) return;
    int r = i / EE, e = i - r * EE;
    switch (r) {
        case 0: if (__ldg(&fA1[df[e]]))  fPa[sf[e]]  = 1; break;
        case 1: if (__ldg(&fA1[dra[e]])) fPr[sra[e]] = 1; break;
        case 2: if (__ldg(&fA1[dta[e]])) fPt[sta[e]] = 1; break;
        case 3: if (__ldg(&fR1[dar[e]])) fPa[sar[e]] = 1; break;
        default: if (__ldg(&fT1[dat[e]])) fPa[sat[e]] = 1; break;
    }
}
// compact all 6 flag arrays into lists (order-independent consumers)
__global__ void compact6(int* __restrict__ ib2) {
    int i = blockIdx.x * blockDim.x + threadIdx.x;
    if (i >= 640000) return;
    int reg, node; size_t fof, lof;
    if (i < 200000)      { reg = 0; node = i;          fof = F_A1; lof = L_A1; }
    else if (i < 220000) { reg = 1; node = i - 200000; fof = F_R1; lof = L_R1; }
    else if (i < 320000) { reg = 2; node = i - 220000; fof = F_T1; lof = L_T1; }
    else if (i < 520000) { reg = 3; node = i - 320000; fof = F_PA; lof = L_PA; }
    else if (i < 540000) { reg = 4; node = i - 520000; fof = F_PR; lof = L_PR; }
    else                 { reg = 5; node = i - 540000; fof = F_PT; lof = L_PT; }
    if (ib2[fof + node]) {
        int p = atomicAdd(&ib2[CTRS + reg], 1);
        ib2[lof + p] = node;
    }
}

// =====================================================================
// gathers
// =====================================================================
__device__ __forceinline__ void accum_rel(const __half* __restrict__ base, int stride,
                                          const int* __restrict__ off,
                                          const int* __restrict__ idx,
                                          int w, int lane, float* a) {
    int se = (lane < 2) ? __ldg(&off[w + lane]) : 0;
    int s = __shfl_sync(0xffffffffu, se, 0);
    int e = __shfl_sync(0xffffffffu, se, 1);
    if (e <= s) return;
    float sc = 1.f / (float)(e - s);
    float m[8] = {0.f, 0.f, 0.f, 0.f, 0.f, 0.f, 0.f, 0.f};
    for (int p = s; p < e; p++) {
        int sn = __ldg(&idx[p]);
        uint4 q = *reinterpret_cast<const uint4*>(base + (size_t)sn * stride + lane * 8);
        float f[8];
        h8_to_f8(q, f);
#pragma unroll
        for (int j = 0; j < 8; j++) m[j] += f[j];
    }
#pragma unroll
    for (int j = 0; j < 8; j++) a[j] += m[j] * sc;
}

// layer-0 gather restricted to frontier lists
__global__ void __launch_bounds__(256) gather_idx(
        const __half* __restrict__ Pa, const __half* __restrict__ Pr,
        const __half* __restrict__ Pt,
        const int* __restrict__ off, const int* __restrict__ idx,
        const int* __restrict__ ib2,
        __half* __restrict__ A, __half* __restrict__ R, __half* __restrict__ T) {
    int w = (blockIdx.x * 256 + threadIdx.x) >> 5;
    int lane = threadIdx.x & 31;
    const int cA = __ldg(&ib2[CTRS + 0]);
    const int cR = __ldg(&ib2[CTRS + 1]);
    const int cT = __ldg(&ib2[CTRS + 2]);
    float a[8];
    if (w < cA) {
        int u = __ldg(&ib2[L_A1 + w]);
        h8_to_f8(*reinterpret_cast<const uint4*>(Pa + (size_t)u * 1024 + 768 + lane * 8), a);
        accum_rel(Pa, 1024, off + B_F,  idx, u, lane, a);
        accum_rel(Pr, 512,  off + B_RA, idx, u, lane, a);
        accum_rel(Pt, 512,  off + B_TA, idx, u, lane, a);
#pragma unroll
        for (int j = 0; j < 8; j++) a[j] = fmaxf(a[j], 0.f);
        *reinterpret_cast<uint4*>(A + (size_t)u * 256 + lane * 8) = f8_to_h8(a);
    } else if (w < cA + cR) {
        int v = __ldg(&ib2[L_R1 + (w - cA)]);
        h8_to_f8(*reinterpret_cast<const uint4*>(Pr + (size_t)v * 512 + 256 + lane * 8), a);
        accum_rel(Pa + 256, 1024, off + B_AR, idx, v, lane, a);
#pragma unroll
        for (int j = 0; j < 8; j++) a[j] = fmaxf(a[j], 0.f);
        *reinterpret_cast<uint4*>(R + (size_t)v * 256 + lane * 8) = f8_to_h8(a);
    } else if (w < cA + cR + cT) {
        int v = __ldg(&ib2[L_T1 + (w - cA - cR)]);
        h8_to_f8(*reinterpret_cast<const uint4*>(Pt + (size_t)v * 512 + 256 + lane * 8), a);
        accum_rel(Pa + 512, 1024, off + B_AT, idx, v, lane, a);
#pragma unroll
        for (int j = 0; j < 8; j++) a[j] = fmaxf(a[j], 0.f);
        *reinterpret_cast<uint4*>(T + (size_t)v * 256 + lane * 8) = f8_to_h8(a);
    }
}

// layer-1 pooled gather: X2[512, 1024] = [mf(a1)|mra(r1)|mta(t1)|a1 self]
__global__ void __launch_bounds__(256) gather_pool(
        const __half* __restrict__ A, const __half* __restrict__ R,
        const __half* __restrict__ T,
        const int* __restrict__ off, const int* __restrict__ idx,
        const int* __restrict__ last, __half* __restrict__ X2) {
    int w = (blockIdx.x * 256 + threadIdx.x) >> 5;
    int lane = threadIdx.x & 31;
    if (w >= 4 * GG) return;
    int g = w >> 2, s = w & 3;
    int nid = __ldg(&last[g]);
    float a[8] = {0.f, 0.f, 0.f, 0.f, 0.f, 0.f, 0.f, 0.f};
    if (s == 0)      accum_rel(A, 256, off + B_F,  idx, nid, lane, a);
    else if (s == 1) accum_rel(R, 256, off + B_RA, idx, nid, lane, a);
    else if (s == 2) accum_rel(T, 256, off + B_TA, idx, nid, lane, a);
    else h8_to_f8(*reinterpret_cast<const uint4*>(A + (size_t)nid * 256 + lane * 8), a);
    *reinterpret_cast<uint4*>(X2 + (size_t)g * 1024 + s * 256 + lane * 8) = f8_to_h8(a);
}

// =====================================================================
// misc kernels
// =====================================================================
__global__ void last_k(const int* __restrict__ batch, int* __restrict__ last, int N) {
    int i = blockIdx.x * blockDim.x + threadIdx.x;
    if (i < N) {
        if (i == N - 1 || batch[i + 1] != batch[i]) last[batch[i]] = i;
    }
}

__global__ void heads_k(const __half* __restrict__ a2,
                        const float* __restrict__ Wo, const float* __restrict__ bo,
                        const float* __restrict__ Wt, const float* __restrict__ bt,
                        const float* __restrict__ Wrm, const float* __restrict__ brm,
                        float* __restrict__ out) {
    int g = blockIdx.x;
    __shared__ float p[Hc];
    const __half* row = a2 + (size_t)g * Hc;
    for (int k = threadIdx.x; k < Hc; k += blockDim.x) p[k] = __half2float(row[k]);
    __syncthreads();
    int j = threadIdx.x;
    if (j < CC) {
        float acc = bo[j];
        for (int k = 0; k < Hc; k++) acc = fmaf(p[k], Wo[k * CC + j], acc);
        out[g * CC + j] = acc;
    } else if (j == CC) {
        float acc = bt[0];
        for (int k = 0; k < Hc; k++) acc = fmaf(p[k], Wt[k], acc);
        out[GG * CC + g] = acc;
    } else if (j == CC + 1) {
        float acc = brm[0];
        for (int k = 0; k < Hc; k++) acc = fmaf(p[k], Wrm[k], acc);
        out[GG * CC + GG + g] = acc;
    }
}

// =====================================================================
// host orchestration
// =====================================================================
extern "C" void kernel_launch(void* const* d_in, const int* in_sizes, int n_in,
                              void* d_out, int out_size) {
    float* buf = nullptr;
    cudaGetSymbolAddress((void**)&buf, g_buf);

    __half* A  = reinterpret_cast<__half*>(buf + OFF_A);
    __half* R  = reinterpret_cast<__half*>(buf + OFF_R);
    __half* T  = reinterpret_cast<__half*>(buf + OFF_T);
    __half* Pa = reinterpret_cast<__half*>(buf + OFF_PA);
    __half* Pr = reinterpret_cast<__half*>(buf + OFF_PR);
    __half* Pt = reinterpret_cast<__half*>(buf + OFF_PT);
    __half* X2 = Pr;
    __half* A2 = Pt;
    __half* WCh = reinterpret_cast<__half*>(buf + OFF_WC);
    __half* WB2 = WCh + 524288;
    float* BF  = buf + OFF_BF;
    float* WLT = buf + OFF_WLT;
    float* WPT = buf + OFF_WPT;
    int*   LAST = reinterpret_cast<int*>(buf + OFF_LAST);
    int*   IB   = reinterpret_cast<int*>(buf + OFF_INT);
    int*   IB2  = reinterpret_cast<int*>(buf + OFF_INT2);
    int* off  = IB + IO_OFFS;
    int* cnt  = IB + IO_CNT;
    int* bsum = IB + IO_BSUM;
    int* idx  = IB + IO_IDX;

    const float* x_act  = (const float*)d_in[0];
    const float* x_res  = (const float*)d_in[1];
    const float* x_time = (const float*)d_in[2];
    const int* src_f  = (const int*)d_in[3];
    const int* dst_f  = (const int*)d_in[4];
    const int* src_ar = (const int*)d_in[5];
    const int* dst_ar = (const int*)d_in[6];
    const int* src_ra = (const int*)d_in[7];
    const int* dst_ra = (const int*)d_in[8];
    const int* src_at = (const int*)d_in[9];
    const int* dst_at = (const int*)d_in[10];
    const int* src_ta = (const int*)d_in[11];
    const int* dst_ta = (const int*)d_in[12];
    const int* batch  = (const int*)d_in[13];

    int w = (in_sizes[14] <= 4) ? 15 : 14;
    const float* Wp_act = (const float*)d_in[w + 0];
    const float* Wp_res = (const float*)d_in[w + 1];
    const float* Wp_tim = (const float*)d_in[w + 2];
    const float* Wl     = (const float*)d_in[w + 3];
    const float* bl     = (const float*)d_in[w + 4];
    const float* Wr     = (const float*)d_in[w + 5];
    const float* Wlin   = (const float*)d_in[w + 6];
    const float* blin   = (const float*)d_in[w + 7];
    const float* Wo     = (const float*)d_in[w + 8];
    const float* bo     = (const float*)d_in[w + 9];
    const float* Wt     = (const float*)d_in[w + 10];
    const float* bt     = (const float*)d_in[w + 11];
    const float* Wrm    = (const float*)d_in[w + 12];
    const float* brm    = (const float*)d_in[w + 13];

    const size_t HH = 65536;  // 256*256

    // --- zero flags, counters, CSR counts, LAST ---
    cudaMemsetAsync(IB2, 0, 840000 * sizeof(int), 0);              // fLast..fPt
    cudaMemsetAsync(IB2 + CTRS, 0, 8 * sizeof(int), 0);
    cudaMemsetAsync(cnt, 0, CSR_N * sizeof(int), 0);
    cudaMemsetAsync(LAST, 0, GG * sizeof(int), 0);

    // --- fused transposes ---
    {
        TPArgs tp;
        tp.in[0] = Wp_act; tp.out[0] = WPT + 0;     tp.kin[0] = 64;
        tp.in[1] = Wp_res; tp.out[1] = WPT + 16384; tp.kin[1] = 32;
        tp.in[2] = Wp_tim; tp.out[2] = WPT + 24576; tp.kin[2] = 16;
        for (int i = 0; i < 6; i++) {
            tp.in[3 + i]  = Wlin + (size_t)i * HH;
            tp.out[3 + i] = WLT + (size_t)i * HH;
            tp.kin[3 + i] = 256;
        }
        transpose9<<<dim3(256, 1, 9), 256>>>(tp);
    }

    // --- fused weight folds: 8 (l=0) + 4 (l=1 concat-K) ---
    {
        Fold12 fa;
        {
            const float* lt0 = WLT + 0 * HH;
            const float* lt1 = WLT + 1 * HH;
            const float* lt2 = WLT + 2 * HH;
            __half* WCa = WCh;
            __half* WCr = WCa + 262144;
            __half* WCt = WCr + 131072;
            fa.d[0] = {lt0, Wl + 0 * HH, nullptr, nullptr, WCa + 0,      256};
            fa.d[1] = {lt1, Wl + 1 * HH, nullptr, nullptr, WCa + 65536,  256};
            fa.d[2] = {lt2, Wl + 3 * HH, nullptr, nullptr, WCa + 131072, 256};
            fa.d[3] = {lt0, Wr + 0 * HH, Wr + 2 * HH, Wr + 4 * HH, WCa + 196608, 256};
            fa.d[4] = {lt0, Wl + 2 * HH, nullptr, nullptr, WCr + 0,      256};
            fa.d[5] = {lt1, Wr + 1 * HH, nullptr, nullptr, WCr + 65536,  256};
            fa.d[6] = {lt0, Wl + 4 * HH, nullptr, nullptr, WCt + 0,      256};
            fa.d[7] = {lt2, Wr + 3 * HH, nullptr, nullptr, WCt + 65536,  256};
        }
        {
            const float* lt0 = WLT + 3 * HH;
            fa.d[8]  = {lt0, Wl + 5 * HH, nullptr, nullptr, WB2 + 0,   1024};
            fa.d[9]  = {lt0, Wl + 7 * HH, nullptr, nullptr, WB2 + 256, 1024};
            fa.d[10] = {lt0, Wl + 9 * HH, nullptr, nullptr, WB2 + 512, 1024};
            fa.d[11] = {lt0, Wr + 5 * HH, Wr + 7 * HH, Wr + 9 * HH, WB2 + 768, 1024};
        }
        gemm_fold<<<dim3(2, 2, 12), 256>>>(fa);

        FoldB6 fb;
        for (int l = 0; l < 2; l++) {
            fb.d[l * 3 + 0] = {bl + (l * 5 + 0) * 256, bl + (l * 5 + 2) * 256,
                               bl + (l * 5 + 4) * 256, Wlin + (size_t)(l * 3 + 0) * HH,
                               blin + (l * 3 + 0) * 256, BF + l * 768 + 0};
            fb.d[l * 3 + 1] = {bl + (l * 5 + 1) * 256, nullptr, nullptr,
                               Wlin + (size_t)(l * 3 + 1) * HH,
                               blin + (l * 3 + 1) * 256, BF + l * 768 + 256};
            fb.d[l * 3 + 2] = {bl + (l * 5 + 3) * 256, nullptr, nullptr,
                               Wlin + (size_t)(l * 3 + 2) * HH,
                               blin + (l * 3 + 2) * 256, BF + l * 768 + 512};
        }
        fold_b6<<<6, 256>>>(fb);
    }

    // --- unified CSR build ---
    {
        int nb = (5 * EE + 255) / 256;
        cnt5<<<nb, 256>>>(dst_f, dst_ra, dst_ta, dst_ar, dst_at, cnt);
        int sb = (CSR_N + 1023) / 1024;
        scan1<<<sb, 1024>>>(cnt, off, bsum, CSR_N);
        scan2<<<1, 1024>>>(bsum, sb);
        scan3<<<(CSR_N + 255) / 256, 256>>>(off, bsum, CSR_N, 5 * EE);
        cudaMemcpyAsync(cnt, off, CSR_N * sizeof(int), cudaMemcpyDeviceToDevice, 0);
        fill5<<<nb, 256>>>(src_f, dst_f, src_ra, dst_ra, src_ta, dst_ta,
                           src_ar, dst_ar, src_at, dst_at, cnt, idx);
    }

    // --- pooled indices + frontier flags + lists ---
    last_k<<<(NACT + 255) / 256, 256>>>(batch, LAST, NACT);
    flag_last<<<(GG + 255) / 256, 256>>>(LAST, IB2 + F_LAST, IB2 + F_A1);
    prop1<<<(3 * EE + 255) / 256, 256>>>(src_f, dst_f, src_ra, dst_ra,
                                         src_ta, dst_ta, IB2 + F_LAST,
                                         IB2 + F_A1, IB2 + F_R1, IB2 + F_T1);
    cudaMemcpyAsync(IB2 + F_PA, IB2 + F_A1, NACT  * sizeof(int),
                    cudaMemcpyDeviceToDevice, 0);
    cudaMemcpyAsync(IB2 + F_PR, IB2 + F_R1, NRES  * sizeof(int),
                    cudaMemcpyDeviceToDevice, 0);
    cudaMemcpyAsync(IB2 + F_PT, IB2 + F_T1, NTIME * sizeof(int),
                    cudaMemcpyDeviceToDevice, 0);
    prop2<<<(5 * EE + 255) / 256, 256>>>(src_f, dst_f, src_ra, dst_ra,
                                         src_ta, dst_ta, src_ar, dst_ar,
                                         src_at, dst_at,
                                         IB2 + F_A1, IB2 + F_R1, IB2 + F_T1,
                                         IB2 + F_PA, IB2 + F_PR, IB2 + F_PT);
    compact6<<<(640000 + 255) / 256, 256>>>(IB2);

    // --- frontier-restricted projections (fused 3) ---
    {
        IdxP3 p;
        p.d[0] = {x_act,  WPT + 0,     A, 64, IB2 + L_PA, IB2 + CTRS + 3};
        p.d[1] = {x_res,  WPT + 16384, R, 32, IB2 + L_PR, IB2 + CTRS + 4};
        p.d[2] = {x_time, WPT + 24576, T, 16, IB2 + L_PT, IB2 + CTRS + 5};
        gemm_proj3<<<dim3(2, (NACT + 127) / 128, 3), 256>>>(p);
    }

    // --- layer 0: frontier-indexed wide GEMM (fused 3) + frontier gather ---
    {
        __half* WCa = WCh;
        __half* WCr = WCa + 262144;
        __half* WCt = WCr + 131072;
        IdxG3 g;
        g.d[0] = {A, WCa, BF + 0,   768, Pa, 1024, 8, IB2 + L_PA, IB2 + CTRS + 3};
        g.d[1] = {R, WCr, BF + 256, 256, Pr, 512,  4, IB2 + L_PR, IB2 + CTRS + 4};
        g.d[2] = {T, WCt, BF + 512, 256, Pt, 512,  4, IB2 + L_PT, IB2 + CTRS + 5};
        gemm_idx3<<<dim3(8, (NACT + 127) / 128, 3), 256>>>(g);

        const int gblocks = ((NACT + NRES + NTIME) * 32 + 255) / 256;
        gather_idx<<<gblocks, 256>>>(Pa, Pr, Pt, off, idx, IB2, A, R, T);
    }

    // --- layer 1: pooled aggregate-then-project (512 rows) ---
    {
        gather_pool<<<(4 * GG * 32 + 255) / 256, 256>>>(A, R, T, off, idx, LAST, X2);
        Gemm3 g;
        g.d[0] = {X2, WB2, BF + 768, A2, 0, GG, 256, 2, 1024, 1};
        g.d[1] = g.d[0]; g.d[2] = g.d[0];
        g.n0 = 8; g.n01 = 8;
        gemm_fast3<<<8, 256>>>(g);
    }

    // --- heads ---
    heads_k<<<GG, 64>>>(A2, Wo, bo, Wt, bt, Wrm, brm, (float*)d_out);
}

// round 15
// speedup vs baseline: 38.7715x; 1.3880x over previous
#include <cuda_runtime.h>
#include <cuda_fp16.h>
#include <cstdint>
#include <cstddef>

#define Hc    256
#define CC    50
#define GG    512
#define NACT  200000
#define NRES  20000
#define NTIME 100000
#define EE    400000

// ---------------- scratch layout (float units) ----------------
static constexpr size_t OFF_A    = 0;            // 200000*256 h
static constexpr size_t OFF_R    = 25600000;     // 20000*256 h
static constexpr size_t OFF_T    = 28160000;     // 100000*256 h
static constexpr size_t OFF_PA   = 40960000;     // 200000*1024 h [f|ar|at|self]
static constexpr size_t OFF_PR   = 143360000;    // 20000*512 h   (reused: X2)
static constexpr size_t OFF_PT   = 148480000;    // 100000*512 h  (reused: A2)
static constexpr size_t OFF_WC   = 174080000;    // folded weights fp16
static constexpr size_t OFF_BF   = 175128576;    // 2*3*256 f32
static constexpr size_t OFF_WLT  = 175130112;    // 6*65536 f32 Wlin^T
static constexpr size_t OFF_WPT  = 175523328;    // 256*(64+32+16) f32 Wp^T
static constexpr size_t OFF_LAST = 175552000;    // 512 ints
static constexpr size_t OFF_INT  = 175552512;    // CSR int scratch
static constexpr size_t OFF_INT2 = 178993600;    // frontier int scratch
static constexpr size_t TOTALF   = 181593700;

// unified CSR (ints, relative to OFF_INT)
static constexpr int CSR_N = 720000;
static constexpr int B_F  = 0;
static constexpr int B_RA = 200000;
static constexpr int B_TA = 400000;
static constexpr int B_AR = 600000;
static constexpr int B_AT = 620000;
static constexpr size_t IO_OFFS = 0;         // 720001
static constexpr size_t IO_CNT  = 720004;    // 720000
static constexpr size_t IO_BSUM = 1440004;   // 1024
static constexpr size_t IO_IDX  = 1441028;   // 2,000,000

// frontier region (ints, relative to OFF_INT2)
static constexpr size_t F_LAST = 0;          // 200000
static constexpr size_t F_A1   = 200000;     // 200000
static constexpr size_t F_R1   = 400000;     // 20000
static constexpr size_t F_T1   = 420000;     // 100000
static constexpr size_t F_LF   = 520000;     // 200000 (act: f-msg rows)
static constexpr size_t F_LAR  = 720000;     // 200000 (act: ar-msg rows)
static constexpr size_t F_LAT  = 920000;     // 200000 (act: at-msg rows)
static constexpr size_t F_LRA  = 1120000;    // 20000  (res: ra-msg rows)
static constexpr size_t F_LTA  = 1140000;    // 100000 (time: ta-msg rows)
static constexpr size_t FLAGS_END = 1240000;
static constexpr size_t L_A1   = 1240000;    // 200000
static constexpr size_t L_R1   = 1440000;    // 20000
static constexpr size_t L_T1   = 1460000;    // 100000
static constexpr size_t L_LF   = 1560000;    // 200000
static constexpr size_t L_LAR  = 1760000;    // 200000
static constexpr size_t L_LAT  = 1960000;    // 200000
static constexpr size_t L_LRA  = 2160000;    // 20000
static constexpr size_t L_LTA  = 2180000;    // 100000
static constexpr size_t L_PA   = 2280000;    // 200000
static constexpr size_t L_PR   = 2480000;    // 20000
static constexpr size_t L_PT   = 2500000;    // 100000
static constexpr size_t CTRS   = 2600000;    // 16
// counters: 0:A1 1:R1 2:T1 3:PA 4:PR 5:PT 6:LF 7:LAR 8:LAT 9:LRA 10:LTA

__device__ float g_buf[TOTALF];

// =====================================================================
// helpers
// =====================================================================
__device__ __forceinline__ void mma_f16(float* d, const uint32_t* a,
                                        uint32_t b0, uint32_t b1) {
    asm volatile(
        "mma.sync.aligned.m16n8k16.row.col.f32.f16.f16.f32 "
        "{%0,%1,%2,%3}, {%4,%5,%6,%7}, {%8,%9}, {%0,%1,%2,%3};"
        : "+f"(d[0]), "+f"(d[1]), "+f"(d[2]), "+f"(d[3])
        : "r"(a[0]), "r"(a[1]), "r"(a[2]), "r"(a[3]), "r"(b0), "r"(b1));
}
__device__ __forceinline__ void ldsm4(uint32_t* r, uint32_t addr) {
    asm volatile("ldmatrix.sync.aligned.m8n8.x4.shared.b16 {%0,%1,%2,%3}, [%4];"
                 : "=r"(r[0]), "=r"(r[1]), "=r"(r[2]), "=r"(r[3]) : "r"(addr));
}
__device__ __forceinline__ void cp16(uint32_t dst, const void* src, int szbytes) {
    asm volatile("cp.async.cg.shared.global [%0], [%1], 16, %2;"
                 :: "r"(dst), "l"(src), "r"(szbytes));
}
#define CP_COMMIT() asm volatile("cp.async.commit_group;" ::: "memory")
template <int N>
__device__ __forceinline__ void cp_wait() {
    asm volatile("cp.async.wait_group %0;" :: "n"(N) : "memory");
}
__device__ __forceinline__ uint32_t saddr(const void* p) {
    return static_cast<uint32_t>(__cvta_generic_to_shared(p));
}
__device__ __forceinline__ uint32_t packh2(float x, float y) {
    __half2 h = __float22half2_rn(make_float2(x, y));
    return *reinterpret_cast<uint32_t*>(&h);
}
__device__ __forceinline__ uint4 pack8(float4 a, float4 b) {
    return make_uint4(packh2(a.x, a.y), packh2(a.z, a.w),
                      packh2(b.x, b.y), packh2(b.z, b.w));
}
__device__ __forceinline__ void h8_to_f8(uint4 q, float* f) {
    const __half2* h = reinterpret_cast<const __half2*>(&q);
#pragma unroll
    for (int i = 0; i < 4; i++) {
        float2 t = __half22float2(h[i]);
        f[2 * i] = t.x; f[2 * i + 1] = t.y;
    }
}
__device__ __forceinline__ uint4 f8_to_h8(const float* f) {
    return make_uint4(packh2(f[0], f[1]), packh2(f[2], f[3]),
                      packh2(f[4], f[5]), packh2(f[6], f[7]));
}

#define STRH 40
#define NOBIAS (1 << 30)

// =====================================================================
// fused fp16 GEMM (pooled layer-1): up to 3 sub-GEMMs, runtime K, relu
// =====================================================================
struct GemmDesc {
    const __half* A; const __half* B; const float* bias;
    __half* C; int bstart; int Nrow; int ldC; int colT; int K; int relu;
};
struct Gemm3 { GemmDesc d[3]; int n0, n01; };

__global__ void __launch_bounds__(256) gemm_fast3(Gemm3 g) {
    __shared__ __align__(16) __half As[2][128 * STRH];
    __shared__ __align__(16) __half Bs[2][128 * STRH];
    const int id = blockIdx.x;
    const int zi = (id < g.n0) ? 0 : ((id < g.n01) ? 1 : 2);
    const int rid = id - ((zi == 0) ? 0 : ((zi == 1) ? g.n0 : g.n01));
    const GemmDesc d = g.d[zi];
    const int row0 = (rid / d.colT) * 128;
    const int col0 = (rid % d.colT) * 128;
    const int Nrow = d.Nrow;
    const int K = d.K;
    const __half* __restrict__ A = d.A;
    const __half* __restrict__ B = d.B;

    const int tid  = threadIdx.x;
    const int lane = tid & 31;
    const int wid  = tid >> 5;
    const int wm   = wid & 3;
    const int wn   = wid >> 2;
    const int t4   = lane & 3;
    const int g4   = lane >> 2;
    const int arow = lane & 15;
    const int acol = (lane >> 4) << 3;
    const int brow = (lane & 7) + ((lane >> 4) << 3);
    const int bcol = ((lane >> 3) & 1) << 3;

    float acc[2][8][4];
#pragma unroll
    for (int mt = 0; mt < 2; mt++)
#pragma unroll
        for (int nt = 0; nt < 8; nt++)
#pragma unroll
            for (int q = 0; q < 4; q++) acc[mt][nt][q] = 0.f;

    auto stage = [&](int c, int b) {
        const int k0 = c << 5;
#pragma unroll
        for (int it = 0; it < 2; it++) {
            const int i  = tid + it * 256;
            const int rr = i >> 2;
            const int sg = (i & 3) << 3;
            const int gr = row0 + rr;
            const int grc = gr < Nrow ? gr : (Nrow - 1);
            cp16(saddr(&As[b][rr * STRH + sg]),
                 A + (size_t)grc * K + k0 + sg, gr < Nrow ? 16 : 0);
            cp16(saddr(&Bs[b][rr * STRH + sg]),
                 B + (size_t)(col0 + rr) * K + k0 + sg, 16);
        }
    };

    stage(0, 0);
    CP_COMMIT();
    const int nc = K >> 5;
#pragma unroll 1
    for (int c = 0; c < nc; c++) {
        const int cb = c & 1;
        if (c + 1 < nc) { stage(c + 1, cb ^ 1); CP_COMMIT(); cp_wait<1>(); }
        else            { cp_wait<0>(); }
        __syncthreads();
#pragma unroll
        for (int ks = 0; ks < 2; ks++) {
            const int kb = ks << 4;
            uint32_t af[2][4];
#pragma unroll
            for (int mt = 0; mt < 2; mt++)
                ldsm4(af[mt], saddr(&As[cb][(wm * 32 + mt * 16 + arow) * STRH + kb + acol]));
            uint32_t bf[4][4];
#pragma unroll
            for (int p = 0; p < 4; p++)
                ldsm4(bf[p], saddr(&Bs[cb][(wn * 64 + p * 16 + brow) * STRH + kb + bcol]));
#pragma unroll
            for (int nt = 0; nt < 8; nt++) {
                const uint32_t b0 = bf[nt >> 1][(nt & 1) * 2];
                const uint32_t b1 = bf[nt >> 1][(nt & 1) * 2 + 1];
                mma_f16(acc[0][nt], af[0], b0, b1);
                mma_f16(acc[1][nt], af[1], b0, b1);
            }
        }
        __syncthreads();
    }
#pragma unroll
    for (int mt = 0; mt < 2; mt++) {
#pragma unroll
        for (int h = 0; h < 2; h++) {
            const int gr = row0 + wm * 32 + mt * 16 + g4 + h * 8;
            if (gr >= Nrow) continue;
#pragma unroll
            for (int nt = 0; nt < 8; nt++) {
                const int col = col0 + wn * 64 + nt * 8 + t4 * 2;
                float2 v = make_float2(acc[mt][nt][h * 2 + 0], acc[mt][nt][h * 2 + 1]);
                if (col >= d.bstart) {
                    v.x += __ldg(&d.bias[col - d.bstart]);
                    v.y += __ldg(&d.bias[col - d.bstart + 1]);
                }
                if (d.relu) { v.x = fmaxf(v.x, 0.f); v.y = fmaxf(v.y, 0.f); }
                __half2 hv = __float22half2_rn(v);
                *reinterpret_cast<__half2*>(d.C + (size_t)gr * d.ldC + col) = hv;
            }
        }
    }
}

// =====================================================================
// INDEXED section GEMM: 8 sub-GEMMs (one per P section), K=256,
// 256 output cols each (colT=2), rows via list, device row count.
// =====================================================================
struct IdxG { const __half* A; const __half* B; const float* bias; int bstart;
              __half* C; int ldC; const int* rows; const int* cntp; };
struct IdxG8 { IdxG d[8]; };

__global__ void __launch_bounds__(256) gemm_sec8(IdxG8 g) {
    const IdxG d = g.d[blockIdx.z];
    const int nrows = *d.cntp;
    const int row0 = blockIdx.y * 128;
    if (row0 >= nrows) return;
    __shared__ __align__(16) __half As[2][128 * STRH];
    __shared__ __align__(16) __half Bs[2][128 * STRH];
    const int col0 = blockIdx.x * 128;
    const __half* __restrict__ A = d.A;
    const __half* __restrict__ B = d.B;
    const int* __restrict__ rows = d.rows;
    constexpr int K = 256;

    const int tid  = threadIdx.x;
    const int lane = tid & 31;
    const int wid  = tid >> 5;
    const int wm   = wid & 3;
    const int wn   = wid >> 2;
    const int t4   = lane & 3;
    const int g4   = lane >> 2;
    const int arow = lane & 15;
    const int acol = (lane >> 4) << 3;
    const int brow = (lane & 7) + ((lane >> 4) << 3);
    const int bcol = ((lane >> 3) & 1) << 3;

    float acc[2][8][4];
#pragma unroll
    for (int mt = 0; mt < 2; mt++)
#pragma unroll
        for (int nt = 0; nt < 8; nt++)
#pragma unroll
            for (int q = 0; q < 4; q++) acc[mt][nt][q] = 0.f;

    auto stage = [&](int c, int b) {
        const int k0 = c << 5;
#pragma unroll
        for (int it = 0; it < 2; it++) {
            const int i  = tid + it * 256;
            const int rr = i >> 2;
            const int sg = (i & 3) << 3;
            const int gr = row0 + rr;
            const int ri = __ldg(&rows[gr < nrows ? gr : (nrows - 1)]);
            cp16(saddr(&As[b][rr * STRH + sg]),
                 A + (size_t)ri * K + k0 + sg, gr < nrows ? 16 : 0);
            cp16(saddr(&Bs[b][rr * STRH + sg]),
                 B + (size_t)(col0 + rr) * K + k0 + sg, 16);
        }
    };

    stage(0, 0);
    CP_COMMIT();
    constexpr int nc = K >> 5;
#pragma unroll 1
    for (int c = 0; c < nc; c++) {
        const int cb = c & 1;
        if (c + 1 < nc) { stage(c + 1, cb ^ 1); CP_COMMIT(); cp_wait<1>(); }
        else            { cp_wait<0>(); }
        __syncthreads();
#pragma unroll
        for (int ks = 0; ks < 2; ks++) {
            const int kb = ks << 4;
            uint32_t af[2][4];
#pragma unroll
            for (int mt = 0; mt < 2; mt++)
                ldsm4(af[mt], saddr(&As[cb][(wm * 32 + mt * 16 + arow) * STRH + kb + acol]));
            uint32_t bf[4][4];
#pragma unroll
            for (int p = 0; p < 4; p++)
                ldsm4(bf[p], saddr(&Bs[cb][(wn * 64 + p * 16 + brow) * STRH + kb + bcol]));
#pragma unroll
            for (int nt = 0; nt < 8; nt++) {
                const uint32_t b0 = bf[nt >> 1][(nt & 1) * 2];
                const uint32_t b1 = bf[nt >> 1][(nt & 1) * 2 + 1];
                mma_f16(acc[0][nt], af[0], b0, b1);
                mma_f16(acc[1][nt], af[1], b0, b1);
            }
        }
        __syncthreads();
    }
#pragma unroll
    for (int mt = 0; mt < 2; mt++) {
#pragma unroll
        for (int h = 0; h < 2; h++) {
            const int gr = row0 + wm * 32 + mt * 16 + g4 + h * 8;
            if (gr >= nrows) continue;
            const int ro = __ldg(&rows[gr]);
#pragma unroll
            for (int nt = 0; nt < 8; nt++) {
                const int col = col0 + wn * 64 + nt * 8 + t4 * 2;
                float2 v = make_float2(acc[mt][nt][h * 2 + 0], acc[mt][nt][h * 2 + 1]);
                if (col >= d.bstart) {
                    v.x += __ldg(&d.bias[col - d.bstart]);
                    v.y += __ldg(&d.bias[col - d.bstart + 1]);
                }
                __half2 hv = __float22half2_rn(v);
                *reinterpret_cast<__half2*>(d.C + (size_t)ro * d.ldC + col) = hv;
            }
        }
    }
}

// =====================================================================
// GENERIC GEMM core (f32 A staged to fp16), optional row indexing
// =====================================================================
__device__ __forceinline__ void gemm_core_f32(
        const float* __restrict__ A,
        const float* __restrict__ B0s, const float* __restrict__ B1s,
        const float* __restrict__ B2s,
        __half* __restrict__ C,
        int nrows, int K, int ldC, int row0, int col0,
        const int* __restrict__ rows,
        __half* As, __half* Bs) {
    const int tid  = threadIdx.x;
    const int lane = tid & 31;
    const int wid  = tid >> 5;
    const int wm   = wid & 3;
    const int wn   = wid >> 2;
    const int g4   = lane >> 2;
    const int t4   = lane & 3;
    const bool has3 = (B1s != nullptr);

    float acc[2][8][4];
#pragma unroll
    for (int mt = 0; mt < 2; mt++)
#pragma unroll
        for (int nt = 0; nt < 8; nt++)
#pragma unroll
            for (int q = 0; q < 4; q++) acc[mt][nt][q] = 0.f;

    const int nc = (K + 31) >> 5;
    for (int c = 0; c < nc; c++) {
        const int k0 = c << 5;
        if (c) __syncthreads();
#pragma unroll
        for (int it = 0; it < 2; it++) {
            const int idx = tid + it * 256;
            const int rr  = idx >> 2;
            const int cg  = (idx & 3) << 3;
            const bool kok = (k0 + cg) < K;
            uint4 qa = make_uint4(0, 0, 0, 0);
            const int gr = row0 + rr;
            if (gr < nrows && kok) {
                const int ri = rows ? __ldg(&rows[gr]) : gr;
                const float* ap = A + (size_t)ri * K + k0 + cg;
                float4 v0 = *reinterpret_cast<const float4*>(ap);
                float4 v1 = *reinterpret_cast<const float4*>(ap + 4);
                qa = pack8(v0, v1);
            }
            *reinterpret_cast<uint4*>(&As[rr * STRH + cg]) = qa;
            uint4 qb = make_uint4(0, 0, 0, 0);
            if (kok) {
                const size_t bo = (size_t)(col0 + rr) * K + k0 + cg;
                float4 w0 = *reinterpret_cast<const float4*>(B0s + bo);
                float4 w1 = *reinterpret_cast<const float4*>(B0s + bo + 4);
                if (has3) {
                    float4 a1 = *reinterpret_cast<const float4*>(B1s + bo);
                    float4 a2 = *reinterpret_cast<const float4*>(B1s + bo + 4);
                    float4 c1 = *reinterpret_cast<const float4*>(B2s + bo);
                    float4 c2 = *reinterpret_cast<const float4*>(B2s + bo + 4);
                    w0.x += a1.x + c1.x; w0.y += a1.y + c1.y;
                    w0.z += a1.z + c1.z; w0.w += a1.w + c1.w;
                    w1.x += a2.x + c2.x; w1.y += a2.y + c2.y;
                    w1.z += a2.z + c2.z; w1.w += a2.w + c2.w;
                }
                qb = pack8(w0, w1);
            }
            *reinterpret_cast<uint4*>(&Bs[rr * STRH + cg]) = qb;
        }
        __syncthreads();
#pragma unroll
        for (int ks = 0; ks < 2; ks++) {
            const int kb = ks << 4;
            uint32_t af[2][4];
#pragma unroll
            for (int mt = 0; mt < 2; mt++) {
                const int r = wm * 32 + mt * 16 + g4;
                const int base = r * STRH + kb + 2 * t4;
                af[mt][0] = *reinterpret_cast<const uint32_t*>(&As[base]);
                af[mt][1] = *reinterpret_cast<const uint32_t*>(&As[base + 8 * STRH]);
                af[mt][2] = *reinterpret_cast<const uint32_t*>(&As[base + 8]);
                af[mt][3] = *reinterpret_cast<const uint32_t*>(&As[base + 8 * STRH + 8]);
            }
#pragma unroll
            for (int nt = 0; nt < 8; nt++) {
                const int n = wn * 64 + nt * 8 + g4;
                const int bb = n * STRH + kb + 2 * t4;
                const uint32_t b0 = *reinterpret_cast<const uint32_t*>(&Bs[bb]);
                const uint32_t b1 = *reinterpret_cast<const uint32_t*>(&Bs[bb + 8]);
                mma_f16(acc[0][nt], af[0], b0, b1);
                mma_f16(acc[1][nt], af[1], b0, b1);
            }
        }
    }
#pragma unroll
    for (int mt = 0; mt < 2; mt++) {
#pragma unroll
        for (int h = 0; h < 2; h++) {
            const int gr = row0 + wm * 32 + mt * 16 + g4 + h * 8;
            if (gr >= nrows) continue;
            const int ro = rows ? __ldg(&rows[gr]) : gr;
#pragma unroll
            for (int nt = 0; nt < 8; nt++) {
                const int col = col0 + wn * 64 + nt * 8 + t4 * 2;
                float2 v = make_float2(acc[mt][nt][h * 2 + 0], acc[mt][nt][h * 2 + 1]);
                __half2 hv = __float22half2_rn(v);
                *reinterpret_cast<__half2*>(C + (size_t)ro * ldC + col) = hv;
            }
        }
    }
}

// indexed projections: fused 3 (act/res/time), grid (2, maxRowT, 3)
struct IdxP { const float* A; const float* B; __half* C; int K;
              const int* rows; const int* cntp; };
struct IdxP3 { IdxP d[3]; };
__global__ void __launch_bounds__(256) gemm_proj3(IdxP3 g) {
    const IdxP d = g.d[blockIdx.z];
    const int nrows = *d.cntp;
    const int row0 = blockIdx.y * 128;
    if (row0 >= nrows) return;
    __shared__ __align__(16) __half As[128 * STRH];
    __shared__ __align__(16) __half Bs[128 * STRH];
    gemm_core_f32(d.A, d.B, nullptr, nullptr, d.C,
                  nrows, d.K, 256, row0, blockIdx.x * 128, d.rows, As, Bs);
}

// batched weight folds: ONE launch, grid (2,2,12)
struct FoldDesc { const float* A; const float* B0; const float* B1;
                  const float* B2; __half* C; int ldC; };
struct Fold12 { FoldDesc d[12]; };
__global__ void __launch_bounds__(256) gemm_fold(Fold12 args) {
    __shared__ __align__(16) __half As[128 * STRH];
    __shared__ __align__(16) __half Bs[128 * STRH];
    const FoldDesc f = args.d[blockIdx.z];
    gemm_core_f32(f.A, f.B0, f.B1, f.B2, f.C,
                  256, 256, f.ldC, blockIdx.y * 128, blockIdx.x * 128, nullptr, As, Bs);
}

// batched transposes (9 in one launch)
struct TPArgs { const float* in[9]; float* out[9]; int kin[9]; };
__global__ void transpose9(TPArgs a) {
    int z = blockIdx.z, k = blockIdx.x, n = threadIdx.x;
    if (k < a.kin[z])
        a.out[z][(size_t)n * a.kin[z] + k] = a.in[z][(size_t)k * 256 + n];
}

// batched bias folds (6 in one launch)
struct FoldB { const float* b1; const float* b2; const float* b3;
               const float* B; const float* blin; float* out; };
struct FoldB6 { FoldB d[6]; };
__global__ void fold_b6(FoldB6 a) {
    const FoldB f = a.d[blockIdx.x];
    int j = threadIdx.x;
    float acc = f.blin[j];
    for (int k = 0; k < Hc; k++) {
        float bb = f.b1[k];
        if (f.b2) bb += f.b2[k];
        if (f.b3) bb += f.b3[k];
        acc = fmaf(bb, f.B[k * Hc + j], acc);
    }
    f.out[j] = acc;
}

// =====================================================================
// CSR scan kernels
// =====================================================================
__global__ void scan1(const int* __restrict__ cnt, int* __restrict__ off,
                      int* __restrict__ bsum, int N) {
    __shared__ int sh[1024];
    int i = blockIdx.x * 1024 + threadIdx.x;
    int x = (i < N) ? cnt[i] : 0;
    sh[threadIdx.x] = x;
    __syncthreads();
    for (int d = 1; d < 1024; d <<= 1) {
        int t = (threadIdx.x >= d) ? sh[threadIdx.x - d] : 0;
        __syncthreads();
        sh[threadIdx.x] += t;
        __syncthreads();
    }
    int incl = sh[threadIdx.x];
    if (i < N) off[i] = incl - x;
    if (threadIdx.x == 1023) bsum[blockIdx.x] = incl;
}
__global__ void scan2(int* __restrict__ bsum, int B) {
    __shared__ int sh[1024];
    int t = threadIdx.x;
    int x = (t < B) ? bsum[t] : 0;
    sh[t] = x;
    __syncthreads();
    for (int d = 1; d < 1024; d <<= 1) {
        int v = (t >= d) ? sh[t - d] : 0;
        __syncthreads();
        sh[t] += v;
        __syncthreads();
    }
    if (t < B) bsum[t] = sh[t] - x;
}
__global__ void scan3(int* __restrict__ off, const int* __restrict__ bsum,
                      int N, int total) {
    int i = blockIdx.x * blockDim.x + threadIdx.x;
    if (i < N) off[i] += bsum[i >> 10];
    if (i == 0) off[N] = total;
}

// =====================================================================
// frontier flags
// =====================================================================
__global__ void flag_last(const int* __restrict__ last, int* __restrict__ fLast,
                          int* __restrict__ fA1) {
    int g = blockIdx.x * blockDim.x + threadIdx.x;
    if (g < GG) { int n = __ldg(&last[g]); fLast[n] = 1; fA1[n] = 1; }
}
// pass 1: sources of edges into last-set (reads fLast only)
__global__ void prop1(const int* __restrict__ sf, const int* __restrict__ df,
                      const int* __restrict__ sra, const int* __restrict__ dra,
                      const int* __restrict__ sta, const int* __restrict__ dta,
                      const int* __restrict__ fLast,
                      int* __restrict__ fA1, int* __restrict__ fR1,
                      int* __restrict__ fT1) {
    int i = blockIdx.x * blockDim.x + threadIdx.x;
    if (i >= 3 * EE) return;
    int r = i / EE, e = i - r * EE;
    if (r == 0)      { if (__ldg(&fLast[df[e]]))  fA1[sf[e]]  = 1; }
    else if (r == 1) { if (__ldg(&fLast[dra[e]])) fR1[sra[e]] = 1; }
    else             { if (__ldg(&fLast[dta[e]])) fT1[sta[e]] = 1; }
}
// pass 2 FUSED with filtered CSR count: per relation, if dst flagged ->
// set per-section src flag AND count the edge (full degree at flagged dst).
__global__ void prop2cnt(const int* __restrict__ sf, const int* __restrict__ df,
                         const int* __restrict__ sra, const int* __restrict__ dra,
                         const int* __restrict__ sta, const int* __restrict__ dta,
                         const int* __restrict__ sar, const int* __restrict__ dar,
                         const int* __restrict__ sat, const int* __restrict__ dat,
                         const int* __restrict__ fA1, const int* __restrict__ fR1,
                         const int* __restrict__ fT1,
                         int* __restrict__ ib2, int* __restrict__ cnt) {
    int i = blockIdx.x * blockDim.x + threadIdx.x;
    if (i >= 5 * EE) return;
    int r = i / EE, e = i - r * EE;
    switch (r) {
        case 0: { int d = df[e];  if (__ldg(&fA1[d])) { ib2[F_LF  + sf[e]]  = 1; atomicAdd(&cnt[B_F  + d], 1); } } break;
        case 1: { int d = dra[e]; if (__ldg(&fA1[d])) { ib2[F_LRA + sra[e]] = 1; atomicAdd(&cnt[B_RA + d], 1); } } break;
        case 2: { int d = dta[e]; if (__ldg(&fA1[d])) { ib2[F_LTA + sta[e]] = 1; atomicAdd(&cnt[B_TA + d], 1); } } break;
        case 3: { int d = dar[e]; if (__ldg(&fR1[d])) { ib2[F_LAR + sar[e]] = 1; atomicAdd(&cnt[B_AR + d], 1); } } break;
        default:{ int d = dat[e]; if (__ldg(&fT1[d])) { ib2[F_LAT + sat[e]] = 1; atomicAdd(&cnt[B_AT + d], 1); } } break;
    }
}
// filtered fill: only edges with flagged dst are placed
__global__ void fill5f(const int* __restrict__ s0, const int* __restrict__ d0,
                       const int* __restrict__ s1, const int* __restrict__ d1,
                       const int* __restrict__ s2, const int* __restrict__ d2,
                       const int* __restrict__ s3, const int* __restrict__ d3,
                       const int* __restrict__ s4, const int* __restrict__ d4,
                       const int* __restrict__ fA1, const int* __restrict__ fR1,
                       const int* __restrict__ fT1,
                       int* __restrict__ cur, int* __restrict__ idx) {
    int i = blockIdx.x * blockDim.x + threadIdx.x;
    if (i >= 5 * EE) return;
    int r = i / EE, e = i - r * EE;
    const int *sp, *dp, *fp; int base;
    switch (r) {
        case 0: sp = s0; dp = d0; base = B_F;  fp = fA1; break;
        case 1: sp = s1; dp = d1; base = B_RA; fp = fA1; break;
        case 2: sp = s2; dp = d2; base = B_TA; fp = fA1; break;
        case 3: sp = s3; dp = d3; base = B_AR; fp = fR1; break;
        default: sp = s4; dp = d4; base = B_AT; fp = fT1; break;
    }
    int d = dp[e];
    if (__ldg(&fp[d])) {
        int p = atomicAdd(&cur[base + d], 1);
        idx[p] = sp[e];
    }
}
// compact all flags into 11 lists
__global__ void compact11(int* __restrict__ ib2) {
    int i = blockIdx.x * blockDim.x + threadIdx.x;
    if (i >= NACT + NRES + NTIME) return;
    if (i < NACT) {
        int a1  = ib2[F_A1  + i];
        int lf  = ib2[F_LF  + i];
        int lar = ib2[F_LAR + i];
        int lat = ib2[F_LAT + i];
        if (a1)  { int p = atomicAdd(&ib2[CTRS + 0],  1); ib2[L_A1  + p] = i; }
        if (lf)  { int p = atomicAdd(&ib2[CTRS + 6],  1); ib2[L_LF  + p] = i; }
        if (lar) { int p = atomicAdd(&ib2[CTRS + 7],  1); ib2[L_LAR + p] = i; }
        if (lat) { int p = atomicAdd(&ib2[CTRS + 8],  1); ib2[L_LAT + p] = i; }
        if (a1 | lf | lar | lat) {
            int p = atomicAdd(&ib2[CTRS + 3], 1); ib2[L_PA + p] = i;
        }
    } else if (i < NACT + NRES) {
        int n = i - NACT;
        int r1  = ib2[F_R1  + n];
        int lra = ib2[F_LRA + n];
        if (r1)  { int p = atomicAdd(&ib2[CTRS + 1],  1); ib2[L_R1  + p] = n; }
        if (lra) { int p = atomicAdd(&ib2[CTRS + 9],  1); ib2[L_LRA + p] = n; }
        if (r1 | lra) {
            int p = atomicAdd(&ib2[CTRS + 4], 1); ib2[L_PR + p] = n;
        }
    } else {
        int n = i - NACT - NRES;
        int t1  = ib2[F_T1  + n];
        int lta = ib2[F_LTA + n];
        if (t1)  { int p = atomicAdd(&ib2[CTRS + 2],  1); ib2[L_T1  + p] = n; }
        if (lta) { int p = atomicAdd(&ib2[CTRS + 10], 1); ib2[L_LTA + p] = n; }
        if (t1 | lta) {
            int p = atomicAdd(&ib2[CTRS + 5], 1); ib2[L_PT + p] = n;
        }
    }
}

// =====================================================================
// gathers
// =====================================================================
__device__ __forceinline__ void accum_rel(const __half* __restrict__ base, int stride,
                                          const int* __restrict__ off,
                                          const int* __restrict__ idx,
                                          int w, int lane, float* a) {
    int se = (lane < 2) ? __ldg(&off[w + lane]) : 0;
    int s = __shfl_sync(0xffffffffu, se, 0);
    int e = __shfl_sync(0xffffffffu, se, 1);
    if (e <= s) return;
    float sc = 1.f / (float)(e - s);
    float m[8] = {0.f, 0.f, 0.f, 0.f, 0.f, 0.f, 0.f, 0.f};
    for (int p = s; p < e; p++) {
        int sn = __ldg(&idx[p]);
        uint4 q = *reinterpret_cast<const uint4*>(base + (size_t)sn * stride + lane * 8);
        float f[8];
        h8_to_f8(q, f);
#pragma unroll
        for (int j = 0; j < 8; j++) m[j] += f[j];
    }
#pragma unroll
    for (int j = 0; j < 8; j++) a[j] += m[j] * sc;
}

// layer-0 gather restricted to frontier lists
__global__ void __launch_bounds__(256) gather_idx(
        const __half* __restrict__ Pa, const __half* __restrict__ Pr,
        const __half* __restrict__ Pt,
        const int* __restrict__ off, const int* __restrict__ idx,
        const int* __restrict__ ib2,
        __half* __restrict__ A, __half* __restrict__ R, __half* __restrict__ T) {
    int w = (blockIdx.x * 256 + threadIdx.x) >> 5;
    int lane = threadIdx.x & 31;
    const int cA = __ldg(&ib2[CTRS + 0]);
    const int cR = __ldg(&ib2[CTRS + 1]);
    const int cT = __ldg(&ib2[CTRS + 2]);
    float a[8];
    if (w < cA) {
        int u = __ldg(&ib2[L_A1 + w]);
        h8_to_f8(*reinterpret_cast<const uint4*>(Pa + (size_t)u * 1024 + 768 + lane * 8), a);
        accum_rel(Pa, 1024, off + B_F,  idx, u, lane, a);
        accum_rel(Pr, 512,  off + B_RA, idx, u, lane, a);
        accum_rel(Pt, 512,  off + B_TA, idx, u, lane, a);
#pragma unroll
        for (int j = 0; j < 8; j++) a[j] = fmaxf(a[j], 0.f);
        *reinterpret_cast<uint4*>(A + (size_t)u * 256 + lane * 8) = f8_to_h8(a);
    } else if (w < cA + cR) {
        int v = __ldg(&ib2[L_R1 + (w - cA)]);
        h8_to_f8(*reinterpret_cast<const uint4*>(Pr + (size_t)v * 512 + 256 + lane * 8), a);
        accum_rel(Pa + 256, 1024, off + B_AR, idx, v, lane, a);
#pragma unroll
        for (int j = 0; j < 8; j++) a[j] = fmaxf(a[j], 0.f);
        *reinterpret_cast<uint4*>(R + (size_t)v * 256 + lane * 8) = f8_to_h8(a);
    } else if (w < cA + cR + cT) {
        int v = __ldg(&ib2[L_T1 + (w - cA - cR)]);
        h8_to_f8(*reinterpret_cast<const uint4*>(Pt + (size_t)v * 512 + 256 + lane * 8), a);
        accum_rel(Pa + 512, 1024, off + B_AT, idx, v, lane, a);
#pragma unroll
        for (int j = 0; j < 8; j++) a[j] = fmaxf(a[j], 0.f);
        *reinterpret_cast<uint4*>(T + (size_t)v * 256 + lane * 8) = f8_to_h8(a);
    }
}

// layer-1 pooled gather: X2[512, 1024] = [mf(a1)|mra(r1)|mta(t1)|a1 self]
__global__ void __launch_bounds__(256) gather_pool(
        const __half* __restrict__ A, const __half* __restrict__ R,
        const __half* __restrict__ T,
        const int* __restrict__ off, const int* __restrict__ idx,
        const int* __restrict__ last, __half* __restrict__ X2) {
    int w = (blockIdx.x * 256 + threadIdx.x) >> 5;
    int lane = threadIdx.x & 31;
    if (w >= 4 * GG) return;
    int g = w >> 2, s = w & 3;
    int nid = __ldg(&last[g]);
    float a[8] = {0.f, 0.f, 0.f, 0.f, 0.f, 0.f, 0.f, 0.f};
    if (s == 0)      accum_rel(A, 256, off + B_F,  idx, nid, lane, a);
    else if (s == 1) accum_rel(R, 256, off + B_RA, idx, nid, lane, a);
    else if (s == 2) accum_rel(T, 256, off + B_TA, idx, nid, lane, a);
    else h8_to_f8(*reinterpret_cast<const uint4*>(A + (size_t)nid * 256 + lane * 8), a);
    *reinterpret_cast<uint4*>(X2 + (size_t)g * 1024 + s * 256 + lane * 8) = f8_to_h8(a);
}

// =====================================================================
// misc kernels
// =====================================================================
__global__ void last_k(const int* __restrict__ batch, int* __restrict__ last, int N) {
    int i = blockIdx.x * blockDim.x + threadIdx.x;
    if (i < N) {
        if (i == N - 1 || batch[i + 1] != batch[i]) last[batch[i]] = i;
    }
}

__global__ void heads_k(const __half* __restrict__ a2,
                        const float* __restrict__ Wo, const float* __restrict__ bo,
                        const float* __restrict__ Wt, const float* __restrict__ bt,
                        const float* __restrict__ Wrm, const float* __restrict__ brm,
                        float* __restrict__ out) {
    int g = blockIdx.x;
    __shared__ float p[Hc];
    const __half* row = a2 + (size_t)g * Hc;
    for (int k = threadIdx.x; k < Hc; k += blockDim.x) p[k] = __half2float(row[k]);
    __syncthreads();
    int j = threadIdx.x;
    if (j < CC) {
        float acc = bo[j];
        for (int k = 0; k < Hc; k++) acc = fmaf(p[k], Wo[k * CC + j], acc);
        out[g * CC + j] = acc;
    } else if (j == CC) {
        float acc = bt[0];
        for (int k = 0; k < Hc; k++) acc = fmaf(p[k], Wt[k], acc);
        out[GG * CC + g] = acc;
    } else if (j == CC + 1) {
        float acc = brm[0];
        for (int k = 0; k < Hc; k++) acc = fmaf(p[k], Wrm[k], acc);
        out[GG * CC + GG + g] = acc;
    }
}

// =====================================================================
// host orchestration
// =====================================================================
extern "C" void kernel_launch(void* const* d_in, const int* in_sizes, int n_in,
                              void* d_out, int out_size) {
    float* buf = nullptr;
    cudaGetSymbolAddress((void**)&buf, g_buf);

    __half* A  = reinterpret_cast<__half*>(buf + OFF_A);
    __half* R  = reinterpret_cast<__half*>(buf + OFF_R);
    __half* T  = reinterpret_cast<__half*>(buf + OFF_T);
    __half* Pa = reinterpret_cast<__half*>(buf + OFF_PA);
    __half* Pr = reinterpret_cast<__half*>(buf + OFF_PR);
    __half* Pt = reinterpret_cast<__half*>(buf + OFF_PT);
    __half* X2 = Pr;
    __half* A2 = Pt;
    __half* WCh = reinterpret_cast<__half*>(buf + OFF_WC);
    __half* WB2 = WCh + 524288;
    float* BF  = buf + OFF_BF;
    float* WLT = buf + OFF_WLT;
    float* WPT = buf + OFF_WPT;
    int*   LAST = reinterpret_cast<int*>(buf + OFF_LAST);
    int*   IB   = reinterpret_cast<int*>(buf + OFF_INT);
    int*   IB2  = reinterpret_cast<int*>(buf + OFF_INT2);
    int* off  = IB + IO_OFFS;
    int* cnt  = IB + IO_CNT;
    int* bsum = IB + IO_BSUM;
    int* idx  = IB + IO_IDX;

    const float* x_act  = (const float*)d_in[0];
    const float* x_res  = (const float*)d_in[1];
    const float* x_time = (const float*)d_in[2];
    const int* src_f  = (const int*)d_in[3];
    const int* dst_f  = (const int*)d_in[4];
    const int* src_ar = (const int*)d_in[5];
    const int* dst_ar = (const int*)d_in[6];
    const int* src_ra = (const int*)d_in[7];
    const int* dst_ra = (const int*)d_in[8];
    const int* src_at = (const int*)d_in[9];
    const int* dst_at = (const int*)d_in[10];
    const int* src_ta = (const int*)d_in[11];
    const int* dst_ta = (const int*)d_in[12];
    const int* batch  = (const int*)d_in[13];

    int w = (in_sizes[14] <= 4) ? 15 : 14;
    const float* Wp_act = (const float*)d_in[w + 0];
    const float* Wp_res = (const float*)d_in[w + 1];
    const float* Wp_tim = (const float*)d_in[w + 2];
    const float* Wl     = (const float*)d_in[w + 3];
    const float* bl     = (const float*)d_in[w + 4];
    const float* Wr     = (const float*)d_in[w + 5];
    const float* Wlin   = (const float*)d_in[w + 6];
    const float* blin   = (const float*)d_in[w + 7];
    const float* Wo     = (const float*)d_in[w + 8];
    const float* bo     = (const float*)d_in[w + 9];
    const float* Wt     = (const float*)d_in[w + 10];
    const float* bt     = (const float*)d_in[w + 11];
    const float* Wrm    = (const float*)d_in[w + 12];
    const float* brm    = (const float*)d_in[w + 13];

    const size_t HH = 65536;  // 256*256

    // --- zero flags, counters, CSR counts, LAST ---
    cudaMemsetAsync(IB2, 0, FLAGS_END * sizeof(int), 0);
    cudaMemsetAsync(IB2 + CTRS, 0, 16 * sizeof(int), 0);
    cudaMemsetAsync(cnt, 0, CSR_N * sizeof(int), 0);
    cudaMemsetAsync(LAST, 0, GG * sizeof(int), 0);

    // --- fused transposes ---
    {
        TPArgs tp;
        tp.in[0] = Wp_act; tp.out[0] = WPT + 0;     tp.kin[0] = 64;
        tp.in[1] = Wp_res; tp.out[1] = WPT + 16384; tp.kin[1] = 32;
        tp.in[2] = Wp_tim; tp.out[2] = WPT + 24576; tp.kin[2] = 16;
        for (int i = 0; i < 6; i++) {
            tp.in[3 + i]  = Wlin + (size_t)i * HH;
            tp.out[3 + i] = WLT + (size_t)i * HH;
            tp.kin[3 + i] = 256;
        }
        transpose9<<<dim3(256, 1, 9), 256>>>(tp);
    }

    // --- fused weight folds: 8 (l=0) + 4 (l=1 concat-K) ---
    {
        Fold12 fa;
        {
            const float* lt0 = WLT + 0 * HH;
            const float* lt1 = WLT + 1 * HH;
            const float* lt2 = WLT + 2 * HH;
            __half* WCa = WCh;
            __half* WCr = WCa + 262144;
            __half* WCt = WCr + 131072;
            fa.d[0] = {lt0, Wl + 0 * HH, nullptr, nullptr, WCa + 0,      256};
            fa.d[1] = {lt1, Wl + 1 * HH, nullptr, nullptr, WCa + 65536,  256};
            fa.d[2] = {lt2, Wl + 3 * HH, nullptr, nullptr, WCa + 131072, 256};
            fa.d[3] = {lt0, Wr + 0 * HH, Wr + 2 * HH, Wr + 4 * HH, WCa + 196608, 256};
            fa.d[4] = {lt0, Wl + 2 * HH, nullptr, nullptr, WCr + 0,      256};
            fa.d[5] = {lt1, Wr + 1 * HH, nullptr, nullptr, WCr + 65536,  256};
            fa.d[6] = {lt0, Wl + 4 * HH, nullptr, nullptr, WCt + 0,      256};
            fa.d[7] = {lt2, Wr + 3 * HH, nullptr, nullptr, WCt + 65536,  256};
        }
        {
            const float* lt0 = WLT + 3 * HH;
            fa.d[8]  = {lt0, Wl + 5 * HH, nullptr, nullptr, WB2 + 0,   1024};
            fa.d[9]  = {lt0, Wl + 7 * HH, nullptr, nullptr, WB2 + 256, 1024};
            fa.d[10] = {lt0, Wl + 9 * HH, nullptr, nullptr, WB2 + 512, 1024};
            fa.d[11] = {lt0, Wr + 5 * HH, Wr + 7 * HH, Wr + 9 * HH, WB2 + 768, 1024};
        }
        gemm_fold<<<dim3(2, 2, 12), 256>>>(fa);

        FoldB6 fb;
        for (int l = 0; l < 2; l++) {
            fb.d[l * 3 + 0] = {bl + (l * 5 + 0) * 256, bl + (l * 5 + 2) * 256,
                               bl + (l * 5 + 4) * 256, Wlin + (size_t)(l * 3 + 0) * HH,
                               blin + (l * 3 + 0) * 256, BF + l * 768 + 0};
            fb.d[l * 3 + 1] = {bl + (l * 5 + 1) * 256, nullptr, nullptr,
                               Wlin + (size_t)(l * 3 + 1) * HH,
                               blin + (l * 3 + 1) * 256, BF + l * 768 + 256};
            fb.d[l * 3 + 2] = {bl + (l * 5 + 3) * 256, nullptr, nullptr,
                               Wlin + (size_t)(l * 3 + 2) * HH,
                               blin + (l * 3 + 2) * 256, BF + l * 768 + 512};
        }
        fold_b6<<<6, 256>>>(fb);
    }

    // --- frontier flags + fused count, scan, filtered fill, compact ---
    last_k<<<(NACT + 255) / 256, 256>>>(batch, LAST, NACT);
    flag_last<<<(GG + 255) / 256, 256>>>(LAST, IB2 + F_LAST, IB2 + F_A1);
    prop1<<<(3 * EE + 255) / 256, 256>>>(src_f, dst_f, src_ra, dst_ra,
                                         src_ta, dst_ta, IB2 + F_LAST,
                                         IB2 + F_A1, IB2 + F_R1, IB2 + F_T1);
    {
        int nb = (5 * EE + 255) / 256;
        prop2cnt<<<nb, 256>>>(src_f, dst_f, src_ra, dst_ra, src_ta, dst_ta,
                              src_ar, dst_ar, src_at, dst_at,
                              IB2 + F_A1, IB2 + F_R1, IB2 + F_T1, IB2, cnt);
        compact11<<<(NACT + NRES + NTIME + 255) / 256, 256>>>(IB2);
        int sb = (CSR_N + 1023) / 1024;
        scan1<<<sb, 1024>>>(cnt, off, bsum, CSR_N);
        scan2<<<1, 1024>>>(bsum, sb);
        scan3<<<(CSR_N + 255) / 256, 256>>>(off, bsum, CSR_N, 5 * EE);
        cudaMemcpyAsync(cnt, off, CSR_N * sizeof(int), cudaMemcpyDeviceToDevice, 0);
        fill5f<<<nb, 256>>>(src_f, dst_f, src_ra, dst_ra, src_ta, dst_ta,
                            src_ar, dst_ar, src_at, dst_at,
                            IB2 + F_A1, IB2 + F_R1, IB2 + F_T1, cnt, idx);
    }

    // --- frontier-restricted projections (fused 3) ---
    {
        IdxP3 p;
        p.d[0] = {x_act,  WPT + 0,     A, 64, IB2 + L_PA, IB2 + CTRS + 3};
        p.d[1] = {x_res,  WPT + 16384, R, 32, IB2 + L_PR, IB2 + CTRS + 4};
        p.d[2] = {x_time, WPT + 24576, T, 16, IB2 + L_PT, IB2 + CTRS + 5};
        gemm_proj3<<<dim3(2, (NACT + 127) / 128, 3), 256>>>(p);
    }

    // --- layer 0: per-section indexed GEMMs (8 in one launch) + gather ---
    {
        __half* WCa = WCh;
        __half* WCr = WCa + 262144;
        __half* WCt = WCr + 131072;
        IdxG8 g;
        // act sections
        g.d[0] = {A, WCa + 0,      BF,       NOBIAS, Pa + 0,   1024, IB2 + L_LF,  IB2 + CTRS + 6};
        g.d[1] = {A, WCa + 65536,  BF,       NOBIAS, Pa + 256, 1024, IB2 + L_LAR, IB2 + CTRS + 7};
        g.d[2] = {A, WCa + 131072, BF,       NOBIAS, Pa + 512, 1024, IB2 + L_LAT, IB2 + CTRS + 8};
        g.d[3] = {A, WCa + 196608, BF + 0,   0,      Pa + 768, 1024, IB2 + L_A1,  IB2 + CTRS + 0};
        // res sections
        g.d[4] = {R, WCr + 0,      BF,       NOBIAS, Pr + 0,   512,  IB2 + L_LRA, IB2 + CTRS + 9};
        g.d[5] = {R, WCr + 65536,  BF + 256, 0,      Pr + 256, 512,  IB2 + L_R1,  IB2 + CTRS + 1};
        // time sections
        g.d[6] = {T, WCt + 0,      BF,       NOBIAS, Pt + 0,   512,  IB2 + L_LTA, IB2 + CTRS + 10};
        g.d[7] = {T, WCt + 65536,  BF + 512, 0,      Pt + 256, 512,  IB2 + L_T1,  IB2 + CTRS + 2};
        gemm_sec8<<<dim3(2, (NACT + 127) / 128, 8), 256>>>(g);

        const int gblocks = ((NACT + NRES + NTIME) * 32 + 255) / 256;
        gather_idx<<<gblocks, 256>>>(Pa, Pr, Pt, off, idx, IB2, A, R, T);
    }

    // --- layer 1: pooled aggregate-then-project (512 rows) ---
    {
        gather_pool<<<(4 * GG * 32 + 255) / 256, 256>>>(A, R, T, off, idx, LAST, X2);
        Gemm3 g;
        g.d[0] = {X2, WB2, BF + 768, A2, 0, GG, 256, 2, 1024, 1};
        g.d[1] = g.d[0]; g.d[2] = g.d[0];
        g.n0 = 8; g.n01 = 8;
        gemm_fast3<<<8, 256>>>(g);
    }

    // --- heads ---
    heads_k<<<GG, 64>>>(A2, Wo, bo, Wt, bt, Wrm, brm, (float*)d_out);
}

// round 16
// speedup vs baseline: 42.7575x; 1.1028x over previous
#include <cuda_runtime.h>
#include <cuda_fp16.h>
#include <cstdint>
#include <cstddef>

#define Hc    256
#define CC    50
#define GG    512
#define NACT  200000
#define NRES  20000
#define NTIME 100000
#define EE    400000

// ---------------- scratch layout (float units) ----------------
static constexpr size_t OFF_A    = 0;            // 200000*256 h
static constexpr size_t OFF_R    = 25600000;     // 20000*256 h
static constexpr size_t OFF_T    = 28160000;     // 100000*256 h
static constexpr size_t OFF_PA   = 40960000;     // 200000*1024 h [f|ar|at|self]
static constexpr size_t OFF_PR   = 143360000;    // 20000*512 h   (reused: X2)
static constexpr size_t OFF_PT   = 148480000;    // 100000*512 h  (reused: A2)
static constexpr size_t OFF_WC   = 174080000;    // folded weights fp16
static constexpr size_t OFF_BF   = 175128576;    // 2*3*256 f32
static constexpr size_t OFF_WLT  = 175130112;    // 6*65536 f32 Wlin^T
static constexpr size_t OFF_WPT  = 175523328;    // 256*(64+32+16) f32 Wp^T
static constexpr size_t OFF_LAST = 175552000;    // 512 ints
static constexpr size_t OFF_INT  = 175552512;    // CSR int scratch (4.2M ints)
static constexpr size_t OFF_INT2 = 179752512;    // frontier int scratch
static constexpr size_t TOTALF   = 182352528;

// unified CSR (ints, relative to OFF_INT)
static constexpr int CSR_N = 720000;
static constexpr int B_F  = 0;
static constexpr int B_RA = 200000;
static constexpr int B_TA = 400000;
static constexpr int B_AR = 600000;
static constexpr int B_AT = 620000;
static constexpr size_t IO_OFFS = 0;          // 720004
static constexpr size_t IO_CNT  = 720004;     // 720000
static constexpr size_t IO_CUR  = 1440004;    // 720000
static constexpr size_t IO_IDX  = 2160004;    // 2,000,000

// frontier region (ints, relative to OFF_INT2)
static constexpr size_t F_LAST = 0;          // 200000
static constexpr size_t F_A1   = 200000;     // 200000
static constexpr size_t F_R1   = 400000;     // 20000
static constexpr size_t F_T1   = 420000;     // 100000
static constexpr size_t F_LF   = 520000;     // 200000
static constexpr size_t F_LAR  = 720000;     // 200000
static constexpr size_t F_LAT  = 920000;     // 200000
static constexpr size_t F_LRA  = 1120000;    // 20000
static constexpr size_t F_LTA  = 1140000;    // 100000
static constexpr size_t FLAGS_END = 1240000;
static constexpr size_t L_A1   = 1240000;    // 200000
static constexpr size_t L_R1   = 1440000;    // 20000
static constexpr size_t L_T1   = 1460000;    // 100000
static constexpr size_t L_LF   = 1560000;    // 200000
static constexpr size_t L_LAR  = 1760000;    // 200000
static constexpr size_t L_LAT  = 1960000;    // 200000
static constexpr size_t L_LRA  = 2160000;    // 20000
static constexpr size_t L_LTA  = 2180000;    // 100000
static constexpr size_t L_PA   = 2280000;    // 200000
static constexpr size_t L_PR   = 2480000;    // 20000
static constexpr size_t L_PT   = 2500000;    // 100000
static constexpr size_t CTRS   = 2600000;    // 16
// counters: 0:A1 1:R1 2:T1 3:PA 4:PR 5:PT 6:LF 7:LAR 8:LAT 9:LRA 10:LTA 11:gcur

__device__ float g_buf[TOTALF];

// =====================================================================
// helpers
// =====================================================================
__device__ __forceinline__ void mma_f16(float* d, const uint32_t* a,
                                        uint32_t b0, uint32_t b1) {
    asm volatile(
        "mma.sync.aligned.m16n8k16.row.col.f32.f16.f16.f32 "
        "{%0,%1,%2,%3}, {%4,%5,%6,%7}, {%8,%9}, {%0,%1,%2,%3};"
        : "+f"(d[0]), "+f"(d[1]), "+f"(d[2]), "+f"(d[3])
        : "r"(a[0]), "r"(a[1]), "r"(a[2]), "r"(a[3]), "r"(b0), "r"(b1));
}
__device__ __forceinline__ void ldsm4(uint32_t* r, uint32_t addr) {
    asm volatile("ldmatrix.sync.aligned.m8n8.x4.shared.b16 {%0,%1,%2,%3}, [%4];"
                 : "=r"(r[0]), "=r"(r[1]), "=r"(r[2]), "=r"(r[3]) : "r"(addr));
}
__device__ __forceinline__ void cp16(uint32_t dst, const void* src, int szbytes) {
    asm volatile("cp.async.cg.shared.global [%0], [%1], 16, %2;"
                 :: "r"(dst), "l"(src), "r"(szbytes));
}
#define CP_COMMIT() asm volatile("cp.async.commit_group;" ::: "memory")
template <int N>
__device__ __forceinline__ void cp_wait() {
    asm volatile("cp.async.wait_group %0;" :: "n"(N) : "memory");
}
__device__ __forceinline__ uint32_t saddr(const void* p) {
    return static_cast<uint32_t>(__cvta_generic_to_shared(p));
}
__device__ __forceinline__ uint32_t packh2(float x, float y) {
    __half2 h = __float22half2_rn(make_float2(x, y));
    return *reinterpret_cast<uint32_t*>(&h);
}
__device__ __forceinline__ uint4 pack8(float4 a, float4 b) {
    return make_uint4(packh2(a.x, a.y), packh2(a.z, a.w),
                      packh2(b.x, b.y), packh2(b.z, b.w));
}
__device__ __forceinline__ void h8_to_f8(uint4 q, float* f) {
    const __half2* h = reinterpret_cast<const __half2*>(&q);
#pragma unroll
    for (int i = 0; i < 4; i++) {
        float2 t = __half22float2(h[i]);
        f[2 * i] = t.x; f[2 * i + 1] = t.y;
    }
}
__device__ __forceinline__ uint4 f8_to_h8(const float* f) {
    return make_uint4(packh2(f[0], f[1]), packh2(f[2], f[3]),
                      packh2(f[4], f[5]), packh2(f[6], f[7]));
}

#define STRH 40
#define NOBIAS (1 << 30)

// =====================================================================
// fused fp16 GEMM (pooled layer-1): up to 3 sub-GEMMs, runtime K, relu
// =====================================================================
struct GemmDesc {
    const __half* A; const __half* B; const float* bias;
    __half* C; int bstart; int Nrow; int ldC; int colT; int K; int relu;
};
struct Gemm3 { GemmDesc d[3]; int n0, n01; };

__global__ void __launch_bounds__(256) gemm_fast3(Gemm3 g) {
    __shared__ __align__(16) __half As[2][128 * STRH];
    __shared__ __align__(16) __half Bs[2][128 * STRH];
    const int id = blockIdx.x;
    const int zi = (id < g.n0) ? 0 : ((id < g.n01) ? 1 : 2);
    const int rid = id - ((zi == 0) ? 0 : ((zi == 1) ? g.n0 : g.n01));
    const GemmDesc d = g.d[zi];
    const int row0 = (rid / d.colT) * 128;
    const int col0 = (rid % d.colT) * 128;
    const int Nrow = d.Nrow;
    const int K = d.K;
    const __half* __restrict__ A = d.A;
    const __half* __restrict__ B = d.B;

    const int tid  = threadIdx.x;
    const int lane = tid & 31;
    const int wid  = tid >> 5;
    const int wm   = wid & 3;
    const int wn   = wid >> 2;
    const int t4   = lane & 3;
    const int g4   = lane >> 2;
    const int arow = lane & 15;
    const int acol = (lane >> 4) << 3;
    const int brow = (lane & 7) + ((lane >> 4) << 3);
    const int bcol = ((lane >> 3) & 1) << 3;

    float acc[2][8][4];
#pragma unroll
    for (int mt = 0; mt < 2; mt++)
#pragma unroll
        for (int nt = 0; nt < 8; nt++)
#pragma unroll
            for (int q = 0; q < 4; q++) acc[mt][nt][q] = 0.f;

    auto stage = [&](int c, int b) {
        const int k0 = c << 5;
#pragma unroll
        for (int it = 0; it < 2; it++) {
            const int i  = tid + it * 256;
            const int rr = i >> 2;
            const int sg = (i & 3) << 3;
            const int gr = row0 + rr;
            const int grc = gr < Nrow ? gr : (Nrow - 1);
            cp16(saddr(&As[b][rr * STRH + sg]),
                 A + (size_t)grc * K + k0 + sg, gr < Nrow ? 16 : 0);
            cp16(saddr(&Bs[b][rr * STRH + sg]),
                 B + (size_t)(col0 + rr) * K + k0 + sg, 16);
        }
    };

    stage(0, 0);
    CP_COMMIT();
    const int nc = K >> 5;
#pragma unroll 1
    for (int c = 0; c < nc; c++) {
        const int cb = c & 1;
        if (c + 1 < nc) { stage(c + 1, cb ^ 1); CP_COMMIT(); cp_wait<1>(); }
        else            { cp_wait<0>(); }
        __syncthreads();
#pragma unroll
        for (int ks = 0; ks < 2; ks++) {
            const int kb = ks << 4;
            uint32_t af[2][4];
#pragma unroll
            for (int mt = 0; mt < 2; mt++)
                ldsm4(af[mt], saddr(&As[cb][(wm * 32 + mt * 16 + arow) * STRH + kb + acol]));
            uint32_t bf[4][4];
#pragma unroll
            for (int p = 0; p < 4; p++)
                ldsm4(bf[p], saddr(&Bs[cb][(wn * 64 + p * 16 + brow) * STRH + kb + bcol]));
#pragma unroll
            for (int nt = 0; nt < 8; nt++) {
                const uint32_t b0 = bf[nt >> 1][(nt & 1) * 2];
                const uint32_t b1 = bf[nt >> 1][(nt & 1) * 2 + 1];
                mma_f16(acc[0][nt], af[0], b0, b1);
                mma_f16(acc[1][nt], af[1], b0, b1);
            }
        }
        __syncthreads();
    }
#pragma unroll
    for (int mt = 0; mt < 2; mt++) {
#pragma unroll
        for (int h = 0; h < 2; h++) {
            const int gr = row0 + wm * 32 + mt * 16 + g4 + h * 8;
            if (gr >= Nrow) continue;
#pragma unroll
            for (int nt = 0; nt < 8; nt++) {
                const int col = col0 + wn * 64 + nt * 8 + t4 * 2;
                float2 v = make_float2(acc[mt][nt][h * 2 + 0], acc[mt][nt][h * 2 + 1]);
                if (col >= d.bstart) {
                    v.x += __ldg(&d.bias[col - d.bstart]);
                    v.y += __ldg(&d.bias[col - d.bstart + 1]);
                }
                if (d.relu) { v.x = fmaxf(v.x, 0.f); v.y = fmaxf(v.y, 0.f); }
                __half2 hv = __float22half2_rn(v);
                *reinterpret_cast<__half2*>(d.C + (size_t)gr * d.ldC + col) = hv;
            }
        }
    }
}

// =====================================================================
// INDEXED section GEMM: 8 sub-GEMMs, K=256, persistent row-tile loop.
// =====================================================================
struct IdxG { const __half* A; const __half* B; const float* bias; int bstart;
              __half* C; int ldC; const int* rows; const int* cntp; };
struct IdxG8 { IdxG d[8]; };

__global__ void __launch_bounds__(256) gemm_sec8(IdxG8 g) {
    __shared__ __align__(16) __half As[2][128 * STRH];
    __shared__ __align__(16) __half Bs[2][128 * STRH];
    const IdxG d = g.d[blockIdx.z];
    const int nrows = *d.cntp;
    const int col0 = blockIdx.x * 128;
    const __half* __restrict__ A = d.A;
    const __half* __restrict__ B = d.B;
    const int* __restrict__ rows = d.rows;
    constexpr int K = 256;

    const int tid  = threadIdx.x;
    const int lane = tid & 31;
    const int wid  = tid >> 5;
    const int wm   = wid & 3;
    const int wn   = wid >> 2;
    const int t4   = lane & 3;
    const int g4   = lane >> 2;
    const int arow = lane & 15;
    const int acol = (lane >> 4) << 3;
    const int brow = (lane & 7) + ((lane >> 4) << 3);
    const int bcol = ((lane >> 3) & 1) << 3;

    for (int row0 = blockIdx.y * 128; row0 < nrows; row0 += gridDim.y * 128) {
        float acc[2][8][4];
#pragma unroll
        for (int mt = 0; mt < 2; mt++)
#pragma unroll
            for (int nt = 0; nt < 8; nt++)
#pragma unroll
                for (int q = 0; q < 4; q++) acc[mt][nt][q] = 0.f;

        auto stage = [&](int c, int b) {
            const int k0 = c << 5;
#pragma unroll
            for (int it = 0; it < 2; it++) {
                const int i  = tid + it * 256;
                const int rr = i >> 2;
                const int sg = (i & 3) << 3;
                const int gr = row0 + rr;
                const int ri = __ldg(&rows[gr < nrows ? gr : (nrows - 1)]);
                cp16(saddr(&As[b][rr * STRH + sg]),
                     A + (size_t)ri * K + k0 + sg, gr < nrows ? 16 : 0);
                cp16(saddr(&Bs[b][rr * STRH + sg]),
                     B + (size_t)(col0 + rr) * K + k0 + sg, 16);
            }
        };

        stage(0, 0);
        CP_COMMIT();
        constexpr int nc = K >> 5;
#pragma unroll 1
        for (int c = 0; c < nc; c++) {
            const int cb = c & 1;
            if (c + 1 < nc) { stage(c + 1, cb ^ 1); CP_COMMIT(); cp_wait<1>(); }
            else            { cp_wait<0>(); }
            __syncthreads();
#pragma unroll
            for (int ks = 0; ks < 2; ks++) {
                const int kb = ks << 4;
                uint32_t af[2][4];
#pragma unroll
                for (int mt = 0; mt < 2; mt++)
                    ldsm4(af[mt], saddr(&As[cb][(wm * 32 + mt * 16 + arow) * STRH + kb + acol]));
                uint32_t bf[4][4];
#pragma unroll
                for (int p = 0; p < 4; p++)
                    ldsm4(bf[p], saddr(&Bs[cb][(wn * 64 + p * 16 + brow) * STRH + kb + bcol]));
#pragma unroll
                for (int nt = 0; nt < 8; nt++) {
                    const uint32_t b0 = bf[nt >> 1][(nt & 1) * 2];
                    const uint32_t b1 = bf[nt >> 1][(nt & 1) * 2 + 1];
                    mma_f16(acc[0][nt], af[0], b0, b1);
                    mma_f16(acc[1][nt], af[1], b0, b1);
                }
            }
            __syncthreads();
        }
#pragma unroll
        for (int mt = 0; mt < 2; mt++) {
#pragma unroll
            for (int h = 0; h < 2; h++) {
                const int gr = row0 + wm * 32 + mt * 16 + g4 + h * 8;
                if (gr >= nrows) continue;
                const int ro = __ldg(&rows[gr]);
#pragma unroll
                for (int nt = 0; nt < 8; nt++) {
                    const int col = col0 + wn * 64 + nt * 8 + t4 * 2;
                    float2 v = make_float2(acc[mt][nt][h * 2 + 0], acc[mt][nt][h * 2 + 1]);
                    if (col >= d.bstart) {
                        v.x += __ldg(&d.bias[col - d.bstart]);
                        v.y += __ldg(&d.bias[col - d.bstart + 1]);
                    }
                    __half2 hv = __float22half2_rn(v);
                    *reinterpret_cast<__half2*>(d.C + (size_t)ro * d.ldC + col) = hv;
                }
            }
        }
    }
}

// =====================================================================
// GENERIC GEMM core (f32 A staged to fp16), optional row indexing
// =====================================================================
__device__ __forceinline__ void gemm_core_f32(
        const float* __restrict__ A,
        const float* __restrict__ B0s, const float* __restrict__ B1s,
        const float* __restrict__ B2s,
        __half* __restrict__ C,
        int nrows, int K, int ldC, int row0, int col0,
        const int* __restrict__ rows,
        __half* As, __half* Bs) {
    const int tid  = threadIdx.x;
    const int lane = tid & 31;
    const int wid  = tid >> 5;
    const int wm   = wid & 3;
    const int wn   = wid >> 2;
    const int g4   = lane >> 2;
    const int t4   = lane & 3;
    const bool has3 = (B1s != nullptr);

    float acc[2][8][4];
#pragma unroll
    for (int mt = 0; mt < 2; mt++)
#pragma unroll
        for (int nt = 0; nt < 8; nt++)
#pragma unroll
            for (int q = 0; q < 4; q++) acc[mt][nt][q] = 0.f;

    const int nc = (K + 31) >> 5;
    for (int c = 0; c < nc; c++) {
        const int k0 = c << 5;
        if (c) __syncthreads();
#pragma unroll
        for (int it = 0; it < 2; it++) {
            const int idx = tid + it * 256;
            const int rr  = idx >> 2;
            const int cg  = (idx & 3) << 3;
            const bool kok = (k0 + cg) < K;
            uint4 qa = make_uint4(0, 0, 0, 0);
            const int gr = row0 + rr;
            if (gr < nrows && kok) {
                const int ri = rows ? __ldg(&rows[gr]) : gr;
                const float* ap = A + (size_t)ri * K + k0 + cg;
                float4 v0 = *reinterpret_cast<const float4*>(ap);
                float4 v1 = *reinterpret_cast<const float4*>(ap + 4);
                qa = pack8(v0, v1);
            }
            *reinterpret_cast<uint4*>(&As[rr * STRH + cg]) = qa;
            uint4 qb = make_uint4(0, 0, 0, 0);
            if (kok) {
                const size_t bo = (size_t)(col0 + rr) * K + k0 + cg;
                float4 w0 = *reinterpret_cast<const float4*>(B0s + bo);
                float4 w1 = *reinterpret_cast<const float4*>(B0s + bo + 4);
                if (has3) {
                    float4 a1 = *reinterpret_cast<const float4*>(B1s + bo);
                    float4 a2 = *reinterpret_cast<const float4*>(B1s + bo + 4);
                    float4 c1 = *reinterpret_cast<const float4*>(B2s + bo);
                    float4 c2 = *reinterpret_cast<const float4*>(B2s + bo + 4);
                    w0.x += a1.x + c1.x; w0.y += a1.y + c1.y;
                    w0.z += a1.z + c1.z; w0.w += a1.w + c1.w;
                    w1.x += a2.x + c2.x; w1.y += a2.y + c2.y;
                    w1.z += a2.z + c2.z; w1.w += a2.w + c2.w;
                }
                qb = pack8(w0, w1);
            }
            *reinterpret_cast<uint4*>(&Bs[rr * STRH + cg]) = qb;
        }
        __syncthreads();
#pragma unroll
        for (int ks = 0; ks < 2; ks++) {
            const int kb = ks << 4;
            uint32_t af[2][4];
#pragma unroll
            for (int mt = 0; mt < 2; mt++) {
                const int r = wm * 32 + mt * 16 + g4;
                const int base = r * STRH + kb + 2 * t4;
                af[mt][0] = *reinterpret_cast<const uint32_t*>(&As[base]);
                af[mt][1] = *reinterpret_cast<const uint32_t*>(&As[base + 8 * STRH]);
                af[mt][2] = *reinterpret_cast<const uint32_t*>(&As[base + 8]);
                af[mt][3] = *reinterpret_cast<const uint32_t*>(&As[base + 8 * STRH + 8]);
            }
#pragma unroll
            for (int nt = 0; nt < 8; nt++) {
                const int n = wn * 64 + nt * 8 + g4;
                const int bb = n * STRH + kb + 2 * t4;
                const uint32_t b0 = *reinterpret_cast<const uint32_t*>(&Bs[bb]);
                const uint32_t b1 = *reinterpret_cast<const uint32_t*>(&Bs[bb + 8]);
                mma_f16(acc[0][nt], af[0], b0, b1);
                mma_f16(acc[1][nt], af[1], b0, b1);
            }
        }
    }
#pragma unroll
    for (int mt = 0; mt < 2; mt++) {
#pragma unroll
        for (int h = 0; h < 2; h++) {
            const int gr = row0 + wm * 32 + mt * 16 + g4 + h * 8;
            if (gr >= nrows) continue;
            const int ro = rows ? __ldg(&rows[gr]) : gr;
#pragma unroll
            for (int nt = 0; nt < 8; nt++) {
                const int col = col0 + wn * 64 + nt * 8 + t4 * 2;
                float2 v = make_float2(acc[mt][nt][h * 2 + 0], acc[mt][nt][h * 2 + 1]);
                __half2 hv = __float22half2_rn(v);
                *reinterpret_cast<__half2*>(C + (size_t)ro * ldC + col) = hv;
            }
        }
    }
}

// indexed projections: fused 3, persistent row-tile loop, grid (2, YT, 3)
struct IdxP { const float* A; const float* B; __half* C; int K;
              const int* rows; const int* cntp; };
struct IdxP3 { IdxP d[3]; };
__global__ void __launch_bounds__(256) gemm_proj3(IdxP3 g) {
    __shared__ __align__(16) __half As[128 * STRH];
    __shared__ __align__(16) __half Bs[128 * STRH];
    const IdxP d = g.d[blockIdx.z];
    const int nrows = *d.cntp;
    for (int row0 = blockIdx.y * 128; row0 < nrows; row0 += gridDim.y * 128) {
        gemm_core_f32(d.A, d.B, nullptr, nullptr, d.C,
                      nrows, d.K, 256, row0, blockIdx.x * 128, d.rows, As, Bs);
        __syncthreads();
    }
}

// batched weight folds: ONE launch, grid (2,2,12)
struct FoldDesc { const float* A; const float* B0; const float* B1;
                  const float* B2; __half* C; int ldC; };
struct Fold12 { FoldDesc d[12]; };
__global__ void __launch_bounds__(256) gemm_fold(Fold12 args) {
    __shared__ __align__(16) __half As[128 * STRH];
    __shared__ __align__(16) __half Bs[128 * STRH];
    const FoldDesc f = args.d[blockIdx.z];
    gemm_core_f32(f.A, f.B0, f.B1, f.B2, f.C,
                  256, 256, f.ldC, blockIdx.y * 128, blockIdx.x * 128, nullptr, As, Bs);
}

// batched transposes (9 in one launch)
struct TPArgs { const float* in[9]; float* out[9]; int kin[9]; };
__global__ void transpose9(TPArgs a) {
    int z = blockIdx.z, k = blockIdx.x, n = threadIdx.x;
    if (k < a.kin[z])
        a.out[z][(size_t)n * a.kin[z] + k] = a.in[z][(size_t)k * 256 + n];
}

// batched bias folds (6 in one launch)
struct FoldB { const float* b1; const float* b2; const float* b3;
               const float* B; const float* blin; float* out; };
struct FoldB6 { FoldB d[6]; };
__global__ void fold_b6(FoldB6 a) {
    const FoldB f = a.d[blockIdx.x];
    int j = threadIdx.x;
    float acc = f.blin[j];
    for (int k = 0; k < Hc; k++) {
        float bb = f.b1[k];
        if (f.b2) bb += f.b2[k];
        if (f.b3) bb += f.b3[k];
        acc = fmaf(bb, f.B[k * Hc + j], acc);
    }
    f.out[j] = acc;
}

// =====================================================================
// frontier flags + CSR (scan-free)
// =====================================================================
// fused: last-node detection + last/A1 flags
__global__ void last_flag_k(const int* __restrict__ batch, int* __restrict__ last,
                            int* __restrict__ fLast, int* __restrict__ fA1, int N) {
    int i = blockIdx.x * blockDim.x + threadIdx.x;
    if (i < N) {
        if (i == N - 1 || batch[i + 1] != batch[i]) {
            last[batch[i]] = i;
            fLast[i] = 1;
            fA1[i] = 1;
        }
    }
}
// pass 1 (int4 vectorized): sources of edges into last-set
__global__ void prop1v(const int* __restrict__ sf, const int* __restrict__ df,
                       const int* __restrict__ sra, const int* __restrict__ dra,
                       const int* __restrict__ sta, const int* __restrict__ dta,
                       const int* __restrict__ fLast,
                       int* __restrict__ fA1, int* __restrict__ fR1,
                       int* __restrict__ fT1) {
    const int E4 = EE / 4;
    int i = blockIdx.x * blockDim.x + threadIdx.x;
    if (i >= 3 * E4) return;
    int r = i / E4, e4 = i - r * E4;
    const int *sp, *dp; int* fo;
    if (r == 0)      { sp = sf;  dp = df;  fo = fA1; }
    else if (r == 1) { sp = sra; dp = dra; fo = fR1; }
    else             { sp = sta; dp = dta; fo = fT1; }
    int4 d = reinterpret_cast<const int4*>(dp)[e4];
    int m0 = __ldg(&fLast[d.x]), m1 = __ldg(&fLast[d.y]);
    int m2 = __ldg(&fLast[d.z]), m3 = __ldg(&fLast[d.w]);
    if (m0 | m1 | m2 | m3) {
        int4 s = reinterpret_cast<const int4*>(sp)[e4];
        if (m0) fo[s.x] = 1;
        if (m1) fo[s.y] = 1;
        if (m2) fo[s.z] = 1;
        if (m3) fo[s.w] = 1;
    }
}
// pass 2 (int4) FUSED with filtered CSR count
__global__ void prop2cntv(const int* __restrict__ sf, const int* __restrict__ df,
                          const int* __restrict__ sra, const int* __restrict__ dra,
                          const int* __restrict__ sta, const int* __restrict__ dta,
                          const int* __restrict__ sar, const int* __restrict__ dar,
                          const int* __restrict__ sat, const int* __restrict__ dat,
                          const int* __restrict__ fA1, const int* __restrict__ fR1,
                          const int* __restrict__ fT1,
                          int* __restrict__ ib2, int* __restrict__ cnt) {
    const int E4 = EE / 4;
    int i = blockIdx.x * blockDim.x + threadIdx.x;
    if (i >= 5 * E4) return;
    int r = i / E4, e4 = i - r * E4;
    const int *sp, *dp, *fp; int base; size_t fof;
    switch (r) {
        case 0: sp = sf;  dp = df;  fp = fA1; base = B_F;  fof = F_LF;  break;
        case 1: sp = sra; dp = dra; fp = fA1; base = B_RA; fof = F_LRA; break;
        case 2: sp = sta; dp = dta; fp = fA1; base = B_TA; fof = F_LTA; break;
        case 3: sp = sar; dp = dar; fp = fR1; base = B_AR; fof = F_LAR; break;
        default: sp = sat; dp = dat; fp = fT1; base = B_AT; fof = F_LAT; break;
    }
    int4 d = reinterpret_cast<const int4*>(dp)[e4];
    int m0 = __ldg(&fp[d.x]), m1 = __ldg(&fp[d.y]);
    int m2 = __ldg(&fp[d.z]), m3 = __ldg(&fp[d.w]);
    if (m0 | m1 | m2 | m3) {
        int4 s = reinterpret_cast<const int4*>(sp)[e4];
        if (m0) { ib2[fof + s.x] = 1; atomicAdd(&cnt[base + d.x], 1); }
        if (m1) { ib2[fof + s.y] = 1; atomicAdd(&cnt[base + d.y], 1); }
        if (m2) { ib2[fof + s.z] = 1; atomicAdd(&cnt[base + d.z], 1); }
        if (m3) { ib2[fof + s.w] = 1; atomicAdd(&cnt[base + d.w], 1); }
    }
}
// scan-free segment allocation: offs/cur from counts via global cursor
__global__ void seg_alloc(const int* __restrict__ cnt, int* __restrict__ offs,
                          int* __restrict__ cur, int* __restrict__ gcur) {
    int i = blockIdx.x * blockDim.x + threadIdx.x;
    if (i >= CSR_N) return;
    int c = cnt[i];
    if (c > 0) {
        int p = atomicAdd(gcur, c);
        offs[i] = p;
        cur[i] = p;
    }
}
// filtered fill (int4)
__global__ void fill5fv(const int* __restrict__ sf, const int* __restrict__ df,
                        const int* __restrict__ sra, const int* __restrict__ dra,
                        const int* __restrict__ sta, const int* __restrict__ dta,
                        const int* __restrict__ sar, const int* __restrict__ dar,
                        const int* __restrict__ sat, const int* __restrict__ dat,
                        const int* __restrict__ fA1, const int* __restrict__ fR1,
                        const int* __restrict__ fT1,
                        int* __restrict__ cur, int* __restrict__ idx) {
    const int E4 = EE / 4;
    int i = blockIdx.x * blockDim.x + threadIdx.x;
    if (i >= 5 * E4) return;
    int r = i / E4, e4 = i - r * E4;
    const int *sp, *dp, *fp; int base;
    switch (r) {
        case 0: sp = sf;  dp = df;  fp = fA1; base = B_F;  break;
        case 1: sp = sra; dp = dra; fp = fA1; base = B_RA; break;
        case 2: sp = sta; dp = dta; fp = fA1; base = B_TA; break;
        case 3: sp = sar; dp = dar; fp = fR1; base = B_AR; break;
        default: sp = sat; dp = dat; fp = fT1; base = B_AT; break;
    }
    int4 d = reinterpret_cast<const int4*>(dp)[e4];
    int m0 = __ldg(&fp[d.x]), m1 = __ldg(&fp[d.y]);
    int m2 = __ldg(&fp[d.z]), m3 = __ldg(&fp[d.w]);
    if (m0 | m1 | m2 | m3) {
        int4 s = reinterpret_cast<const int4*>(sp)[e4];
        if (m0) { int p = atomicAdd(&cur[base + d.x], 1); idx[p] = s.x; }
        if (m1) { int p = atomicAdd(&cur[base + d.y], 1); idx[p] = s.y; }
        if (m2) { int p = atomicAdd(&cur[base + d.z], 1); idx[p] = s.z; }
        if (m3) { int p = atomicAdd(&cur[base + d.w], 1); idx[p] = s.w; }
    }
}
// compact all flags into 11 lists
__global__ void compact11(int* __restrict__ ib2) {
    int i = blockIdx.x * blockDim.x + threadIdx.x;
    if (i >= NACT + NRES + NTIME) return;
    if (i < NACT) {
        int a1  = ib2[F_A1  + i];
        int lf  = ib2[F_LF  + i];
        int lar = ib2[F_LAR + i];
        int lat = ib2[F_LAT + i];
        if (a1)  { int p = atomicAdd(&ib2[CTRS + 0],  1); ib2[L_A1  + p] = i; }
        if (lf)  { int p = atomicAdd(&ib2[CTRS + 6],  1); ib2[L_LF  + p] = i; }
        if (lar) { int p = atomicAdd(&ib2[CTRS + 7],  1); ib2[L_LAR + p] = i; }
        if (lat) { int p = atomicAdd(&ib2[CTRS + 8],  1); ib2[L_LAT + p] = i; }
        if (a1 | lf | lar | lat) {
            int p = atomicAdd(&ib2[CTRS + 3], 1); ib2[L_PA + p] = i;
        }
    } else if (i < NACT + NRES) {
        int n = i - NACT;
        int r1  = ib2[F_R1  + n];
        int lra = ib2[F_LRA + n];
        if (r1)  { int p = atomicAdd(&ib2[CTRS + 1],  1); ib2[L_R1  + p] = n; }
        if (lra) { int p = atomicAdd(&ib2[CTRS + 9],  1); ib2[L_LRA + p] = n; }
        if (r1 | lra) {
            int p = atomicAdd(&ib2[CTRS + 4], 1); ib2[L_PR + p] = n;
        }
    } else {
        int n = i - NACT - NRES;
        int t1  = ib2[F_T1  + n];
        int lta = ib2[F_LTA + n];
        if (t1)  { int p = atomicAdd(&ib2[CTRS + 2],  1); ib2[L_T1  + p] = n; }
        if (lta) { int p = atomicAdd(&ib2[CTRS + 10], 1); ib2[L_LTA + p] = n; }
        if (t1 | lta) {
            int p = atomicAdd(&ib2[CTRS + 5], 1); ib2[L_PT + p] = n;
        }
    }
}

// =====================================================================
// gathers (offs + cnt segments)
// =====================================================================
__device__ __forceinline__ void accum_rel(const __half* __restrict__ base, int stride,
                                          const int* __restrict__ offs,
                                          const int* __restrict__ cnt,
                                          const int* __restrict__ idx,
                                          int w, int lane, float* a) {
    int c = __ldg(&cnt[w]);
    if (c <= 0) return;
    int s = __ldg(&offs[w]);
    float sc = 1.f / (float)c;
    float m[8] = {0.f, 0.f, 0.f, 0.f, 0.f, 0.f, 0.f, 0.f};
    for (int p = s; p < s + c; p++) {
        int sn = __ldg(&idx[p]);
        uint4 q = *reinterpret_cast<const uint4*>(base + (size_t)sn * stride + lane * 8);
        float f[8];
        h8_to_f8(q, f);
#pragma unroll
        for (int j = 0; j < 8; j++) m[j] += f[j];
    }
#pragma unroll
    for (int j = 0; j < 8; j++) a[j] += m[j] * sc;
}

// layer-0 gather over frontier lists, persistent warps
__global__ void __launch_bounds__(256) gather_idx(
        const __half* __restrict__ Pa, const __half* __restrict__ Pr,
        const __half* __restrict__ Pt,
        const int* __restrict__ offs, const int* __restrict__ cnt,
        const int* __restrict__ idx, const int* __restrict__ ib2,
        __half* __restrict__ A, __half* __restrict__ R, __half* __restrict__ T) {
    const int lane = threadIdx.x & 31;
    const int cA = __ldg(&ib2[CTRS + 0]);
    const int cR = __ldg(&ib2[CTRS + 1]);
    const int cT = __ldg(&ib2[CTRS + 2]);
    const int total = cA + cR + cT;
    const int wstep = gridDim.x * 8;
    for (int w = blockIdx.x * 8 + (threadIdx.x >> 5); w < total; w += wstep) {
        float a[8];
        if (w < cA) {
            int u = __ldg(&ib2[L_A1 + w]);
            h8_to_f8(*reinterpret_cast<const uint4*>(Pa + (size_t)u * 1024 + 768 + lane * 8), a);
            accum_rel(Pa, 1024, offs + B_F,  cnt + B_F,  idx, u, lane, a);
            accum_rel(Pr, 512,  offs + B_RA, cnt + B_RA, idx, u, lane, a);
            accum_rel(Pt, 512,  offs + B_TA, cnt + B_TA, idx, u, lane, a);
#pragma unroll
            for (int j = 0; j < 8; j++) a[j] = fmaxf(a[j], 0.f);
            *reinterpret_cast<uint4*>(A + (size_t)u * 256 + lane * 8) = f8_to_h8(a);
        } else if (w < cA + cR) {
            int v = __ldg(&ib2[L_R1 + (w - cA)]);
            h8_to_f8(*reinterpret_cast<const uint4*>(Pr + (size_t)v * 512 + 256 + lane * 8), a);
            accum_rel(Pa + 256, 1024, offs + B_AR, cnt + B_AR, idx, v, lane, a);
#pragma unroll
            for (int j = 0; j < 8; j++) a[j] = fmaxf(a[j], 0.f);
            *reinterpret_cast<uint4*>(R + (size_t)v * 256 + lane * 8) = f8_to_h8(a);
        } else {
            int v = __ldg(&ib2[L_T1 + (w - cA - cR)]);
            h8_to_f8(*reinterpret_cast<const uint4*>(Pt + (size_t)v * 512 + 256 + lane * 8), a);
            accum_rel(Pa + 512, 1024, offs + B_AT, cnt + B_AT, idx, v, lane, a);
#pragma unroll
            for (int j = 0; j < 8; j++) a[j] = fmaxf(a[j], 0.f);
            *reinterpret_cast<uint4*>(T + (size_t)v * 256 + lane * 8) = f8_to_h8(a);
        }
    }
}

// layer-1 pooled gather
__global__ void __launch_bounds__(256) gather_pool(
        const __half* __restrict__ A, const __half* __restrict__ R,
        const __half* __restrict__ T,
        const int* __restrict__ offs, const int* __restrict__ cnt,
        const int* __restrict__ idx,
        const int* __restrict__ last, __half* __restrict__ X2) {
    int w = (blockIdx.x * 256 + threadIdx.x) >> 5;
    int lane = threadIdx.x & 31;
    if (w >= 4 * GG) return;
    int g = w >> 2, s = w & 3;
    int nid = __ldg(&last[g]);
    float a[8] = {0.f, 0.f, 0.f, 0.f, 0.f, 0.f, 0.f, 0.f};
    if (s == 0)      accum_rel(A, 256, offs + B_F,  cnt + B_F,  idx, nid, lane, a);
    else if (s == 1) accum_rel(R, 256, offs + B_RA, cnt + B_RA, idx, nid, lane, a);
    else if (s == 2) accum_rel(T, 256, offs + B_TA, cnt + B_TA, idx, nid, lane, a);
    else h8_to_f8(*reinterpret_cast<const uint4*>(A + (size_t)nid * 256 + lane * 8), a);
    *reinterpret_cast<uint4*>(X2 + (size_t)g * 1024 + s * 256 + lane * 8) = f8_to_h8(a);
}

// =====================================================================
// heads
// =====================================================================
__global__ void heads_k(const __half* __restrict__ a2,
                        const float* __restrict__ Wo, const float* __restrict__ bo,
                        const float* __restrict__ Wt, const float* __restrict__ bt,
                        const float* __restrict__ Wrm, const float* __restrict__ brm,
                        float* __restrict__ out) {
    int g = blockIdx.x;
    __shared__ float p[Hc];
    const __half* row = a2 + (size_t)g * Hc;
    for (int k = threadIdx.x; k < Hc; k += blockDim.x) p[k] = __half2float(row[k]);
    __syncthreads();
    int j = threadIdx.x;
    if (j < CC) {
        float acc = bo[j];
        for (int k = 0; k < Hc; k++) acc = fmaf(p[k], Wo[k * CC + j], acc);
        out[g * CC + j] = acc;
    } else if (j == CC) {
        float acc = bt[0];
        for (int k = 0; k < Hc; k++) acc = fmaf(p[k], Wt[k], acc);
        out[GG * CC + g] = acc;
    } else if (j == CC + 1) {
        float acc = brm[0];
        for (int k = 0; k < Hc; k++) acc = fmaf(p[k], Wrm[k], acc);
        out[GG * CC + GG + g] = acc;
    }
}

// =====================================================================
// host orchestration
// =====================================================================
extern "C" void kernel_launch(void* const* d_in, const int* in_sizes, int n_in,
                              void* d_out, int out_size) {
    float* buf = nullptr;
    cudaGetSymbolAddress((void**)&buf, g_buf);

    __half* A  = reinterpret_cast<__half*>(buf + OFF_A);
    __half* R  = reinterpret_cast<__half*>(buf + OFF_R);
    __half* T  = reinterpret_cast<__half*>(buf + OFF_T);
    __half* Pa = reinterpret_cast<__half*>(buf + OFF_PA);
    __half* Pr = reinterpret_cast<__half*>(buf + OFF_PR);
    __half* Pt = reinterpret_cast<__half*>(buf + OFF_PT);
    __half* X2 = Pr;
    __half* A2 = Pt;
    __half* WCh = reinterpret_cast<__half*>(buf + OFF_WC);
    __half* WB2 = WCh + 524288;
    float* BF  = buf + OFF_BF;
    float* WLT = buf + OFF_WLT;
    float* WPT = buf + OFF_WPT;
    int*   LAST = reinterpret_cast<int*>(buf + OFF_LAST);
    int*   IB   = reinterpret_cast<int*>(buf + OFF_INT);
    int*   IB2  = reinterpret_cast<int*>(buf + OFF_INT2);
    int* offs = IB + IO_OFFS;
    int* cnt  = IB + IO_CNT;
    int* cur  = IB + IO_CUR;
    int* idx  = IB + IO_IDX;

    const float* x_act  = (const float*)d_in[0];
    const float* x_res  = (const float*)d_in[1];
    const float* x_time = (const float*)d_in[2];
    const int* src_f  = (const int*)d_in[3];
    const int* dst_f  = (const int*)d_in[4];
    const int* src_ar = (const int*)d_in[5];
    const int* dst_ar = (const int*)d_in[6];
    const int* src_ra = (const int*)d_in[7];
    const int* dst_ra = (const int*)d_in[8];
    const int* src_at = (const int*)d_in[9];
    const int* dst_at = (const int*)d_in[10];
    const int* src_ta = (const int*)d_in[11];
    const int* dst_ta = (const int*)d_in[12];
    const int* batch  = (const int*)d_in[13];

    int w = (in_sizes[14] <= 4) ? 15 : 14;
    const float* Wp_act = (const float*)d_in[w + 0];
    const float* Wp_res = (const float*)d_in[w + 1];
    const float* Wp_tim = (const float*)d_in[w + 2];
    const float* Wl     = (const float*)d_in[w + 3];
    const float* bl     = (const float*)d_in[w + 4];
    const float* Wr     = (const float*)d_in[w + 5];
    const float* Wlin   = (const float*)d_in[w + 6];
    const float* blin   = (const float*)d_in[w + 7];
    const float* Wo     = (const float*)d_in[w + 8];
    const float* bo     = (const float*)d_in[w + 9];
    const float* Wt     = (const float*)d_in[w + 10];
    const float* bt     = (const float*)d_in[w + 11];
    const float* Wrm    = (const float*)d_in[w + 12];
    const float* brm    = (const float*)d_in[w + 13];

    const size_t HH = 65536;  // 256*256

    // --- zero flags, counters, CSR counts, LAST ---
    cudaMemsetAsync(IB2, 0, FLAGS_END * sizeof(int), 0);
    cudaMemsetAsync(IB2 + CTRS, 0, 16 * sizeof(int), 0);
    cudaMemsetAsync(cnt, 0, CSR_N * sizeof(int), 0);
    cudaMemsetAsync(LAST, 0, GG * sizeof(int), 0);

    // --- fused transposes ---
    {
        TPArgs tp;
        tp.in[0] = Wp_act; tp.out[0] = WPT + 0;     tp.kin[0] = 64;
        tp.in[1] = Wp_res; tp.out[1] = WPT + 16384; tp.kin[1] = 32;
        tp.in[2] = Wp_tim; tp.out[2] = WPT + 24576; tp.kin[2] = 16;
        for (int i = 0; i < 6; i++) {
            tp.in[3 + i]  = Wlin + (size_t)i * HH;
            tp.out[3 + i] = WLT + (size_t)i * HH;
            tp.kin[3 + i] = 256;
        }
        transpose9<<<dim3(256, 1, 9), 256>>>(tp);
    }

    // --- fused weight folds: 8 (l=0) + 4 (l=1 concat-K) ---
    {
        Fold12 fa;
        {
            const float* lt0 = WLT + 0 * HH;
            const float* lt1 = WLT + 1 * HH;
            const float* lt2 = WLT + 2 * HH;
            __half* WCa = WCh;
            __half* WCr = WCa + 262144;
            __half* WCt = WCr + 131072;
            fa.d[0] = {lt0, Wl + 0 * HH, nullptr, nullptr, WCa + 0,      256};
            fa.d[1] = {lt1, Wl + 1 * HH, nullptr, nullptr, WCa + 65536,  256};
            fa.d[2] = {lt2, Wl + 3 * HH, nullptr, nullptr, WCa + 131072, 256};
            fa.d[3] = {lt0, Wr + 0 * HH, Wr + 2 * HH, Wr + 4 * HH, WCa + 196608, 256};
            fa.d[4] = {lt0, Wl + 2 * HH, nullptr, nullptr, WCr + 0,      256};
            fa.d[5] = {lt1, Wr + 1 * HH, nullptr, nullptr, WCr + 65536,  256};
            fa.d[6] = {lt0, Wl + 4 * HH, nullptr, nullptr, WCt + 0,      256};
            fa.d[7] = {lt2, Wr + 3 * HH, nullptr, nullptr, WCt + 65536,  256};
        }
        {
            const float* lt0 = WLT + 3 * HH;
            fa.d[8]  = {lt0, Wl + 5 * HH, nullptr, nullptr, WB2 + 0,   1024};
            fa.d[9]  = {lt0, Wl + 7 * HH, nullptr, nullptr, WB2 + 256, 1024};
            fa.d[10] = {lt0, Wl + 9 * HH, nullptr, nullptr, WB2 + 512, 1024};
            fa.d[11] = {lt0, Wr + 5 * HH, Wr + 7 * HH, Wr + 9 * HH, WB2 + 768, 1024};
        }
        gemm_fold<<<dim3(2, 2, 12), 256>>>(fa);

        FoldB6 fb;
        for (int l = 0; l < 2; l++) {
            fb.d[l * 3 + 0] = {bl + (l * 5 + 0) * 256, bl + (l * 5 + 2) * 256,
                               bl + (l * 5 + 4) * 256, Wlin + (size_t)(l * 3 + 0) * HH,
                               blin + (l * 3 + 0) * 256, BF + l * 768 + 0};
            fb.d[l * 3 + 1] = {bl + (l * 5 + 1) * 256, nullptr, nullptr,
                               Wlin + (size_t)(l * 3 + 1) * HH,
                               blin + (l * 3 + 1) * 256, BF + l * 768 + 256};
            fb.d[l * 3 + 2] = {bl + (l * 5 + 3) * 256, nullptr, nullptr,
                               Wlin + (size_t)(l * 3 + 2) * HH,
                               blin + (l * 3 + 2) * 256, BF + l * 768 + 512};
        }
        fold_b6<<<6, 256>>>(fb);
    }

    // --- frontier flags + scan-free CSR ---
    last_flag_k<<<(NACT + 255) / 256, 256>>>(batch, LAST, IB2 + F_LAST,
                                             IB2 + F_A1, NACT);
    prop1v<<<(3 * EE / 4 + 255) / 256, 256>>>(src_f, dst_f, src_ra, dst_ra,
                                              src_ta, dst_ta, IB2 + F_LAST,
                                              IB2 + F_A1, IB2 + F_R1, IB2 + F_T1);
    {
        int nb4 = (5 * EE / 4 + 255) / 256;
        prop2cntv<<<nb4, 256>>>(src_f, dst_f, src_ra, dst_ra, src_ta, dst_ta,
                                src_ar, dst_ar, src_at, dst_at,
                                IB2 + F_A1, IB2 + F_R1, IB2 + F_T1, IB2, cnt);
        compact11<<<(NACT + NRES + NTIME + 255) / 256, 256>>>(IB2);
        seg_alloc<<<(CSR_N + 255) / 256, 256>>>(cnt, offs, cur, IB2 + CTRS + 11);
        fill5fv<<<nb4, 256>>>(src_f, dst_f, src_ra, dst_ra, src_ta, dst_ta,
                              src_ar, dst_ar, src_at, dst_at,
                              IB2 + F_A1, IB2 + F_R1, IB2 + F_T1, cur, idx);
    }

    // --- frontier-restricted projections (fused 3, persistent) ---
    {
        IdxP3 p;
        p.d[0] = {x_act,  WPT + 0,     A, 64, IB2 + L_PA, IB2 + CTRS + 3};
        p.d[1] = {x_res,  WPT + 16384, R, 32, IB2 + L_PR, IB2 + CTRS + 4};
        p.d[2] = {x_time, WPT + 24576, T, 16, IB2 + L_PT, IB2 + CTRS + 5};
        gemm_proj3<<<dim3(2, 32, 3), 256>>>(p);
    }

    // --- layer 0: per-section indexed GEMMs (persistent) + gather ---
    {
        __half* WCa = WCh;
        __half* WCr = WCa + 262144;
        __half* WCt = WCr + 131072;
        IdxG8 g;
        g.d[0] = {A, WCa + 0,      BF,       NOBIAS, Pa + 0,   1024, IB2 + L_LF,  IB2 + CTRS + 6};
        g.d[1] = {A, WCa + 65536,  BF,       NOBIAS, Pa + 256, 1024, IB2 + L_LAR, IB2 + CTRS + 7};
        g.d[2] = {A, WCa + 131072, BF,       NOBIAS, Pa + 512, 1024, IB2 + L_LAT, IB2 + CTRS + 8};
        g.d[3] = {A, WCa + 196608, BF + 0,   0,      Pa + 768, 1024, IB2 + L_A1,  IB2 + CTRS + 0};
        g.d[4] = {R, WCr + 0,      BF,       NOBIAS, Pr + 0,   512,  IB2 + L_LRA, IB2 + CTRS + 9};
        g.d[5] = {R, WCr + 65536,  BF + 256, 0,      Pr + 256, 512,  IB2 + L_R1,  IB2 + CTRS + 1};
        g.d[6] = {T, WCt + 0,      BF,       NOBIAS, Pt + 0,   512,  IB2 + L_LTA, IB2 + CTRS + 10};
        g.d[7] = {T, WCt + 65536,  BF + 512, 0,      Pt + 256, 512,  IB2 + L_T1,  IB2 + CTRS + 2};
        gemm_sec8<<<dim3(2, 64, 8), 256>>>(g);

        gather_idx<<<256, 256>>>(Pa, Pr, Pt, offs, cnt, idx, IB2, A, R, T);
    }

    // --- layer 1: pooled aggregate-then-project (512 rows) ---
    {
        gather_pool<<<(4 * GG * 32 + 255) / 256, 256>>>(A, R, T, offs, cnt, idx,
                                                        LAST, X2);
        Gemm3 g;
        g.d[0] = {X2, WB2, BF + 768, A2, 0, GG, 256, 2, 1024, 1};
        g.d[1] = g.d[0]; g.d[2] = g.d[0];
        g.n0 = 8; g.n01 = 8;
        gemm_fast3<<<8, 256>>>(g);
    }

    // --- heads ---
    heads_k<<<GG, 64>>>(A2, Wo, bo, Wt, bt, Wrm, brm, (float*)d_out);
}

// round 17
// speedup vs baseline: 49.9572x; 1.1684x over previous
#include <cuda_runtime.h>
#include <cuda_fp16.h>
#include <cstdint>
#include <cstddef>

#define Hc    256
#define CC    50
#define GG    512
#define NACT  200000
#define NRES  20000
#define NTIME 100000
#define EE    400000

// ---------------- scratch layout (float units) ----------------
static constexpr size_t OFF_A    = 0;            // 200000*256 h (layer-1 act feats)
static constexpr size_t OFF_R    = 25600000;     // 20000*256 h
static constexpr size_t OFF_T    = 28160000;     // 100000*256 h
static constexpr size_t OFF_PA   = 40960000;     // 200000*1024 h [f|ar|at|self]
static constexpr size_t OFF_PR   = 143360000;    // 20000*512 h   (reused: X2)
static constexpr size_t OFF_PT   = 148480000;    // 100000*512 h  (reused: A2)
static constexpr size_t OFF_WC   = 174080000;    // WB2 fp16 (256*1024 h)
static constexpr size_t OFF_BF   = 175128576;    // 2*3*256 f32
static constexpr size_t OFF_WLT  = 175130112;    // 6*65536 f32 Wlin^T
static constexpr size_t OFF_LAST = 175552000;    // 512 ints
static constexpr size_t OFF_INT  = 175552512;    // CSR int scratch
static constexpr size_t OFF_INT2 = 179752512;    // frontier int scratch
static constexpr size_t OFF_WCF  = 182352528;    // 8*65536 f32 stage-1 folds
static constexpr size_t OFF_BFW  = 182876816;    // 90112 f32 stage-2 fused weights
static constexpr size_t TOTALF   = 182976000;

// unified CSR (ints, relative to OFF_INT)
static constexpr int CSR_N = 720000;
static constexpr int B_F  = 0;
static constexpr int B_RA = 200000;
static constexpr int B_TA = 400000;
static constexpr int B_AR = 600000;
static constexpr int B_AT = 620000;
static constexpr size_t IO_OFFS = 0;          // 720004
static constexpr size_t IO_CNT  = 720004;     // 720000
static constexpr size_t IO_CUR  = 1440004;    // 720000
static constexpr size_t IO_IDX  = 2160004;    // 2,000,000

// frontier region (ints, relative to OFF_INT2)
static constexpr size_t F_A1   = 200000;     // 200000
static constexpr size_t F_R1   = 400000;     // 20000
static constexpr size_t F_T1   = 420000;     // 100000
static constexpr size_t F_LF   = 520000;     // 200000
static constexpr size_t F_LAR  = 720000;     // 200000
static constexpr size_t F_LAT  = 920000;     // 200000
static constexpr size_t F_LRA  = 1120000;    // 20000
static constexpr size_t F_LTA  = 1140000;    // 100000
static constexpr size_t FLAGS_END = 1240000;
static constexpr size_t L_A1   = 1240000;
static constexpr size_t L_R1   = 1440000;
static constexpr size_t L_T1   = 1460000;
static constexpr size_t L_LF   = 1560000;
static constexpr size_t L_LAR  = 1760000;
static constexpr size_t L_LAT  = 1960000;
static constexpr size_t L_LRA  = 2160000;
static constexpr size_t L_LTA  = 2180000;
static constexpr size_t L_PA   = 2280000;    // (unused now, kept for layout)
static constexpr size_t CTRS   = 2600000;    // 16
// counters: 0:A1 1:R1 2:T1 3..5:unused 6:LF 7:LAR 8:LAT 9:LRA 10:LTA 11:gcur

__device__ float g_buf[TOTALF];

// =====================================================================
// helpers
// =====================================================================
__device__ __forceinline__ void mma_f16(float* d, const uint32_t* a,
                                        uint32_t b0, uint32_t b1) {
    asm volatile(
        "mma.sync.aligned.m16n8k16.row.col.f32.f16.f16.f32 "
        "{%0,%1,%2,%3}, {%4,%5,%6,%7}, {%8,%9}, {%0,%1,%2,%3};"
        : "+f"(d[0]), "+f"(d[1]), "+f"(d[2]), "+f"(d[3])
        : "r"(a[0]), "r"(a[1]), "r"(a[2]), "r"(a[3]), "r"(b0), "r"(b1));
}
__device__ __forceinline__ void ldsm4(uint32_t* r, uint32_t addr) {
    asm volatile("ldmatrix.sync.aligned.m8n8.x4.shared.b16 {%0,%1,%2,%3}, [%4];"
                 : "=r"(r[0]), "=r"(r[1]), "=r"(r[2]), "=r"(r[3]) : "r"(addr));
}
__device__ __forceinline__ void cp16(uint32_t dst, const void* src, int szbytes) {
    asm volatile("cp.async.cg.shared.global [%0], [%1], 16, %2;"
                 :: "r"(dst), "l"(src), "r"(szbytes));
}
#define CP_COMMIT() asm volatile("cp.async.commit_group;" ::: "memory")
template <int N>
__device__ __forceinline__ void cp_wait() {
    asm volatile("cp.async.wait_group %0;" :: "n"(N) : "memory");
}
__device__ __forceinline__ uint32_t saddr(const void* p) {
    return static_cast<uint32_t>(__cvta_generic_to_shared(p));
}
__device__ __forceinline__ uint32_t packh2(float x, float y) {
    __half2 h = __float22half2_rn(make_float2(x, y));
    return *reinterpret_cast<uint32_t*>(&h);
}
__device__ __forceinline__ uint4 pack8(float4 a, float4 b) {
    return make_uint4(packh2(a.x, a.y), packh2(a.z, a.w),
                      packh2(b.x, b.y), packh2(b.z, b.w));
}
__device__ __forceinline__ void h8_to_f8(uint4 q, float* f) {
    const __half2* h = reinterpret_cast<const __half2*>(&q);
#pragma unroll
    for (int i = 0; i < 4; i++) {
        float2 t = __half22float2(h[i]);
        f[2 * i] = t.x; f[2 * i + 1] = t.y;
    }
}
__device__ __forceinline__ uint4 f8_to_h8(const float* f) {
    return make_uint4(packh2(f[0], f[1]), packh2(f[2], f[3]),
                      packh2(f[4], f[5]), packh2(f[6], f[7]));
}

#define STRH 40
#define NOBIAS (1 << 30)

// =====================================================================
// fused fp16 GEMM (pooled layer-1): up to 3 sub-GEMMs, runtime K, relu
// =====================================================================
struct GemmDesc {
    const __half* A; const __half* B; const float* bias;
    __half* C; int bstart; int Nrow; int ldC; int colT; int K; int relu;
};
struct Gemm3 { GemmDesc d[3]; int n0, n01; };

__global__ void __launch_bounds__(256) gemm_fast3(Gemm3 g) {
    __shared__ __align__(16) __half As[2][128 * STRH];
    __shared__ __align__(16) __half Bs[2][128 * STRH];
    const int id = blockIdx.x;
    const int zi = (id < g.n0) ? 0 : ((id < g.n01) ? 1 : 2);
    const int rid = id - ((zi == 0) ? 0 : ((zi == 1) ? g.n0 : g.n01));
    const GemmDesc d = g.d[zi];
    const int row0 = (rid / d.colT) * 128;
    const int col0 = (rid % d.colT) * 128;
    const int Nrow = d.Nrow;
    const int K = d.K;
    const __half* __restrict__ A = d.A;
    const __half* __restrict__ B = d.B;

    const int tid  = threadIdx.x;
    const int lane = tid & 31;
    const int wid  = tid >> 5;
    const int wm   = wid & 3;
    const int wn   = wid >> 2;
    const int t4   = lane & 3;
    const int g4   = lane >> 2;
    const int arow = lane & 15;
    const int acol = (lane >> 4) << 3;
    const int brow = (lane & 7) + ((lane >> 4) << 3);
    const int bcol = ((lane >> 3) & 1) << 3;

    float acc[2][8][4];
#pragma unroll
    for (int mt = 0; mt < 2; mt++)
#pragma unroll
        for (int nt = 0; nt < 8; nt++)
#pragma unroll
            for (int q = 0; q < 4; q++) acc[mt][nt][q] = 0.f;

    auto stage = [&](int c, int b) {
        const int k0 = c << 5;
#pragma unroll
        for (int it = 0; it < 2; it++) {
            const int i  = tid + it * 256;
            const int rr = i >> 2;
            const int sg = (i & 3) << 3;
            const int gr = row0 + rr;
            const int grc = gr < Nrow ? gr : (Nrow - 1);
            cp16(saddr(&As[b][rr * STRH + sg]),
                 A + (size_t)grc * K + k0 + sg, gr < Nrow ? 16 : 0);
            cp16(saddr(&Bs[b][rr * STRH + sg]),
                 B + (size_t)(col0 + rr) * K + k0 + sg, 16);
        }
    };

    stage(0, 0);
    CP_COMMIT();
    const int nc = K >> 5;
#pragma unroll 1
    for (int c = 0; c < nc; c++) {
        const int cb = c & 1;
        if (c + 1 < nc) { stage(c + 1, cb ^ 1); CP_COMMIT(); cp_wait<1>(); }
        else            { cp_wait<0>(); }
        __syncthreads();
#pragma unroll
        for (int ks = 0; ks < 2; ks++) {
            const int kb = ks << 4;
            uint32_t af[2][4];
#pragma unroll
            for (int mt = 0; mt < 2; mt++)
                ldsm4(af[mt], saddr(&As[cb][(wm * 32 + mt * 16 + arow) * STRH + kb + acol]));
            uint32_t bf[4][4];
#pragma unroll
            for (int p = 0; p < 4; p++)
                ldsm4(bf[p], saddr(&Bs[cb][(wn * 64 + p * 16 + brow) * STRH + kb + bcol]));
#pragma unroll
            for (int nt = 0; nt < 8; nt++) {
                const uint32_t b0 = bf[nt >> 1][(nt & 1) * 2];
                const uint32_t b1 = bf[nt >> 1][(nt & 1) * 2 + 1];
                mma_f16(acc[0][nt], af[0], b0, b1);
                mma_f16(acc[1][nt], af[1], b0, b1);
            }
        }
        __syncthreads();
    }
#pragma unroll
    for (int mt = 0; mt < 2; mt++) {
#pragma unroll
        for (int h = 0; h < 2; h++) {
            const int gr = row0 + wm * 32 + mt * 16 + g4 + h * 8;
            if (gr >= Nrow) continue;
#pragma unroll
            for (int nt = 0; nt < 8; nt++) {
                const int col = col0 + wn * 64 + nt * 8 + t4 * 2;
                float2 v = make_float2(acc[mt][nt][h * 2 + 0], acc[mt][nt][h * 2 + 1]);
                if (col >= d.bstart) {
                    v.x += __ldg(&d.bias[col - d.bstart]);
                    v.y += __ldg(&d.bias[col - d.bstart + 1]);
                }
                if (d.relu) { v.x = fmaxf(v.x, 0.f); v.y = fmaxf(v.y, 0.f); }
                __half2 hv = __float22half2_rn(v);
                *reinterpret_cast<__half2*>(d.C + (size_t)gr * d.ldC + col) = hv;
            }
        }
    }
}

// =====================================================================
// GENERIC GEMM core: f32 A + f32 B (staged to fp16 smem), optional:
// row index list, bias (cols >= bstart), f32 or f16 output, col clip,
// B row clip (zero-fill rows >= bRows).
// =====================================================================
__device__ __forceinline__ void gemm_core_f32(
        const float* __restrict__ A,
        const float* __restrict__ B0s, const float* __restrict__ B1s,
        const float* __restrict__ B2s,
        const float* __restrict__ bias, int bstart,
        __half* __restrict__ C, float* __restrict__ Cf,
        int nrows, int K, int ldC, int ncols, int bRows,
        int row0, int col0,
        const int* __restrict__ rows,
        __half* As, __half* Bs) {
    const int tid  = threadIdx.x;
    const int lane = tid & 31;
    const int wid  = tid >> 5;
    const int wm   = wid & 3;
    const int wn   = wid >> 2;
    const int g4   = lane >> 2;
    const int t4   = lane & 3;
    const bool has3 = (B1s != nullptr);

    float acc[2][8][4];
#pragma unroll
    for (int mt = 0; mt < 2; mt++)
#pragma unroll
        for (int nt = 0; nt < 8; nt++)
#pragma unroll
            for (int q = 0; q < 4; q++) acc[mt][nt][q] = 0.f;

    const int nc = (K + 31) >> 5;
    for (int c = 0; c < nc; c++) {
        const int k0 = c << 5;
        if (c) __syncthreads();
#pragma unroll
        for (int it = 0; it < 2; it++) {
            const int idx = tid + it * 256;
            const int rr  = idx >> 2;
            const int cg  = (idx & 3) << 3;
            const bool kok = (k0 + cg) < K;
            uint4 qa = make_uint4(0, 0, 0, 0);
            const int gr = row0 + rr;
            if (gr < nrows && kok) {
                const int ri = rows ? __ldg(&rows[gr]) : gr;
                const float* ap = A + (size_t)ri * K + k0 + cg;
                float4 v0 = *reinterpret_cast<const float4*>(ap);
                float4 v1 = *reinterpret_cast<const float4*>(ap + 4);
                qa = pack8(v0, v1);
            }
            *reinterpret_cast<uint4*>(&As[rr * STRH + cg]) = qa;
            uint4 qb = make_uint4(0, 0, 0, 0);
            if (kok && (col0 + rr) < bRows) {
                const size_t bo = (size_t)(col0 + rr) * K + k0 + cg;
                float4 w0 = *reinterpret_cast<const float4*>(B0s + bo);
                float4 w1 = *reinterpret_cast<const float4*>(B0s + bo + 4);
                if (has3) {
                    float4 a1 = *reinterpret_cast<const float4*>(B1s + bo);
                    float4 a2 = *reinterpret_cast<const float4*>(B1s + bo + 4);
                    float4 c1 = *reinterpret_cast<const float4*>(B2s + bo);
                    float4 c2 = *reinterpret_cast<const float4*>(B2s + bo + 4);
                    w0.x += a1.x + c1.x; w0.y += a1.y + c1.y;
                    w0.z += a1.z + c1.z; w0.w += a1.w + c1.w;
                    w1.x += a2.x + c2.x; w1.y += a2.y + c2.y;
                    w1.z += a2.z + c2.z; w1.w += a2.w + c2.w;
                }
                qb = pack8(w0, w1);
            }
            *reinterpret_cast<uint4*>(&Bs[rr * STRH + cg]) = qb;
        }
        __syncthreads();
#pragma unroll
        for (int ks = 0; ks < 2; ks++) {
            const int kb = ks << 4;
            uint32_t af[2][4];
#pragma unroll
            for (int mt = 0; mt < 2; mt++) {
                const int r = wm * 32 + mt * 16 + g4;
                const int base = r * STRH + kb + 2 * t4;
                af[mt][0] = *reinterpret_cast<const uint32_t*>(&As[base]);
                af[mt][1] = *reinterpret_cast<const uint32_t*>(&As[base + 8 * STRH]);
                af[mt][2] = *reinterpret_cast<const uint32_t*>(&As[base + 8]);
                af[mt][3] = *reinterpret_cast<const uint32_t*>(&As[base + 8 * STRH + 8]);
            }
#pragma unroll
            for (int nt = 0; nt < 8; nt++) {
                const int n = wn * 64 + nt * 8 + g4;
                const int bb = n * STRH + kb + 2 * t4;
                const uint32_t b0 = *reinterpret_cast<const uint32_t*>(&Bs[bb]);
                const uint32_t b1 = *reinterpret_cast<const uint32_t*>(&Bs[bb + 8]);
                mma_f16(acc[0][nt], af[0], b0, b1);
                mma_f16(acc[1][nt], af[1], b0, b1);
            }
        }
    }
#pragma unroll
    for (int mt = 0; mt < 2; mt++) {
#pragma unroll
        for (int h = 0; h < 2; h++) {
            const int gr = row0 + wm * 32 + mt * 16 + g4 + h * 8;
            if (gr >= nrows) continue;
            const int ro = rows ? __ldg(&rows[gr]) : gr;
#pragma unroll
            for (int nt = 0; nt < 8; nt++) {
                const int col = col0 + wn * 64 + nt * 8 + t4 * 2;
                if (col >= ncols) continue;
                float2 v = make_float2(acc[mt][nt][h * 2 + 0], acc[mt][nt][h * 2 + 1]);
                if (col >= bstart) {
                    v.x += __ldg(&bias[col - bstart]);
                    v.y += __ldg(&bias[col - bstart + 1]);
                }
                if (Cf) {
                    *reinterpret_cast<float2*>(Cf + (size_t)ro * ldC + col) = v;
                } else {
                    __half2 hv = __float22half2_rn(v);
                    *reinterpret_cast<__half2*>(C + (size_t)ro * ldC + col) = hv;
                }
            }
        }
    }
}

// batched weight folds (stage 1: 12 descs; stage 2: 8 descs via grid.z)
struct FoldD { const float* A; const float* B0; const float* B1;
               const float* B2; __half* C; float* Cf; int ldC; int ncols;
               int bRows; };
struct FoldArr { FoldD d[12]; };
__global__ void __launch_bounds__(256) gemm_fold(FoldArr args, const float* bias) {
    __shared__ __align__(16) __half As[128 * STRH];
    __shared__ __align__(16) __half Bs[128 * STRH];
    const FoldD f = args.d[blockIdx.z];
    if ((int)blockIdx.x * 128 >= f.ncols) return;
    gemm_core_f32(f.A, f.B0, f.B1, f.B2, bias, NOBIAS, f.C, f.Cf,
                  256, 256, f.ldC, f.ncols, f.bRows,
                  blockIdx.y * 128, blockIdx.x * 128, nullptr, As, Bs);
}

// per-section layer-0 GEMM from RAW features: A f32 [n,Kx], B f32 [256,Kx]
struct SecD { const float* A; const float* B; const float* bias; int bstart;
              __half* C; int ldC; int K; const int* rows; const int* cntp; };
struct Sec8 { SecD d[8]; };
__global__ void __launch_bounds__(256) gemm_secP8(Sec8 g, const float* dummyb) {
    __shared__ __align__(16) __half As[128 * STRH];
    __shared__ __align__(16) __half Bs[128 * STRH];
    const SecD d = g.d[blockIdx.z];
    const int nrows = *d.cntp;
    for (int row0 = blockIdx.y * 128; row0 < nrows; row0 += gridDim.y * 128) {
        gemm_core_f32(d.A, d.B, nullptr, nullptr,
                      d.bstart == 0 ? d.bias : dummyb, d.bstart,
                      d.C, nullptr,
                      nrows, d.K, d.ldC, 256, 1 << 29,
                      row0, blockIdx.x * 128, d.rows, As, Bs);
        __syncthreads();
    }
}

// batched transposes (6 Wlin in one launch)
struct TPArgs { const float* in[6]; float* out[6]; };
__global__ void transpose6(TPArgs a) {
    int z = blockIdx.z, k = blockIdx.x, n = threadIdx.x;
    a.out[z][(size_t)n * 256 + k] = a.in[z][(size_t)k * 256 + n];
}

// batched bias folds (6 in one launch)
struct FoldB { const float* b1; const float* b2; const float* b3;
               const float* B; const float* blin; float* out; };
struct FoldB6 { FoldB d[6]; };
__global__ void fold_b6(FoldB6 a) {
    const FoldB f = a.d[blockIdx.x];
    int j = threadIdx.x;
    float acc = f.blin[j];
    for (int k = 0; k < Hc; k++) {
        float bb = f.b1[k];
        if (f.b2) bb += f.b2[k];
        if (f.b3) bb += f.b3[k];
        acc = fmaf(bb, f.B[k * Hc + j], acc);
    }
    f.out[j] = acc;
}

// =====================================================================
// fused zero-fill (replaces 4 memsets)
// =====================================================================
__global__ void zero_k(int* __restrict__ ib2, int* __restrict__ cnt,
                       int* __restrict__ last) {
    int i = blockIdx.x * blockDim.x + threadIdx.x;
    if (i < 1040000) ib2[F_A1 + i] = 0;
    else if (i < 1040016) ib2[CTRS + (i - 1040000)] = 0;
    else if (i < 1760016) cnt[i - 1040016] = 0;
    else if (i < 1760528) last[i - 1760016] = 0;
}

// =====================================================================
// fused last-node detection + pass-1 frontier (boundary test inlined)
// =====================================================================
__global__ void prop1_last(const int* __restrict__ batch, int* __restrict__ last,
                           int* __restrict__ fA1, int* __restrict__ fR1,
                           int* __restrict__ fT1,
                           const int* __restrict__ sf, const int* __restrict__ df,
                           const int* __restrict__ sra, const int* __restrict__ dra,
                           const int* __restrict__ sta, const int* __restrict__ dta) {
    const int E4 = EE / 4;
    int i = blockIdx.x * blockDim.x + threadIdx.x;
    if (i < NACT) {
        if (i == NACT - 1 || __ldg(&batch[i + 1]) != __ldg(&batch[i])) {
            last[__ldg(&batch[i])] = i;
            fA1[i] = 1;
        }
        return;
    }
    i -= NACT;
    if (i >= 3 * E4) return;
    int r = i / E4, e4 = i - r * E4;
    const int *sp, *dp; int* fo;
    if (r == 0)      { sp = sf;  dp = df;  fo = fA1; }
    else if (r == 1) { sp = sra; dp = dra; fo = fR1; }
    else             { sp = sta; dp = dta; fo = fT1; }
    int4 d = reinterpret_cast<const int4*>(dp)[e4];
    auto isL = [&](int dd) {
        return (dd == NACT - 1) || (__ldg(&batch[dd + 1]) != __ldg(&batch[dd]));
    };
    int m0 = isL(d.x), m1 = isL(d.y), m2 = isL(d.z), m3 = isL(d.w);
    if (m0 | m1 | m2 | m3) {
        int4 s = reinterpret_cast<const int4*>(sp)[e4];
        if (m0) fo[s.x] = 1;
        if (m1) fo[s.y] = 1;
        if (m2) fo[s.z] = 1;
        if (m3) fo[s.w] = 1;
    }
}

// pass 2 (int4) FUSED with filtered CSR count
__global__ void prop2cntv(const int* __restrict__ sf, const int* __restrict__ df,
                          const int* __restrict__ sra, const int* __restrict__ dra,
                          const int* __restrict__ sta, const int* __restrict__ dta,
                          const int* __restrict__ sar, const int* __restrict__ dar,
                          const int* __restrict__ sat, const int* __restrict__ dat,
                          const int* __restrict__ fA1, const int* __restrict__ fR1,
                          const int* __restrict__ fT1,
                          int* __restrict__ ib2, int* __restrict__ cnt) {
    const int E4 = EE / 4;
    int i = blockIdx.x * blockDim.x + threadIdx.x;
    if (i >= 5 * E4) return;
    int r = i / E4, e4 = i - r * E4;
    const int *sp, *dp, *fp; int base; size_t fof;
    switch (r) {
        case 0: sp = sf;  dp = df;  fp = fA1; base = B_F;  fof = F_LF;  break;
        case 1: sp = sra; dp = dra; fp = fA1; base = B_RA; fof = F_LRA; break;
        case 2: sp = sta; dp = dta; fp = fA1; base = B_TA; fof = F_LTA; break;
        case 3: sp = sar; dp = dar; fp = fR1; base = B_AR; fof = F_LAR; break;
        default: sp = sat; dp = dat; fp = fT1; base = B_AT; fof = F_LAT; break;
    }
    int4 d = reinterpret_cast<const int4*>(dp)[e4];
    int m0 = __ldg(&fp[d.x]), m1 = __ldg(&fp[d.y]);
    int m2 = __ldg(&fp[d.z]), m3 = __ldg(&fp[d.w]);
    if (m0 | m1 | m2 | m3) {
        int4 s = reinterpret_cast<const int4*>(sp)[e4];
        if (m0) { ib2[fof + s.x] = 1; atomicAdd(&cnt[base + d.x], 1); }
        if (m1) { ib2[fof + s.y] = 1; atomicAdd(&cnt[base + d.y], 1); }
        if (m2) { ib2[fof + s.z] = 1; atomicAdd(&cnt[base + d.z], 1); }
        if (m3) { ib2[fof + s.w] = 1; atomicAdd(&cnt[base + d.w], 1); }
    }
}

// fused: scan-free segment alloc + list compaction
__global__ void compact_alloc(int* __restrict__ ib2, const int* __restrict__ cnt,
                              int* __restrict__ offs, int* __restrict__ cur) {
    int i = blockIdx.x * blockDim.x + threadIdx.x;
    if (i < CSR_N) {
        int c = cnt[i];
        if (c > 0) {
            int p = atomicAdd(&ib2[CTRS + 11], c);
            offs[i] = p;
            cur[i] = p;
        }
        return;
    }
    i -= CSR_N;
    if (i >= NACT + NRES + NTIME) return;
    if (i < NACT) {
        if (ib2[F_A1  + i]) { int p = atomicAdd(&ib2[CTRS + 0],  1); ib2[L_A1  + p] = i; }
        if (ib2[F_LF  + i]) { int p = atomicAdd(&ib2[CTRS + 6],  1); ib2[L_LF  + p] = i; }
        if (ib2[F_LAR + i]) { int p = atomicAdd(&ib2[CTRS + 7],  1); ib2[L_LAR + p] = i; }
        if (ib2[F_LAT + i]) { int p = atomicAdd(&ib2[CTRS + 8],  1); ib2[L_LAT + p] = i; }
    } else if (i < NACT + NRES) {
        int n = i - NACT;
        if (ib2[F_R1  + n]) { int p = atomicAdd(&ib2[CTRS + 1],  1); ib2[L_R1  + p] = n; }
        if (ib2[F_LRA + n]) { int p = atomicAdd(&ib2[CTRS + 9],  1); ib2[L_LRA + p] = n; }
    } else {
        int n = i - NACT - NRES;
        if (ib2[F_T1  + n]) { int p = atomicAdd(&ib2[CTRS + 2],  1); ib2[L_T1  + p] = n; }
        if (ib2[F_LTA + n]) { int p = atomicAdd(&ib2[CTRS + 10], 1); ib2[L_LTA + p] = n; }
    }
}

// filtered fill (int4)
__global__ void fill5fv(const int* __restrict__ sf, const int* __restrict__ df,
                        const int* __restrict__ sra, const int* __restrict__ dra,
                        const int* __restrict__ sta, const int* __restrict__ dta,
                        const int* __restrict__ sar, const int* __restrict__ dar,
                        const int* __restrict__ sat, const int* __restrict__ dat,
                        const int* __restrict__ fA1, const int* __restrict__ fR1,
                        const int* __restrict__ fT1,
                        int* __restrict__ cur, int* __restrict__ idx) {
    const int E4 = EE / 4;
    int i = blockIdx.x * blockDim.x + threadIdx.x;
    if (i >= 5 * E4) return;
    int r = i / E4, e4 = i - r * E4;
    const int *sp, *dp, *fp; int base;
    switch (r) {
        case 0: sp = sf;  dp = df;  fp = fA1; base = B_F;  break;
        case 1: sp = sra; dp = dra; fp = fA1; base = B_RA; break;
        case 2: sp = sta; dp = dta; fp = fA1; base = B_TA; break;
        case 3: sp = sar; dp = dar; fp = fR1; base = B_AR; break;
        default: sp = sat; dp = dat; fp = fT1; base = B_AT; break;
    }
    int4 d = reinterpret_cast<const int4*>(dp)[e4];
    int m0 = __ldg(&fp[d.x]), m1 = __ldg(&fp[d.y]);
    int m2 = __ldg(&fp[d.z]), m3 = __ldg(&fp[d.w]);
    if (m0 | m1 | m2 | m3) {
        int4 s = reinterpret_cast<const int4*>(sp)[e4];
        if (m0) { int p = atomicAdd(&cur[base + d.x], 1); idx[p] = s.x; }
        if (m1) { int p = atomicAdd(&cur[base + d.y], 1); idx[p] = s.y; }
        if (m2) { int p = atomicAdd(&cur[base + d.z], 1); idx[p] = s.z; }
        if (m3) { int p = atomicAdd(&cur[base + d.w], 1); idx[p] = s.w; }
    }
}

// =====================================================================
// gathers (offs + cnt segments)
// =====================================================================
__device__ __forceinline__ void accum_rel(const __half* __restrict__ base, int stride,
                                          const int* __restrict__ offs,
                                          const int* __restrict__ cnt,
                                          const int* __restrict__ idx,
                                          int w, int lane, float* a) {
    int c = __ldg(&cnt[w]);
    if (c <= 0) return;
    int s = __ldg(&offs[w]);
    float sc = 1.f / (float)c;
    float m[8] = {0.f, 0.f, 0.f, 0.f, 0.f, 0.f, 0.f, 0.f};
    for (int p = s; p < s + c; p++) {
        int sn = __ldg(&idx[p]);
        uint4 q = *reinterpret_cast<const uint4*>(base + (size_t)sn * stride + lane * 8);
        float f[8];
        h8_to_f8(q, f);
#pragma unroll
        for (int j = 0; j < 8; j++) m[j] += f[j];
    }
#pragma unroll
    for (int j = 0; j < 8; j++) a[j] += m[j] * sc;
}

// layer-0 gather over frontier lists, persistent warps
__global__ void __launch_bounds__(256) gather_idx(
        const __half* __restrict__ Pa, const __half* __restrict__ Pr,
        const __half* __restrict__ Pt,
        const int* __restrict__ offs, const int* __restrict__ cnt,
        const int* __restrict__ idx, const int* __restrict__ ib2,
        __half* __restrict__ A, __half* __restrict__ R, __half* __restrict__ T) {
    const int lane = threadIdx.x & 31;
    const int cA = __ldg(&ib2[CTRS + 0]);
    const int cR = __ldg(&ib2[CTRS + 1]);
    const int cT = __ldg(&ib2[CTRS + 2]);
    const int total = cA + cR + cT;
    const int wstep = gridDim.x * 8;
    for (int w = blockIdx.x * 8 + (threadIdx.x >> 5); w < total; w += wstep) {
        float a[8];
        if (w < cA) {
            int u = __ldg(&ib2[L_A1 + w]);
            h8_to_f8(*reinterpret_cast<const uint4*>(Pa + (size_t)u * 1024 + 768 + lane * 8), a);
            accum_rel(Pa, 1024, offs + B_F,  cnt + B_F,  idx, u, lane, a);
            accum_rel(Pr, 512,  offs + B_RA, cnt + B_RA, idx, u, lane, a);
            accum_rel(Pt, 512,  offs + B_TA, cnt + B_TA, idx, u, lane, a);
#pragma unroll
            for (int j = 0; j < 8; j++) a[j] = fmaxf(a[j], 0.f);
            *reinterpret_cast<uint4*>(A + (size_t)u * 256 + lane * 8) = f8_to_h8(a);
        } else if (w < cA + cR) {
            int v = __ldg(&ib2[L_R1 + (w - cA)]);
            h8_to_f8(*reinterpret_cast<const uint4*>(Pr + (size_t)v * 512 + 256 + lane * 8), a);
            accum_rel(Pa + 256, 1024, offs + B_AR, cnt + B_AR, idx, v, lane, a);
#pragma unroll
            for (int j = 0; j < 8; j++) a[j] = fmaxf(a[j], 0.f);
            *reinterpret_cast<uint4*>(R + (size_t)v * 256 + lane * 8) = f8_to_h8(a);
        } else {
            int v = __ldg(&ib2[L_T1 + (w - cA - cR)]);
            h8_to_f8(*reinterpret_cast<const uint4*>(Pt + (size_t)v * 512 + 256 + lane * 8), a);
            accum_rel(Pa + 512, 1024, offs + B_AT, cnt + B_AT, idx, v, lane, a);
#pragma unroll
            for (int j = 0; j < 8; j++) a[j] = fmaxf(a[j], 0.f);
            *reinterpret_cast<uint4*>(T + (size_t)v * 256 + lane * 8) = f8_to_h8(a);
        }
    }
}

// layer-1 pooled gather
__global__ void __launch_bounds__(256) gather_pool(
        const __half* __restrict__ A, const __half* __restrict__ R,
        const __half* __restrict__ T,
        const int* __restrict__ offs, const int* __restrict__ cnt,
        const int* __restrict__ idx,
        const int* __restrict__ last, __half* __restrict__ X2) {
    int w = (blockIdx.x * 256 + threadIdx.x) >> 5;
    int lane = threadIdx.x & 31;
    if (w >= 4 * GG) return;
    int g = w >> 2, s = w & 3;
    int nid = __ldg(&last[g]);
    float a[8] = {0.f, 0.f, 0.f, 0.f, 0.f, 0.f, 0.f, 0.f};
    if (s == 0)      accum_rel(A, 256, offs + B_F,  cnt + B_F,  idx, nid, lane, a);
    else if (s == 1) accum_rel(R, 256, offs + B_RA, cnt + B_RA, idx, nid, lane, a);
    else if (s == 2) accum_rel(T, 256, offs + B_TA, cnt + B_TA, idx, nid, lane, a);
    else h8_to_f8(*reinterpret_cast<const uint4*>(A + (size_t)nid * 256 + lane * 8), a);
    *reinterpret_cast<uint4*>(X2 + (size_t)g * 1024 + s * 256 + lane * 8) = f8_to_h8(a);
}

// =====================================================================
// heads
// =====================================================================
__global__ void heads_k(const __half* __restrict__ a2,
                        const float* __restrict__ Wo, const float* __restrict__ bo,
                        const float* __restrict__ Wt, const float* __restrict__ bt,
                        const float* __restrict__ Wrm, const float* __restrict__ brm,
                        float* __restrict__ out) {
    int g = blockIdx.x;
    __shared__ float p[Hc];
    const __half* row = a2 + (size_t)g * Hc;
    for (int k = threadIdx.x; k < Hc; k += blockDim.x) p[k] = __half2float(row[k]);
    __syncthreads();
    int j = threadIdx.x;
    if (j < CC) {
        float acc = bo[j];
        for (int k = 0; k < Hc; k++) acc = fmaf(p[k], Wo[k * CC + j], acc);
        out[g * CC + j] = acc;
    } else if (j == CC) {
        float acc = bt[0];
        for (int k = 0; k < Hc; k++) acc = fmaf(p[k], Wt[k], acc);
        out[GG * CC + g] = acc;
    } else if (j == CC + 1) {
        float acc = brm[0];
        for (int k = 0; k < Hc; k++) acc = fmaf(p[k], Wrm[k], acc);
        out[GG * CC + GG + g] = acc;
    }
}

// =====================================================================
// host orchestration
// =====================================================================
extern "C" void kernel_launch(void* const* d_in, const int* in_sizes, int n_in,
                              void* d_out, int out_size) {
    float* buf = nullptr;
    cudaGetSymbolAddress((void**)&buf, g_buf);

    __half* A  = reinterpret_cast<__half*>(buf + OFF_A);
    __half* R  = reinterpret_cast<__half*>(buf + OFF_R);
    __half* T  = reinterpret_cast<__half*>(buf + OFF_T);
    __half* Pa = reinterpret_cast<__half*>(buf + OFF_PA);
    __half* Pr = reinterpret_cast<__half*>(buf + OFF_PR);
    __half* Pt = reinterpret_cast<__half*>(buf + OFF_PT);
    __half* X2 = Pr;
    __half* A2 = Pt;
    __half* WB2 = reinterpret_cast<__half*>(buf + OFF_WC);
    float* BF  = buf + OFF_BF;
    float* WLT = buf + OFF_WLT;
    float* WCF = buf + OFF_WCF;
    float* BFW = buf + OFF_BFW;
    int*   LAST = reinterpret_cast<int*>(buf + OFF_LAST);
    int*   IB   = reinterpret_cast<int*>(buf + OFF_INT);
    int*   IB2  = reinterpret_cast<int*>(buf + OFF_INT2);
    int* offs = IB + IO_OFFS;
    int* cnt  = IB + IO_CNT;
    int* cur  = IB + IO_CUR;
    int* idx  = IB + IO_IDX;

    const float* x_act  = (const float*)d_in[0];
    const float* x_res  = (const float*)d_in[1];
    const float* x_time = (const float*)d_in[2];
    const int* src_f  = (const int*)d_in[3];
    const int* dst_f  = (const int*)d_in[4];
    const int* src_ar = (const int*)d_in[5];
    const int* dst_ar = (const int*)d_in[6];
    const int* src_ra = (const int*)d_in[7];
    const int* dst_ra = (const int*)d_in[8];
    const int* src_at = (const int*)d_in[9];
    const int* dst_at = (const int*)d_in[10];
    const int* src_ta = (const int*)d_in[11];
    const int* dst_ta = (const int*)d_in[12];
    const int* batch  = (const int*)d_in[13];

    int w = (in_sizes[14] <= 4) ? 15 : 14;
    const float* Wp_act = (const float*)d_in[w + 0];
    const float* Wp_res = (const float*)d_in[w + 1];
    const float* Wp_tim = (const float*)d_in[w + 2];
    const float* Wl     = (const float*)d_in[w + 3];
    const float* bl     = (const float*)d_in[w + 4];
    const float* Wr     = (const float*)d_in[w + 5];
    const float* Wlin   = (const float*)d_in[w + 6];
    const float* blin   = (const float*)d_in[w + 7];
    const float* Wo     = (const float*)d_in[w + 8];
    const float* bo     = (const float*)d_in[w + 9];
    const float* Wt     = (const float*)d_in[w + 10];
    const float* bt     = (const float*)d_in[w + 11];
    const float* Wrm    = (const float*)d_in[w + 12];
    const float* brm    = (const float*)d_in[w + 13];

    const size_t HH = 65536;  // 256*256

    // --- fused zero-fill ---
    zero_k<<<(1760528 + 255) / 256, 256>>>(IB2, cnt, LAST);

    // --- Wlin transposes (6) ---
    {
        TPArgs tp;
        for (int i = 0; i < 6; i++) {
            tp.in[i]  = Wlin + (size_t)i * HH;
            tp.out[i] = WLT + (size_t)i * HH;
        }
        transpose6<<<dim3(256, 1, 6), 256>>>(tp);
    }

    // --- stage-1 folds: 8 l=0 sections (f32 out) + 4 l=1 (f16 WB2) ---
    {
        FoldArr fa;
        const float* lt0 = WLT + 0 * HH;
        const float* lt1 = WLT + 1 * HH;
        const float* lt2 = WLT + 2 * HH;
        fa.d[0] = {lt0, Wl + 0 * HH, nullptr, nullptr, nullptr, WCF + 0,      256, 256, 256};
        fa.d[1] = {lt1, Wl + 1 * HH, nullptr, nullptr, nullptr, WCF + 65536,  256, 256, 256};
        fa.d[2] = {lt2, Wl + 3 * HH, nullptr, nullptr, nullptr, WCF + 131072, 256, 256, 256};
        fa.d[3] = {lt0, Wr + 0 * HH, Wr + 2 * HH, Wr + 4 * HH, nullptr, WCF + 196608, 256, 256, 256};
        fa.d[4] = {lt0, Wl + 2 * HH, nullptr, nullptr, nullptr, WCF + 262144, 256, 256, 256};
        fa.d[5] = {lt1, Wr + 1 * HH, nullptr, nullptr, nullptr, WCF + 327680, 256, 256, 256};
        fa.d[6] = {lt0, Wl + 4 * HH, nullptr, nullptr, nullptr, WCF + 393216, 256, 256, 256};
        fa.d[7] = {lt2, Wr + 3 * HH, nullptr, nullptr, nullptr, WCF + 458752, 256, 256, 256};
        const float* lt3 = WLT + 3 * HH;
        fa.d[8]  = {lt3, Wl + 5 * HH, nullptr, nullptr, WB2 + 0,   nullptr, 1024, 256, 256};
        fa.d[9]  = {lt3, Wl + 7 * HH, nullptr, nullptr, WB2 + 256, nullptr, 1024, 256, 256};
        fa.d[10] = {lt3, Wl + 9 * HH, nullptr, nullptr, WB2 + 512, nullptr, 1024, 256, 256};
        fa.d[11] = {lt3, Wr + 5 * HH, Wr + 7 * HH, Wr + 9 * HH, WB2 + 768, nullptr, 1024, 256, 256};
        gemm_fold<<<dim3(2, 2, 12), 256>>>(fa, BF);
    }
    // --- stage-2 folds: fuse Wp into sections -> Bf[256, Kx] (f32) ---
    {
        FoldArr fb;
        fb.d[0] = {WCF + 0,      Wp_act, nullptr, nullptr, nullptr, BFW + 0,     64, 64, 64};
        fb.d[1] = {WCF + 65536,  Wp_act, nullptr, nullptr, nullptr, BFW + 16384, 64, 64, 64};
        fb.d[2] = {WCF + 131072, Wp_act, nullptr, nullptr, nullptr, BFW + 32768, 64, 64, 64};
        fb.d[3] = {WCF + 196608, Wp_act, nullptr, nullptr, nullptr, BFW + 49152, 64, 64, 64};
        fb.d[4] = {WCF + 262144, Wp_res, nullptr, nullptr, nullptr, BFW + 65536, 32, 32, 32};
        fb.d[5] = {WCF + 327680, Wp_res, nullptr, nullptr, nullptr, BFW + 73728, 32, 32, 32};
        fb.d[6] = {WCF + 393216, Wp_tim, nullptr, nullptr, nullptr, BFW + 81920, 16, 16, 16};
        fb.d[7] = {WCF + 458752, Wp_tim, nullptr, nullptr, nullptr, BFW + 86016, 16, 16, 16};
        for (int i = 8; i < 12; i++) fb.d[i] = fb.d[0];
        gemm_fold<<<dim3(1, 2, 8), 256>>>(fb, BF);
    }
    // --- bias folds ---
    {
        FoldB6 fc;
        for (int l = 0; l < 2; l++) {
            fc.d[l * 3 + 0] = {bl + (l * 5 + 0) * 256, bl + (l * 5 + 2) * 256,
                               bl + (l * 5 + 4) * 256, Wlin + (size_t)(l * 3 + 0) * HH,
                               blin + (l * 3 + 0) * 256, BF + l * 768 + 0};
            fc.d[l * 3 + 1] = {bl + (l * 5 + 1) * 256, nullptr, nullptr,
                               Wlin + (size_t)(l * 3 + 1) * HH,
                               blin + (l * 3 + 1) * 256, BF + l * 768 + 256};
            fc.d[l * 3 + 2] = {bl + (l * 5 + 3) * 256, nullptr, nullptr,
                               Wlin + (size_t)(l * 3 + 2) * HH,
                               blin + (l * 3 + 2) * 256, BF + l * 768 + 512};
        }
        fold_b6<<<6, 256>>>(fc);
    }

    // --- frontier + CSR (4 launches) ---
    prop1_last<<<(NACT + 3 * EE / 4 + 255) / 256, 256>>>(
        batch, LAST, IB2 + F_A1, IB2 + F_R1, IB2 + F_T1,
        src_f, dst_f, src_ra, dst_ra, src_ta, dst_ta);
    {
        int nb4 = (5 * EE / 4 + 255) / 256;
        prop2cntv<<<nb4, 256>>>(src_f, dst_f, src_ra, dst_ra, src_ta, dst_ta,
                                src_ar, dst_ar, src_at, dst_at,
                                IB2 + F_A1, IB2 + F_R1, IB2 + F_T1, IB2, cnt);
        compact_alloc<<<(CSR_N + NACT + NRES + NTIME + 255) / 256, 256>>>(
            IB2, cnt, offs, cur);
        fill5fv<<<nb4, 256>>>(src_f, dst_f, src_ra, dst_ra, src_ta, dst_ta,
                              src_ar, dst_ar, src_at, dst_at,
                              IB2 + F_A1, IB2 + F_R1, IB2 + F_T1, cur, idx);
    }

    // --- layer 0: proj-fused per-section GEMMs (one launch) + gather ---
    {
        Sec8 g;
        g.d[0] = {x_act,  BFW + 0,     BF,       NOBIAS, Pa + 0,   1024, 64, IB2 + L_LF,  IB2 + CTRS + 6};
        g.d[1] = {x_act,  BFW + 16384, BF,       NOBIAS, Pa + 256, 1024, 64, IB2 + L_LAR, IB2 + CTRS + 7};
        g.d[2] = {x_act,  BFW + 32768, BF,       NOBIAS, Pa + 512, 1024, 64, IB2 + L_LAT, IB2 + CTRS + 8};
        g.d[3] = {x_act,  BFW + 49152, BF + 0,   0,      Pa + 768, 1024, 64, IB2 + L_A1,  IB2 + CTRS + 0};
        g.d[4] = {x_res,  BFW + 65536, BF,       NOBIAS, Pr + 0,   512,  32, IB2 + L_LRA, IB2 + CTRS + 9};
        g.d[5] = {x_res,  BFW + 73728, BF + 256, 0,      Pr + 256, 512,  32, IB2 + L_R1,  IB2 + CTRS + 1};
        g.d[6] = {x_time, BFW + 81920, BF,       NOBIAS, Pt + 0,   512,  16, IB2 + L_LTA, IB2 + CTRS + 10};
        g.d[7] = {x_time, BFW + 86016, BF + 512, 0,      Pt + 256, 512,  16, IB2 + L_T1,  IB2 + CTRS + 2};
        gemm_secP8<<<dim3(2, 48, 8), 256>>>(g, BF);

        gather_idx<<<256, 256>>>(Pa, Pr, Pt, offs, cnt, idx, IB2, A, R, T);
    }

    // --- layer 1: pooled aggregate-then-project (512 rows) ---
    {
        gather_pool<<<(4 * GG * 32 + 255) / 256, 256>>>(A, R, T, offs, cnt, idx,
                                                        LAST, X2);
        Gemm3 g;
        g.d[0] = {X2, WB2, BF + 768, A2, 0, GG, 256, 2, 1024, 1};
        g.d[1] = g.d[0]; g.d[2] = g.d[0];
        g.n0 = 8; g.n01 = 8;
        gemm_fast3<<<8, 256>>>(g);
    }

    // --- heads ---
    heads_k<<<GG, 64>>>(A2, Wo, bo, Wt, bt, Wrm, brm, (float*)d_out);
}